// round 5
// baseline (speedup 1.0000x reference)
#include <cuda_runtime.h>
#include <cuda_fp16.h>
#include <math.h>
#include <stdint.h>

// ---------------- problem constants ----------------
#define BATCH 128
#define SEQ   50
#define DMODEL 1024
#define DFF   4096
#define NHEAD 16
#define DK    64
#define NLAYER 5
#define KEMB  1200
#define KEMBP 1216
#define NTOK  6400
#define NCLS  71
#define NQKV  3072

#define GBK 32

// ---------------- weight scratch layout (transposed fp16 hi/lo) ----------------
#define WT_EMB_SZ (1024u*1216u)
#define WT_LAYER  (12u*1024u*1024u)
#define WT_TOTAL  (WT_EMB_SZ + 5u*WT_LAYER)

// ---------------- scratch (device globals) ----------------
__device__ float d_h  [NTOK * DMODEL];
__device__ float d_qkv[NTOK * NQKV];
__device__ float d_z0 [BATCH * DMODEL];
__device__ float d_z1 [BATCH * DMODEL];

__device__ __align__(16) __half d_xh[NTOK * KEMBP];
__device__ __align__(16) __half d_xl[NTOK * KEMBP];
__device__ __align__(16) __half d_ah[NTOK * DMODEL];
__device__ __align__(16) __half d_al[NTOK * DMODEL];
__device__ __align__(16) __half d_oh[NTOK * DMODEL];
__device__ __align__(16) __half d_ol[NTOK * DMODEL];
__device__ __align__(16) __half d_fh[NTOK * DFF];
__device__ __align__(16) __half d_fl[NTOK * DFF];
__device__ __align__(16) __half d_wth[WT_TOTAL];
__device__ __align__(16) __half d_wtl[WT_TOTAL];

// ---------------- PTX helpers ----------------
__device__ __forceinline__ uint32_t smem_u32(const void* p) {
    uint32_t a;
    asm("{ .reg .u64 t; cvta.to.shared.u64 t, %1; cvt.u32.u64 %0, t; }" : "=r"(a) : "l"(p));
    return a;
}
__device__ __forceinline__ void cpa16(uint32_t dst, const void* src) {
    asm volatile("cp.async.cg.shared.global [%0], [%1], 16;" :: "r"(dst), "l"(src));
}
#define CP_COMMIT() asm volatile("cp.async.commit_group;" ::: "memory")
#define CP_WAIT1()  asm volatile("cp.async.wait_group 1;" ::: "memory")
#define CP_WAIT0()  asm volatile("cp.async.wait_group 0;" ::: "memory")
#define LDSM4(r, a) \
    asm volatile("ldmatrix.sync.aligned.m8n8.x4.shared.b16 {%0,%1,%2,%3}, [%4];" \
        : "=r"((r)[0]), "=r"((r)[1]), "=r"((r)[2]), "=r"((r)[3]) : "r"(a))
#define MMA16816(c, a, b) \
    asm volatile("mma.sync.aligned.m16n8k16.row.col.f32.f16.f16.f32 " \
        "{%0,%1,%2,%3}, {%4,%5,%6,%7}, {%8,%9}, {%0,%1,%2,%3};" \
        : "+f"((c)[0]), "+f"((c)[1]), "+f"((c)[2]), "+f"((c)[3]) \
        : "r"((a)[0]), "r"((a)[1]), "r"((a)[2]), "r"((a)[3]), "r"((b)[0]), "r"((b)[1]))

__device__ __forceinline__ void split_f16(float v, __half& h, __half& l) {
    h = __float2half_rn(v);
    l = __float2half_rn(v - __half2float(h));
}

// ---------------- HMMA GEMM: C(MxN) = (Ah+Al) @ (Bh+Bl)^T, fp32 accum ----------------
// templated on BM (64 or 128); BN fixed 128, BK 32, 256 threads, 3-stage cp.async.
// epi: 0 = +bias -> Cf; 1 = relu(+bias) -> Chi/Clo; 2 = +bias+resid -> Cf; 3 = +PE -> Cf
template<int BM>
__global__ void __launch_bounds__(256, 2) tgemm_kernel(
    const __half* __restrict__ Ah, const __half* __restrict__ Al,
    const __half* __restrict__ Bh, const __half* __restrict__ Bl,
    const float* __restrict__ bias, const float* __restrict__ resid,
    float* __restrict__ Cf, __half* __restrict__ Chi, __half* __restrict__ Clo,
    int Kp, int N, int epi)
{
    constexpr int WM = BM / 32;              // warps along m (4 or 2)
    constexpr int WN = 8 / WM;               // warps along n (2 or 4)
    constexpr int NTILE = 128 / WN;          // per-warp n width (64 or 32)
    constexpr int NT = NTILE / 8;            // n frags (8 or 4)
    constexpr int NHALF = (NT + 3) / 4;      // b-frag groups (2 or 1)
    constexpr uint32_t OFFAL = (uint32_t)BM * 64u;
    constexpr uint32_t OFFBH = 2u * BM * 64u;
    constexpr uint32_t OFFBL = 2u * BM * 64u + 8192u;
    constexpr uint32_t STAGE = 2u * BM * 64u + 16384u;

    extern __shared__ char sm[];
    const uint32_t smb = smem_u32(sm);
    const int tid  = threadIdx.x;
    const int lane = tid & 31;
    const int wid  = tid >> 5;
    const int wm   = wid % WM;
    const int wn   = wid / WM;
    const int m0 = blockIdx.y * BM;
    const int n0 = blockIdx.x * 128;

    float acc[2][NT][4];
#pragma unroll
    for (int i = 0; i < 2; i++)
#pragma unroll
        for (int j = 0; j < NT; j++)
#pragma unroll
            for (int t = 0; t < 4; t++) acc[i][j][t] = 0.f;

    auto load_stage = [&](int st, int k0) {
        const uint32_t sb = smb + (uint32_t)st * STAGE;
#pragma unroll
        for (int v = tid; v < BM * 4; v += 256) {
            const int row = v >> 2, cc = v & 3;
            const uint32_t off = (uint32_t)((row << 6) + ((cc ^ ((row >> 1) & 3)) << 4));
            const size_t ka = (size_t)(m0 + row) * Kp + k0 + cc * 8;
            cpa16(sb + off, Ah + ka);
            cpa16(sb + OFFAL + off, Al + ka);
        }
#pragma unroll
        for (int v = tid; v < 512; v += 256) {
            const int row = v >> 2, cc = v & 3;
            const uint32_t off = (uint32_t)((row << 6) + ((cc ^ ((row >> 1) & 3)) << 4));
            const size_t kb = (size_t)(n0 + row) * Kp + k0 + cc * 8;
            cpa16(sb + OFFBH + off, Bh + kb);
            cpa16(sb + OFFBL + off, Bl + kb);
        }
    };

    auto compute = [&](int st) {
        const uint32_t sb = smb + (uint32_t)st * STAGE;
#pragma unroll
        for (int ks = 0; ks < 2; ks++) {
            uint32_t aH[2][4], aL[2][4];
#pragma unroll
            for (int mt = 0; mt < 2; mt++) {
                const int r = wm * 32 + mt * 16 + (lane & 15);
                const int ch = ks * 2 + (lane >> 4);
                const uint32_t off = (uint32_t)((r << 6) + ((ch ^ ((r >> 1) & 3)) << 4));
                LDSM4(aH[mt], sb + off);
                LDSM4(aL[mt], sb + OFFAL + off);
            }
#pragma unroll
            for (int half = 0; half < NHALF; half++) {
                uint32_t bH[4][2], bL[4][2];
#pragma unroll
                for (int p = 0; p < 2; p++) {
                    const int r = wn * NTILE + (half * 2 + p) * 16 + (lane & 7) + ((lane & 16) >> 1);
                    const int ch = ks * 2 + ((lane >> 3) & 1);
                    const uint32_t off = (uint32_t)((r << 6) + ((ch ^ ((r >> 1) & 3)) << 4));
                    uint32_t q[4];
                    LDSM4(q, sb + OFFBH + off);
                    bH[p*2][0] = q[0]; bH[p*2][1] = q[1];
                    bH[p*2+1][0] = q[2]; bH[p*2+1][1] = q[3];
                    LDSM4(q, sb + OFFBL + off);
                    bL[p*2][0] = q[0]; bL[p*2][1] = q[1];
                    bL[p*2+1][0] = q[2]; bL[p*2+1][1] = q[3];
                }
#pragma unroll
                for (int mt = 0; mt < 2; mt++)
#pragma unroll
                    for (int nt = 0; nt < 4; nt++) MMA16816(acc[mt][half*4+nt], aH[mt], bH[nt]);
#pragma unroll
                for (int mt = 0; mt < 2; mt++)
#pragma unroll
                    for (int nt = 0; nt < 4; nt++) MMA16816(acc[mt][half*4+nt], aH[mt], bL[nt]);
#pragma unroll
                for (int mt = 0; mt < 2; mt++)
#pragma unroll
                    for (int nt = 0; nt < 4; nt++) MMA16816(acc[mt][half*4+nt], aL[mt], bH[nt]);
            }
        }
    };

    const int nchunk = Kp / GBK;
    load_stage(0, 0);
    CP_COMMIT();
    if (nchunk > 1) { load_stage(1, GBK); CP_COMMIT(); }
    int s_c = 0, s_ld = 2;
    for (int c = 0; c < nchunk; c++) {
        if (c + 1 < nchunk) CP_WAIT1(); else CP_WAIT0();
        __syncthreads();
        if (c + 2 < nchunk) { load_stage(s_ld, (c + 2) * GBK); CP_COMMIT(); }
        compute(s_c);
        s_c = (s_c == 2) ? 0 : s_c + 1;
        s_ld = (s_ld == 2) ? 0 : s_ld + 1;
    }

    // ---------------- epilogue ----------------
#pragma unroll
    for (int mt = 0; mt < 2; mt++) {
        const int r0 = m0 + wm * 32 + mt * 16 + (lane >> 2);
#pragma unroll
        for (int nt = 0; nt < NT; nt++) {
            const int col = n0 + wn * NTILE + nt * 8 + (lane & 3) * 2;
            const float* a = acc[mt][nt];
            if (epi == 1) {
                const float b0 = __ldg(&bias[col]);
                const float b1 = __ldg(&bias[col + 1]);
#pragma unroll
                for (int rr = 0; rr < 2; rr++) {
                    const int row = r0 + rr * 8;
                    const float v0 = fmaxf(a[rr * 2 + 0] + b0, 0.f);
                    const float v1 = fmaxf(a[rr * 2 + 1] + b1, 0.f);
                    __half h0, l0, h1, l1;
                    split_f16(v0, h0, l0);
                    split_f16(v1, h1, l1);
                    *reinterpret_cast<__half2*>(&Chi[(size_t)row * N + col]) = __halves2half2(h0, h1);
                    *reinterpret_cast<__half2*>(&Clo[(size_t)row * N + col]) = __halves2half2(l0, l1);
                }
            } else if (epi == 3) {
                const float dv = expf((float)(col & ~1) * (-9.210340371976184f / (float)DMODEL));
#pragma unroll
                for (int rr = 0; rr < 2; rr++) {
                    const int row = r0 + rr * 8;
                    const int srow = row % SEQ;
                    float sn, cs;
                    sincosf((float)srow * dv, &sn, &cs);
                    float2 o;
                    o.x = a[rr * 2 + 0] + sn;
                    o.y = a[rr * 2 + 1] + cs;
                    *reinterpret_cast<float2*>(&Cf[(size_t)row * N + col]) = o;
                }
            } else {
                const float b0 = __ldg(&bias[col]);
                const float b1 = __ldg(&bias[col + 1]);
#pragma unroll
                for (int rr = 0; rr < 2; rr++) {
                    const int row = r0 + rr * 8;
                    float v0 = a[rr * 2 + 0] + b0;
                    float v1 = a[rr * 2 + 1] + b1;
                    if (epi == 2) {
                        const float2 rv = *reinterpret_cast<const float2*>(&resid[(size_t)row * N + col]);
                        v0 += rv.x; v1 += rv.y;
                    }
                    float2 o; o.x = v0; o.y = v1;
                    *reinterpret_cast<float2*>(&Cf[(size_t)row * N + col]) = o;
                }
            }
        }
    }
}

// ---------------- converters ----------------
__global__ void __launch_bounds__(256) cvt_x_kernel(
    const float* __restrict__ x, __half* __restrict__ xh, __half* __restrict__ xl)
{
    const int idx = blockIdx.x * 256 + threadIdx.x;
    if (idx >= NTOK * KEMBP) return;
    const int r = idx / KEMBP, c = idx % KEMBP;
    const float v = (c < KEMB) ? x[(size_t)r * KEMB + c] : 0.f;
    __half h, l; split_f16(v, h, l);
    xh[idx] = h; xl[idx] = l;
}

// transpose + split one 32x32 tile; batched over blockIdx.z
__global__ void cvt_wT_batch_kernel(
    const float* __restrict__ W, __half* __restrict__ Th, __half* __restrict__ Tl,
    int K, int N, int Kp,
    size_t w_stride, size_t o_outer, size_t o_inner, int inner_mod)
{
    const int z = blockIdx.z;
    const float* Wz = W + (size_t)z * w_stride;
    const size_t ooff = (size_t)(z / inner_mod) * o_outer + (size_t)(z % inner_mod) * o_inner;
    __shared__ float t[32][33];
    const int k0 = blockIdx.y * 32, n0 = blockIdx.x * 32;
    const int tx = threadIdx.x, ty = threadIdx.y;   // block (32, 8)
#pragma unroll
    for (int i = 0; i < 32; i += 8) {
        const int k = k0 + ty + i;
        t[ty + i][tx] = (k < K) ? Wz[(size_t)k * N + n0 + tx] : 0.f;
    }
    __syncthreads();
#pragma unroll
    for (int i = 0; i < 32; i += 8) {
        const int n = n0 + ty + i;
        const int k = k0 + tx;
        __half h, l; split_f16(t[tx][ty + i], h, l);
        Th[ooff + (size_t)n * Kp + k] = h;
        Tl[ooff + (size_t)n * Kp + k] = l;
    }
}

// ---------------- LayerNorm (ddof=1, eps on std) -> fp16 hi/lo ----------------
__global__ void __launch_bounds__(256) ln_kernel(
    const float* __restrict__ in, const float* __restrict__ g,
    const float* __restrict__ b, __half* __restrict__ outh, __half* __restrict__ outl)
{
    const int row = blockIdx.x;
    const float* x = in + (size_t)row * DMODEL;
    float vals[4];
    float s = 0.f, s2 = 0.f;
#pragma unroll
    for (int i = 0; i < 4; i++) {
        float v = x[threadIdx.x + i * 256];
        vals[i] = v; s += v; s2 += v * v;
    }
#pragma unroll
    for (int o = 16; o; o >>= 1) {
        s  += __shfl_xor_sync(0xffffffffu, s, o);
        s2 += __shfl_xor_sync(0xffffffffu, s2, o);
    }
    __shared__ float sh[2][8];
    const int w = threadIdx.x >> 5;
    if ((threadIdx.x & 31) == 0) { sh[0][w] = s; sh[1][w] = s2; }
    __syncthreads();
    if (threadIdx.x < 32) {
        s  = (threadIdx.x < 8) ? sh[0][threadIdx.x] : 0.f;
        s2 = (threadIdx.x < 8) ? sh[1][threadIdx.x] : 0.f;
#pragma unroll
        for (int o = 4; o; o >>= 1) {
            s  += __shfl_xor_sync(0xffffffffu, s, o);
            s2 += __shfl_xor_sync(0xffffffffu, s2, o);
        }
        if (threadIdx.x == 0) { sh[0][0] = s; sh[1][0] = s2; }
    }
    __syncthreads();
    const float mean = sh[0][0] * (1.f / (float)DMODEL);
    float var = (sh[1][0] - (float)DMODEL * mean * mean) * (1.f / (float)(DMODEL - 1));
    var = fmaxf(var, 0.f);
    const float inv = 1.f / (sqrtf(var) + 1e-6f);
#pragma unroll
    for (int i = 0; i < 4; i++) {
        const int c = threadIdx.x + i * 256;
        const float r = g[c] * (vals[i] - mean) * inv + b[c];
        __half h, l; split_f16(r, h, l);
        outh[(size_t)row * DMODEL + c] = h;
        outl[(size_t)row * DMODEL + c] = l;
    }
}

// ---------------- attention on fused QKV buffer ----------------
__global__ void __launch_bounds__(256) attn_kernel(
    const float* __restrict__ QKV, __half* __restrict__ Oh, __half* __restrict__ Ol)
{
    const int bh = blockIdx.x;
    const int b = bh >> 4;
    const int h = bh & 15;

    __shared__ float qs[SEQ][DK];
    __shared__ float ks[SEQ][DK + 1];
    __shared__ float vs[SEQ][DK];
    __shared__ float sc[SEQ][SEQ];

    const int tid = threadIdx.x;
    for (int e = tid; e < SEQ * DK; e += 256) {
        const int s = e >> 6;
        const int d = e & 63;
        const size_t gbase = (size_t)(b * SEQ + s) * NQKV + h * DK + d;
        qs[s][d] = QKV[gbase];
        ks[s][d] = QKV[gbase + DMODEL];
        vs[s][d] = QKV[gbase + 2 * DMODEL];
    }
    __syncthreads();

    for (int e = tid; e < SEQ * SEQ; e += 256) {
        const int i = e / SEQ;
        const int j = e % SEQ;
        float acc = 0.f;
#pragma unroll
        for (int d = 0; d < DK; d++) acc = fmaf(qs[i][d], ks[j][d], acc);
        sc[i][j] = acc * 0.125f;
    }
    __syncthreads();

    if (tid < SEQ) {
        float mx = -1e30f;
#pragma unroll 1
        for (int j = 0; j < SEQ; j++) mx = fmaxf(mx, sc[tid][j]);
        float sum = 0.f;
#pragma unroll 1
        for (int j = 0; j < SEQ; j++) {
            float ev = expf(sc[tid][j] - mx);
            sum += ev;
            sc[tid][j] = ev;
        }
        const float r = 1.f / sum;
#pragma unroll 1
        for (int j = 0; j < SEQ; j++) sc[tid][j] *= r;
    }
    __syncthreads();

    for (int e = tid; e < SEQ * DK; e += 256) {
        const int i = e >> 6;
        const int d = e & 63;
        float acc = 0.f;
#pragma unroll
        for (int j = 0; j < SEQ; j++) acc = fmaf(sc[i][j], vs[j][d], acc);
        const size_t gidx = (size_t)(b * SEQ + i) * DMODEL + h * DK + d;
        __half hh, ll; split_f16(acc, hh, ll);
        Oh[gidx] = hh;
        Ol[gidx] = ll;
    }
}

// ---------------- fp32 SGEMM (head only) ----------------
#define BM_S 128
#define BN_S 128
#define BK_S 8
__global__ void __launch_bounds__(256) sgemm_kernel(
    const float* __restrict__ A, const float* __restrict__ B,
    const float* __restrict__ bias, float* __restrict__ C,
    int M, int N, int K, int relu)
{
    __shared__ float As[BK_S][BM_S];
    __shared__ float Bs[BK_S][BN_S];
    const int tid = threadIdx.x;
    const int m0 = blockIdx.y * BM_S;
    const int n0 = blockIdx.x * BN_S;
    const int arow = tid >> 1;
    const int acol = (tid & 1) * 4;
    const int brow = tid >> 5;
    const int bcol = (tid & 31) * 4;
    const float* Aptr = A + (size_t)(m0 + arow) * K + acol;
    const float* Bptr = B + (size_t)brow * N + n0 + bcol;
    const int tx = tid & 15;
    const int ty = tid >> 4;
    float acc[8][8];
#pragma unroll
    for (int i = 0; i < 8; i++)
#pragma unroll
        for (int j = 0; j < 8; j++) acc[i][j] = 0.f;
    for (int k0 = 0; k0 < K; k0 += BK_S) {
        float4 a4 = *reinterpret_cast<const float4*>(Aptr + k0);
        float4 b4 = *reinterpret_cast<const float4*>(Bptr + (size_t)k0 * N);
        As[acol + 0][arow] = a4.x;
        As[acol + 1][arow] = a4.y;
        As[acol + 2][arow] = a4.z;
        As[acol + 3][arow] = a4.w;
        *reinterpret_cast<float4*>(&Bs[brow][bcol]) = b4;
        __syncthreads();
#pragma unroll
        for (int k = 0; k < BK_S; k++) {
            float ra[8], rb[8];
            *reinterpret_cast<float4*>(&ra[0]) = *reinterpret_cast<const float4*>(&As[k][ty * 8]);
            *reinterpret_cast<float4*>(&ra[4]) = *reinterpret_cast<const float4*>(&As[k][ty * 8 + 4]);
            *reinterpret_cast<float4*>(&rb[0]) = *reinterpret_cast<const float4*>(&Bs[k][tx * 8]);
            *reinterpret_cast<float4*>(&rb[4]) = *reinterpret_cast<const float4*>(&Bs[k][tx * 8 + 4]);
#pragma unroll
            for (int i = 0; i < 8; i++)
#pragma unroll
                for (int j = 0; j < 8; j++)
                    acc[i][j] = fmaf(ra[i], rb[j], acc[i][j]);
        }
        __syncthreads();
    }
#pragma unroll
    for (int i = 0; i < 8; i++) {
        const size_t base = (size_t)(m0 + ty * 8 + i) * N + n0 + tx * 8;
#pragma unroll
        for (int j = 0; j < 8; j++) {
            float v = acc[i][j] + __ldg(&bias[n0 + tx * 8 + j]);
            if (relu) v = fmaxf(v, 0.f);
            C[base + j] = v;
        }
    }
}

// ---------------- head kernels ----------------
__global__ void __launch_bounds__(256) pool_ln_scale_kernel(
    const float* __restrict__ hbuf,
    const float* __restrict__ fin_g, const float* __restrict__ fin_b,
    const float* __restrict__ bn_g, const float* __restrict__ bn_b,
    float* __restrict__ z)
{
    const int bb = blockIdx.x;
    const float* x = hbuf + (size_t)(bb * SEQ + (SEQ - 1)) * DMODEL;
    float vals[4];
    float s = 0.f, s2 = 0.f;
#pragma unroll
    for (int i = 0; i < 4; i++) {
        float v = x[threadIdx.x + i * 256];
        vals[i] = v; s += v; s2 += v * v;
    }
#pragma unroll
    for (int o = 16; o; o >>= 1) {
        s  += __shfl_xor_sync(0xffffffffu, s, o);
        s2 += __shfl_xor_sync(0xffffffffu, s2, o);
    }
    __shared__ float sh[2][8];
    const int w = threadIdx.x >> 5;
    if ((threadIdx.x & 31) == 0) { sh[0][w] = s; sh[1][w] = s2; }
    __syncthreads();
    if (threadIdx.x < 32) {
        s  = (threadIdx.x < 8) ? sh[0][threadIdx.x] : 0.f;
        s2 = (threadIdx.x < 8) ? sh[1][threadIdx.x] : 0.f;
#pragma unroll
        for (int o = 4; o; o >>= 1) {
            s  += __shfl_xor_sync(0xffffffffu, s, o);
            s2 += __shfl_xor_sync(0xffffffffu, s2, o);
        }
        if (threadIdx.x == 0) { sh[0][0] = s; sh[1][0] = s2; }
    }
    __syncthreads();
    const float mean = sh[0][0] * (1.f / (float)DMODEL);
    float var = (sh[1][0] - (float)DMODEL * mean * mean) * (1.f / (float)(DMODEL - 1));
    var = fmaxf(var, 0.f);
    const float inv = 1.f / (sqrtf(var) + 1e-6f);
    const float invbn = 1.f / sqrtf(1.0f + 1e-5f);
#pragma unroll
    for (int i = 0; i < 4; i++) {
        const int c = threadIdx.x + i * 256;
        const float lnv = fin_g[c] * (vals[i] - mean) * inv + fin_b[c];
        z[(size_t)bb * DMODEL + c] = lnv * invbn * bn_g[c] + bn_b[c];
    }
}

// fused bn2 + final fc
__global__ void __launch_bounds__(128) fc_kernel(
    const float* __restrict__ z1, const float* __restrict__ bn_g,
    const float* __restrict__ bn_b, const float* __restrict__ W,
    const float* __restrict__ bias, float* __restrict__ out)
{
    __shared__ float zs[DMODEL];
    const int bb = blockIdx.x;
    const float invbn = 1.f / sqrtf(1.0f + 1e-5f);
    for (int i = threadIdx.x; i < DMODEL; i += 128)
        zs[i] = z1[(size_t)bb * DMODEL + i] * invbn * bn_g[i] + bn_b[i];
    __syncthreads();
    const int c = threadIdx.x;
    if (c < NCLS) {
        float acc = bias[c];
        for (int k = 0; k < DMODEL; k++) acc = fmaf(zs[k], W[(size_t)k * NCLS + c], acc);
        out[(size_t)bb * NCLS + c] = acc;
    }
}

// ---------------- host launcher ----------------
template<int BM>
static inline void launch_tgemm(const __half* Ah, const __half* Al,
                                const __half* Bh, const __half* Bl,
                                const float* bias, const float* resid,
                                float* Cf, __half* Chi, __half* Clo,
                                int M, int N, int Kp, int epi)
{
    constexpr uint32_t STAGE = 2u * BM * 64u + 16384u;
    dim3 grid(N / 128, M / BM);
    tgemm_kernel<BM><<<grid, 256, 3 * STAGE>>>(Ah, Al, Bh, Bl, bias, resid, Cf, Chi, Clo, Kp, N, epi);
}

extern "C" void kernel_launch(void* const* d_in, const int* in_sizes, int n_in,
                              void* d_out, int out_size)
{
    const float* x        = (const float*)d_in[0];
    const float* embed_w  = (const float*)d_in[1];
    const float* attn_w   = (const float*)d_in[2];
    const float* attn_b   = (const float*)d_in[3];
    const float* ff_w1    = (const float*)d_in[4];
    const float* ff_b1    = (const float*)d_in[5];
    const float* ff_w2    = (const float*)d_in[6];
    const float* ff_b2    = (const float*)d_in[7];
    const float* ln_g     = (const float*)d_in[8];
    const float* ln_b     = (const float*)d_in[9];
    const float* fin_g    = (const float*)d_in[10];
    const float* fin_b    = (const float*)d_in[11];
    const float* cf_bn_g  = (const float*)d_in[12];
    const float* cf_bn_b  = (const float*)d_in[13];
    const float* cf_w     = (const float*)d_in[14];
    const float* cf_b     = (const float*)d_in[15];
    const float* fc_bn_g  = (const float*)d_in[16];
    const float* fc_bn_b  = (const float*)d_in[17];
    const float* fc_w     = (const float*)d_in[18];
    const float* fc_b     = (const float*)d_in[19];

    cudaFuncSetAttribute(tgemm_kernel<128>, cudaFuncAttributeMaxDynamicSharedMemorySize, 3 * 32768);
    cudaFuncSetAttribute(tgemm_kernel<64>,  cudaFuncAttributeMaxDynamicSharedMemorySize, 3 * 24576);

    float *g_h, *g_qkv, *g_z0, *g_z1;
    __half *g_xh, *g_xl, *g_ah, *g_al, *g_oh, *g_ol, *g_fh, *g_fl, *g_wth, *g_wtl;
    cudaGetSymbolAddress((void**)&g_h,   d_h);
    cudaGetSymbolAddress((void**)&g_qkv, d_qkv);
    cudaGetSymbolAddress((void**)&g_z0,  d_z0);
    cudaGetSymbolAddress((void**)&g_z1,  d_z1);
    cudaGetSymbolAddress((void**)&g_xh,  d_xh);
    cudaGetSymbolAddress((void**)&g_xl,  d_xl);
    cudaGetSymbolAddress((void**)&g_ah,  d_ah);
    cudaGetSymbolAddress((void**)&g_al,  d_al);
    cudaGetSymbolAddress((void**)&g_oh,  d_oh);
    cudaGetSymbolAddress((void**)&g_ol,  d_ol);
    cudaGetSymbolAddress((void**)&g_fh,  d_fh);
    cudaGetSymbolAddress((void**)&g_fl,  d_fl);
    cudaGetSymbolAddress((void**)&g_wth, d_wth);
    cudaGetSymbolAddress((void**)&g_wtl, d_wtl);

    dim3 blk(32, 8);

    // launch 1: input split
    cvt_x_kernel<<<(NTOK * KEMBP + 255) / 256, 256>>>(x, g_xh, g_xl);
    // launch 2: embed weight (K=1200 guard, Kp=1216)
    cvt_wT_batch_kernel<<<dim3(1024 / 32, KEMBP / 32, 1), blk>>>(
        embed_w, g_wth, g_wtl, KEMB, DMODEL, KEMBP, 0, 0, 0, 1);
    // launch 3: all attention weights (5 layers x 4 mats)
    cvt_wT_batch_kernel<<<dim3(32, 32, 20), blk>>>(
        attn_w, g_wth + WT_EMB_SZ, g_wtl + WT_EMB_SZ, DMODEL, DMODEL, DMODEL,
        (size_t)DMODEL * DMODEL, (size_t)WT_LAYER, (size_t)1048576u, 4);
    // launch 4: all ff1 weights
    cvt_wT_batch_kernel<<<dim3(DFF / 32, 32, 5), blk>>>(
        ff_w1, g_wth + WT_EMB_SZ + 4u * 1048576u, g_wtl + WT_EMB_SZ + 4u * 1048576u,
        DMODEL, DFF, DMODEL, (size_t)DMODEL * DFF, (size_t)WT_LAYER, 0, 1);
    // launch 5: all ff2 weights
    cvt_wT_batch_kernel<<<dim3(32, DFF / 32, 5), blk>>>(
        ff_w2, g_wth + WT_EMB_SZ + 8u * 1048576u, g_wtl + WT_EMB_SZ + 8u * 1048576u,
        DFF, DMODEL, DFF, (size_t)DFF * DMODEL, (size_t)WT_LAYER, 0, 1);

    // launch 6 (ncu -s 5 -c 1 profiles this): embed GEMM
    launch_tgemm<64>(g_xh, g_xl, g_wth, g_wtl, nullptr, nullptr,
                     g_h, nullptr, nullptr, NTOK, DMODEL, KEMBP, 3);

    for (int l = 0; l < NLAYER; l++) {
        const size_t lw = (size_t)WT_EMB_SZ + (size_t)l * WT_LAYER;
        const __half* wq_h = g_wth + lw;
        const __half* wq_l = g_wtl + lw;
        const float* bq = attn_b + (size_t)l * 4 * DMODEL;

        ln_kernel<<<NTOK, 256>>>(g_h, ln_g + (size_t)(l * 2) * DMODEL,
                                 ln_b + (size_t)(l * 2) * DMODEL, g_ah, g_al);
        launch_tgemm<128>(g_ah, g_al, wq_h, wq_l, bq, nullptr,
                          g_qkv, nullptr, nullptr, NTOK, NQKV, DMODEL, 0);
        attn_kernel<<<BATCH * NHEAD, 256>>>(g_qkv, g_oh, g_ol);
        launch_tgemm<64>(g_oh, g_ol, wq_h + 3u * 1048576u, wq_l + 3u * 1048576u,
                         bq + 3 * DMODEL, g_h, g_h, nullptr, nullptr, NTOK, DMODEL, DMODEL, 2);
        ln_kernel<<<NTOK, 256>>>(g_h, ln_g + (size_t)(l * 2 + 1) * DMODEL,
                                 ln_b + (size_t)(l * 2 + 1) * DMODEL, g_ah, g_al);
        launch_tgemm<128>(g_ah, g_al, g_wth + lw + 4u * 1048576u, g_wtl + lw + 4u * 1048576u,
                          ff_b1 + (size_t)l * DFF, nullptr, nullptr, g_fh, g_fl, NTOK, DFF, DMODEL, 1);
        launch_tgemm<64>(g_fh, g_fl, g_wth + lw + 8u * 1048576u, g_wtl + lw + 8u * 1048576u,
                         ff_b2 + (size_t)l * DMODEL, g_h, g_h, nullptr, nullptr, NTOK, DMODEL, DFF, 2);
    }

    // ---- classifier head ----
    pool_ln_scale_kernel<<<BATCH, 256>>>(g_h, fin_g, fin_b, cf_bn_g, cf_bn_b, g_z0);
    sgemm_kernel<<<dim3(DMODEL / BN_S, 1), 256>>>(g_z0, cf_w, cf_b, g_z1, BATCH, DMODEL, DMODEL, 1);
    fc_kernel<<<BATCH, 128>>>(g_z1, fc_bn_g, fc_bn_b, fc_w, fc_b, (float*)d_out);
}

// round 6
// speedup vs baseline: 1.0286x; 1.0286x over previous
#include <cuda_runtime.h>
#include <cuda_fp16.h>
#include <math.h>
#include <stdint.h>

// ---------------- problem constants ----------------
#define BATCH 128
#define SEQ   50
#define DMODEL 1024
#define DFF   4096
#define NHEAD 16
#define DK    64
#define NLAYER 5
#define KEMB  1200
#define KEMBP 1216
#define NTOK  6400
#define NCLS  71
#define NQKV  3072

#define GBK 32

// ---------------- weight scratch layout (transposed fp16 hi/lo) ----------------
#define WT_EMB_SZ (1024u*1216u)
#define WT_LAYER  (12u*1024u*1024u)
#define WT_TOTAL  (WT_EMB_SZ + 5u*WT_LAYER)

// ---------------- scratch (device globals) ----------------
__device__ float d_h  [NTOK * DMODEL];
__device__ float d_qkv[NTOK * NQKV];
__device__ float d_z0 [BATCH * DMODEL];
__device__ float d_z1 [BATCH * DMODEL];

__device__ __align__(16) __half d_xh[NTOK * KEMBP];
__device__ __align__(16) __half d_xl[NTOK * KEMBP];
__device__ __align__(16) __half d_ah[NTOK * DMODEL];
__device__ __align__(16) __half d_al[NTOK * DMODEL];
__device__ __align__(16) __half d_oh[NTOK * DMODEL];
__device__ __align__(16) __half d_ol[NTOK * DMODEL];
__device__ __align__(16) __half d_fh[NTOK * DFF];
__device__ __align__(16) __half d_fl[NTOK * DFF];
__device__ __align__(16) __half d_wth[WT_TOTAL];
__device__ __align__(16) __half d_wtl[WT_TOTAL];

// ---------------- PTX helpers ----------------
__device__ __forceinline__ uint32_t smem_u32(const void* p) {
    uint32_t a;
    asm("{ .reg .u64 t; cvta.to.shared.u64 t, %1; cvt.u32.u64 %0, t; }" : "=r"(a) : "l"(p));
    return a;
}
__device__ __forceinline__ void cpa16(uint32_t dst, const void* src) {
    asm volatile("cp.async.cg.shared.global [%0], [%1], 16;" :: "r"(dst), "l"(src));
}
#define CP_COMMIT() asm volatile("cp.async.commit_group;" ::: "memory")
#define CP_WAIT1()  asm volatile("cp.async.wait_group 1;" ::: "memory")
#define CP_WAIT0()  asm volatile("cp.async.wait_group 0;" ::: "memory")
#define LDSM4(r, a) \
    asm volatile("ldmatrix.sync.aligned.m8n8.x4.shared.b16 {%0,%1,%2,%3}, [%4];" \
        : "=r"((r)[0]), "=r"((r)[1]), "=r"((r)[2]), "=r"((r)[3]) : "r"(a))
#define MMA16816(c, a, b) \
    asm volatile("mma.sync.aligned.m16n8k16.row.col.f32.f16.f16.f32 " \
        "{%0,%1,%2,%3}, {%4,%5,%6,%7}, {%8,%9}, {%0,%1,%2,%3};" \
        : "+f"((c)[0]), "+f"((c)[1]), "+f"((c)[2]), "+f"((c)[3]) \
        : "r"((a)[0]), "r"((a)[1]), "r"((a)[2]), "r"((a)[3]), "r"((b)[0]), "r"((b)[1]))
__device__ __forceinline__ void red_add_f32(float* p, float v) {
    asm volatile("red.global.add.f32 [%0], %1;" :: "l"(p), "f"(v) : "memory");
}

__device__ __forceinline__ void split_f16(float v, __half& h, __half& l) {
    h = __float2half_rn(v);
    l = __float2half_rn(v - __half2float(h));
}

// ================= HMMA GEMM core (128x128 tile, 256 thr, 3-stage) =================
// shared load/compute helpers via macros to keep both kernels in sync
#define OFFAL 8192u
#define OFFBH 16384u
#define OFFBL 24576u
#define STAGE 32768u

// ---------------- standard GEMM with fused epilogue ----------------
// epi: 0 = +bias -> Cf; 1 = relu(+bias) -> Chi/Clo; 3 = +PE -> Cf
template<int BM>   // BM == 128 only
__global__ void __launch_bounds__(256, 2) tgemm_kernel(
    const __half* __restrict__ Ah, const __half* __restrict__ Al,
    const __half* __restrict__ Bh, const __half* __restrict__ Bl,
    const float* __restrict__ bias,
    float* __restrict__ Cf, __half* __restrict__ Chi, __half* __restrict__ Clo,
    int Kp, int N, int epi)
{
    extern __shared__ char sm[];
    const uint32_t smb = smem_u32(sm);
    const int tid  = threadIdx.x;
    const int lane = tid & 31;
    const int wid  = tid >> 5;
    const int wm   = wid & 3;
    const int wn   = wid >> 2;
    const int m0 = blockIdx.y * 128;
    const int n0 = blockIdx.x * 128;

    float acc[2][8][4];
#pragma unroll
    for (int i = 0; i < 2; i++)
#pragma unroll
        for (int j = 0; j < 8; j++)
#pragma unroll
            for (int t = 0; t < 4; t++) acc[i][j][t] = 0.f;

    auto load_stage = [&](int st, int k0) {
        const uint32_t sb = smb + (uint32_t)st * STAGE;
#pragma unroll
        for (int i = 0; i < 2; i++) {
            const int id = tid + i * 256;
            const int row = id >> 2, cc = id & 3;
            const uint32_t off = (uint32_t)((row << 6) + ((cc ^ ((row >> 1) & 3)) << 4));
            const size_t ka = (size_t)(m0 + row) * Kp + k0 + cc * 8;
            const size_t kb = (size_t)(n0 + row) * Kp + k0 + cc * 8;
            cpa16(sb + off, Ah + ka);
            cpa16(sb + OFFAL + off, Al + ka);
            cpa16(sb + OFFBH + off, Bh + kb);
            cpa16(sb + OFFBL + off, Bl + kb);
        }
    };

    auto compute = [&](int st) {
        const uint32_t sb = smb + (uint32_t)st * STAGE;
#pragma unroll
        for (int ks = 0; ks < 2; ks++) {
            uint32_t aH[2][4], aL[2][4];
#pragma unroll
            for (int mt = 0; mt < 2; mt++) {
                const int r = wm * 32 + mt * 16 + (lane & 15);
                const int ch = ks * 2 + (lane >> 4);
                const uint32_t off = (uint32_t)((r << 6) + ((ch ^ ((r >> 1) & 3)) << 4));
                LDSM4(aH[mt], sb + off);
                LDSM4(aL[mt], sb + OFFAL + off);
            }
#pragma unroll
            for (int half = 0; half < 2; half++) {
                uint32_t bH[4][2], bL[4][2];
#pragma unroll
                for (int p = 0; p < 2; p++) {
                    const int r = wn * 64 + (half * 2 + p) * 16 + (lane & 7) + ((lane & 16) >> 1);
                    const int ch = ks * 2 + ((lane >> 3) & 1);
                    const uint32_t off = (uint32_t)((r << 6) + ((ch ^ ((r >> 1) & 3)) << 4));
                    uint32_t q[4];
                    LDSM4(q, sb + OFFBH + off);
                    bH[p*2][0] = q[0]; bH[p*2][1] = q[1];
                    bH[p*2+1][0] = q[2]; bH[p*2+1][1] = q[3];
                    LDSM4(q, sb + OFFBL + off);
                    bL[p*2][0] = q[0]; bL[p*2][1] = q[1];
                    bL[p*2+1][0] = q[2]; bL[p*2+1][1] = q[3];
                }
#pragma unroll
                for (int mt = 0; mt < 2; mt++)
#pragma unroll
                    for (int nt = 0; nt < 4; nt++) MMA16816(acc[mt][half*4+nt], aH[mt], bH[nt]);
#pragma unroll
                for (int mt = 0; mt < 2; mt++)
#pragma unroll
                    for (int nt = 0; nt < 4; nt++) MMA16816(acc[mt][half*4+nt], aH[mt], bL[nt]);
#pragma unroll
                for (int mt = 0; mt < 2; mt++)
#pragma unroll
                    for (int nt = 0; nt < 4; nt++) MMA16816(acc[mt][half*4+nt], aL[mt], bH[nt]);
            }
        }
    };

    const int nchunk = Kp / GBK;
    load_stage(0, 0);
    CP_COMMIT();
    if (nchunk > 1) { load_stage(1, GBK); CP_COMMIT(); }
    int s_c = 0, s_ld = 2;
    for (int c = 0; c < nchunk; c++) {
        if (c + 1 < nchunk) CP_WAIT1(); else CP_WAIT0();
        __syncthreads();
        if (c + 2 < nchunk) { load_stage(s_ld, (c + 2) * GBK); CP_COMMIT(); }
        compute(s_c);
        s_c = (s_c == 2) ? 0 : s_c + 1;
        s_ld = (s_ld == 2) ? 0 : s_ld + 1;
    }

    // epilogue
#pragma unroll
    for (int mt = 0; mt < 2; mt++) {
        const int r0 = m0 + wm * 32 + mt * 16 + (lane >> 2);
#pragma unroll
        for (int nt = 0; nt < 8; nt++) {
            const int col = n0 + wn * 64 + nt * 8 + (lane & 3) * 2;
            const float* a = acc[mt][nt];
            if (epi == 1) {
                const float b0 = __ldg(&bias[col]);
                const float b1 = __ldg(&bias[col + 1]);
#pragma unroll
                for (int rr = 0; rr < 2; rr++) {
                    const int row = r0 + rr * 8;
                    const float v0 = fmaxf(a[rr * 2 + 0] + b0, 0.f);
                    const float v1 = fmaxf(a[rr * 2 + 1] + b1, 0.f);
                    __half h0, l0, h1, l1;
                    split_f16(v0, h0, l0);
                    split_f16(v1, h1, l1);
                    *reinterpret_cast<__half2*>(&Chi[(size_t)row * N + col]) = __halves2half2(h0, h1);
                    *reinterpret_cast<__half2*>(&Clo[(size_t)row * N + col]) = __halves2half2(l0, l1);
                }
            } else if (epi == 3) {
                const float dv = expf((float)(col & ~1) * (-9.210340371976184f / (float)DMODEL));
#pragma unroll
                for (int rr = 0; rr < 2; rr++) {
                    const int row = r0 + rr * 8;
                    const int srow = row % SEQ;
                    float sn, cs;
                    sincosf((float)srow * dv, &sn, &cs);
                    float2 o;
                    o.x = a[rr * 2 + 0] + sn;
                    o.y = a[rr * 2 + 1] + cs;
                    *reinterpret_cast<float2*>(&Cf[(size_t)row * N + col]) = o;
                }
            } else {
                const float b0 = __ldg(&bias[col]);
                const float b1 = __ldg(&bias[col + 1]);
#pragma unroll
                for (int rr = 0; rr < 2; rr++) {
                    const int row = r0 + rr * 8;
                    float2 o;
                    o.x = a[rr * 2 + 0] + b0;
                    o.y = a[rr * 2 + 1] + b1;
                    *reinterpret_cast<float2*>(&Cf[(size_t)row * N + col]) = o;
                }
            }
        }
    }
}

// ---------------- split-K GEMM: partial sums atomically added into prefilled C ----------------
__global__ void __launch_bounds__(256, 2) tgemm_atomic_kernel(
    const __half* __restrict__ Ah, const __half* __restrict__ Al,
    const __half* __restrict__ Bh, const __half* __restrict__ Bl,
    float* __restrict__ Cf, int Kp, int Kz, int N)
{
    extern __shared__ char sm[];
    const uint32_t smb = smem_u32(sm);
    const int tid  = threadIdx.x;
    const int lane = tid & 31;
    const int wid  = tid >> 5;
    const int wm   = wid & 3;
    const int wn   = wid >> 2;
    const int m0 = blockIdx.y * 128;
    const int n0 = blockIdx.x * 128;
    const int kbase = blockIdx.z * Kz;

    float acc[2][8][4];
#pragma unroll
    for (int i = 0; i < 2; i++)
#pragma unroll
        for (int j = 0; j < 8; j++)
#pragma unroll
            for (int t = 0; t < 4; t++) acc[i][j][t] = 0.f;

    auto load_stage = [&](int st, int k0) {
        const uint32_t sb = smb + (uint32_t)st * STAGE;
#pragma unroll
        for (int i = 0; i < 2; i++) {
            const int id = tid + i * 256;
            const int row = id >> 2, cc = id & 3;
            const uint32_t off = (uint32_t)((row << 6) + ((cc ^ ((row >> 1) & 3)) << 4));
            const size_t ka = (size_t)(m0 + row) * Kp + k0 + cc * 8;
            const size_t kb = (size_t)(n0 + row) * Kp + k0 + cc * 8;
            cpa16(sb + off, Ah + ka);
            cpa16(sb + OFFAL + off, Al + ka);
            cpa16(sb + OFFBH + off, Bh + kb);
            cpa16(sb + OFFBL + off, Bl + kb);
        }
    };

    auto compute = [&](int st) {
        const uint32_t sb = smb + (uint32_t)st * STAGE;
#pragma unroll
        for (int ks = 0; ks < 2; ks++) {
            uint32_t aH[2][4], aL[2][4];
#pragma unroll
            for (int mt = 0; mt < 2; mt++) {
                const int r = wm * 32 + mt * 16 + (lane & 15);
                const int ch = ks * 2 + (lane >> 4);
                const uint32_t off = (uint32_t)((r << 6) + ((ch ^ ((r >> 1) & 3)) << 4));
                LDSM4(aH[mt], sb + off);
                LDSM4(aL[mt], sb + OFFAL + off);
            }
#pragma unroll
            for (int half = 0; half < 2; half++) {
                uint32_t bH[4][2], bL[4][2];
#pragma unroll
                for (int p = 0; p < 2; p++) {
                    const int r = wn * 64 + (half * 2 + p) * 16 + (lane & 7) + ((lane & 16) >> 1);
                    const int ch = ks * 2 + ((lane >> 3) & 1);
                    const uint32_t off = (uint32_t)((r << 6) + ((ch ^ ((r >> 1) & 3)) << 4));
                    uint32_t q[4];
                    LDSM4(q, sb + OFFBH + off);
                    bH[p*2][0] = q[0]; bH[p*2][1] = q[1];
                    bH[p*2+1][0] = q[2]; bH[p*2+1][1] = q[3];
                    LDSM4(q, sb + OFFBL + off);
                    bL[p*2][0] = q[0]; bL[p*2][1] = q[1];
                    bL[p*2+1][0] = q[2]; bL[p*2+1][1] = q[3];
                }
#pragma unroll
                for (int mt = 0; mt < 2; mt++)
#pragma unroll
                    for (int nt = 0; nt < 4; nt++) MMA16816(acc[mt][half*4+nt], aH[mt], bH[nt]);
#pragma unroll
                for (int mt = 0; mt < 2; mt++)
#pragma unroll
                    for (int nt = 0; nt < 4; nt++) MMA16816(acc[mt][half*4+nt], aH[mt], bL[nt]);
#pragma unroll
                for (int mt = 0; mt < 2; mt++)
#pragma unroll
                    for (int nt = 0; nt < 4; nt++) MMA16816(acc[mt][half*4+nt], aL[mt], bH[nt]);
            }
        }
    };

    const int nchunk = Kz / GBK;
    load_stage(0, kbase);
    CP_COMMIT();
    if (nchunk > 1) { load_stage(1, kbase + GBK); CP_COMMIT(); }
    int s_c = 0, s_ld = 2;
    for (int c = 0; c < nchunk; c++) {
        if (c + 1 < nchunk) CP_WAIT1(); else CP_WAIT0();
        __syncthreads();
        if (c + 2 < nchunk) { load_stage(s_ld, kbase + (c + 2) * GBK); CP_COMMIT(); }
        compute(s_c);
        s_c = (s_c == 2) ? 0 : s_c + 1;
        s_ld = (s_ld == 2) ? 0 : s_ld + 1;
    }

    // atomic epilogue
#pragma unroll
    for (int mt = 0; mt < 2; mt++) {
        const int r0 = m0 + wm * 32 + mt * 16 + (lane >> 2);
#pragma unroll
        for (int nt = 0; nt < 8; nt++) {
            const int col = n0 + wn * 64 + nt * 8 + (lane & 3) * 2;
            const float* a = acc[mt][nt];
#pragma unroll
            for (int rr = 0; rr < 2; rr++) {
                const int row = r0 + rr * 8;
                float* p = &Cf[(size_t)row * N + col];
                red_add_f32(p,     a[rr * 2 + 0]);
                red_add_f32(p + 1, a[rr * 2 + 1]);
            }
        }
    }
}

// ---------------- prefill: C[i] += bias[col] (residual already resident in C) ----------------
__global__ void __launch_bounds__(256) prefill_bias_kernel(
    float* __restrict__ C, const float* __restrict__ bias)
{
    const int i = blockIdx.x * 256 + threadIdx.x;     // float4 index
    const int col = (i * 4) & (DMODEL - 1);
    float4 c = reinterpret_cast<float4*>(C)[i];
    const float4 b = *reinterpret_cast<const float4*>(&bias[col]);
    c.x += b.x; c.y += b.y; c.z += b.z; c.w += b.w;
    reinterpret_cast<float4*>(C)[i] = c;
}

// ---------------- converters ----------------
__global__ void __launch_bounds__(256) cvt_x_kernel(
    const float* __restrict__ x, __half* __restrict__ xh, __half* __restrict__ xl)
{
    const int idx = blockIdx.x * 256 + threadIdx.x;
    if (idx >= NTOK * KEMBP) return;
    const int r = idx / KEMBP, c = idx % KEMBP;
    const float v = (c < KEMB) ? x[(size_t)r * KEMB + c] : 0.f;
    __half h, l; split_f16(v, h, l);
    xh[idx] = h; xl[idx] = l;
}

__global__ void cvt_wT_batch_kernel(
    const float* __restrict__ W, __half* __restrict__ Th, __half* __restrict__ Tl,
    int K, int N, int Kp,
    size_t w_stride, size_t o_outer, size_t o_inner, int inner_mod)
{
    const int z = blockIdx.z;
    const float* Wz = W + (size_t)z * w_stride;
    const size_t ooff = (size_t)(z / inner_mod) * o_outer + (size_t)(z % inner_mod) * o_inner;
    __shared__ float t[32][33];
    const int k0 = blockIdx.y * 32, n0 = blockIdx.x * 32;
    const int tx = threadIdx.x, ty = threadIdx.y;
#pragma unroll
    for (int i = 0; i < 32; i += 8) {
        const int k = k0 + ty + i;
        t[ty + i][tx] = (k < K) ? Wz[(size_t)k * N + n0 + tx] : 0.f;
    }
    __syncthreads();
#pragma unroll
    for (int i = 0; i < 32; i += 8) {
        const int n = n0 + ty + i;
        const int k = k0 + tx;
        __half h, l; split_f16(t[tx][ty + i], h, l);
        Th[ooff + (size_t)n * Kp + k] = h;
        Tl[ooff + (size_t)n * Kp + k] = l;
    }
}

// ---------------- LayerNorm (ddof=1, eps on std) -> fp16 hi/lo ----------------
__global__ void __launch_bounds__(256) ln_kernel(
    const float* __restrict__ in, const float* __restrict__ g,
    const float* __restrict__ b, __half* __restrict__ outh, __half* __restrict__ outl)
{
    const int row = blockIdx.x;
    const float* x = in + (size_t)row * DMODEL;
    float vals[4];
    float s = 0.f, s2 = 0.f;
#pragma unroll
    for (int i = 0; i < 4; i++) {
        float v = x[threadIdx.x + i * 256];
        vals[i] = v; s += v; s2 += v * v;
    }
#pragma unroll
    for (int o = 16; o; o >>= 1) {
        s  += __shfl_xor_sync(0xffffffffu, s, o);
        s2 += __shfl_xor_sync(0xffffffffu, s2, o);
    }
    __shared__ float sh[2][8];
    const int w = threadIdx.x >> 5;
    if ((threadIdx.x & 31) == 0) { sh[0][w] = s; sh[1][w] = s2; }
    __syncthreads();
    if (threadIdx.x < 32) {
        s  = (threadIdx.x < 8) ? sh[0][threadIdx.x] : 0.f;
        s2 = (threadIdx.x < 8) ? sh[1][threadIdx.x] : 0.f;
#pragma unroll
        for (int o = 4; o; o >>= 1) {
            s  += __shfl_xor_sync(0xffffffffu, s, o);
            s2 += __shfl_xor_sync(0xffffffffu, s2, o);
        }
        if (threadIdx.x == 0) { sh[0][0] = s; sh[1][0] = s2; }
    }
    __syncthreads();
    const float mean = sh[0][0] * (1.f / (float)DMODEL);
    float var = (sh[1][0] - (float)DMODEL * mean * mean) * (1.f / (float)(DMODEL - 1));
    var = fmaxf(var, 0.f);
    const float inv = 1.f / (sqrtf(var) + 1e-6f);
#pragma unroll
    for (int i = 0; i < 4; i++) {
        const int c = threadIdx.x + i * 256;
        const float r = g[c] * (vals[i] - mean) * inv + b[c];
        __half h, l; split_f16(r, h, l);
        outh[(size_t)row * DMODEL + c] = h;
        outl[(size_t)row * DMODEL + c] = l;
    }
}

// ---------------- attention on fused QKV buffer ----------------
__global__ void __launch_bounds__(256) attn_kernel(
    const float* __restrict__ QKV, __half* __restrict__ Oh, __half* __restrict__ Ol)
{
    const int bh = blockIdx.x;
    const int b = bh >> 4;
    const int h = bh & 15;

    __shared__ float qs[SEQ][DK];
    __shared__ float ks[SEQ][DK + 1];
    __shared__ float vs[SEQ][DK];
    __shared__ float sc[SEQ][SEQ];

    const int tid = threadIdx.x;
    for (int e = tid; e < SEQ * DK; e += 256) {
        const int s = e >> 6;
        const int d = e & 63;
        const size_t gbase = (size_t)(b * SEQ + s) * NQKV + h * DK + d;
        qs[s][d] = QKV[gbase];
        ks[s][d] = QKV[gbase + DMODEL];
        vs[s][d] = QKV[gbase + 2 * DMODEL];
    }
    __syncthreads();

    for (int e = tid; e < SEQ * SEQ; e += 256) {
        const int i = e / SEQ;
        const int j = e % SEQ;
        float acc = 0.f;
#pragma unroll
        for (int d = 0; d < DK; d++) acc = fmaf(qs[i][d], ks[j][d], acc);
        sc[i][j] = acc * 0.125f;
    }
    __syncthreads();

    if (tid < SEQ) {
        float mx = -1e30f;
#pragma unroll 1
        for (int j = 0; j < SEQ; j++) mx = fmaxf(mx, sc[tid][j]);
        float sum = 0.f;
#pragma unroll 1
        for (int j = 0; j < SEQ; j++) {
            float ev = expf(sc[tid][j] - mx);
            sum += ev;
            sc[tid][j] = ev;
        }
        const float r = 1.f / sum;
#pragma unroll 1
        for (int j = 0; j < SEQ; j++) sc[tid][j] *= r;
    }
    __syncthreads();

    for (int e = tid; e < SEQ * DK; e += 256) {
        const int i = e >> 6;
        const int d = e & 63;
        float acc = 0.f;
#pragma unroll
        for (int j = 0; j < SEQ; j++) acc = fmaf(sc[i][j], vs[j][d], acc);
        const size_t gidx = (size_t)(b * SEQ + i) * DMODEL + h * DK + d;
        __half hh, ll; split_f16(acc, hh, ll);
        Oh[gidx] = hh;
        Ol[gidx] = ll;
    }
}

// ---------------- fp32 SGEMM (head only) ----------------
#define BM_S 128
#define BN_S 128
#define BK_S 8
__global__ void __launch_bounds__(256) sgemm_kernel(
    const float* __restrict__ A, const float* __restrict__ B,
    const float* __restrict__ bias, float* __restrict__ C,
    int M, int N, int K, int relu)
{
    __shared__ float As[BK_S][BM_S];
    __shared__ float Bs[BK_S][BN_S];
    const int tid = threadIdx.x;
    const int m0 = blockIdx.y * BM_S;
    const int n0 = blockIdx.x * BN_S;
    const int arow = tid >> 1;
    const int acol = (tid & 1) * 4;
    const int brow = tid >> 5;
    const int bcol = (tid & 31) * 4;
    const float* Aptr = A + (size_t)(m0 + arow) * K + acol;
    const float* Bptr = B + (size_t)brow * N + n0 + bcol;
    const int tx = tid & 15;
    const int ty = tid >> 4;
    float acc[8][8];
#pragma unroll
    for (int i = 0; i < 8; i++)
#pragma unroll
        for (int j = 0; j < 8; j++) acc[i][j] = 0.f;
    for (int k0 = 0; k0 < K; k0 += BK_S) {
        float4 a4 = *reinterpret_cast<const float4*>(Aptr + k0);
        float4 b4 = *reinterpret_cast<const float4*>(Bptr + (size_t)k0 * N);
        As[acol + 0][arow] = a4.x;
        As[acol + 1][arow] = a4.y;
        As[acol + 2][arow] = a4.z;
        As[acol + 3][arow] = a4.w;
        *reinterpret_cast<float4*>(&Bs[brow][bcol]) = b4;
        __syncthreads();
#pragma unroll
        for (int k = 0; k < BK_S; k++) {
            float ra[8], rb[8];
            *reinterpret_cast<float4*>(&ra[0]) = *reinterpret_cast<const float4*>(&As[k][ty * 8]);
            *reinterpret_cast<float4*>(&ra[4]) = *reinterpret_cast<const float4*>(&As[k][ty * 8 + 4]);
            *reinterpret_cast<float4*>(&rb[0]) = *reinterpret_cast<const float4*>(&Bs[k][tx * 8]);
            *reinterpret_cast<float4*>(&rb[4]) = *reinterpret_cast<const float4*>(&Bs[k][tx * 8 + 4]);
#pragma unroll
            for (int i = 0; i < 8; i++)
#pragma unroll
                for (int j = 0; j < 8; j++)
                    acc[i][j] = fmaf(ra[i], rb[j], acc[i][j]);
        }
        __syncthreads();
    }
#pragma unroll
    for (int i = 0; i < 8; i++) {
        const size_t base = (size_t)(m0 + ty * 8 + i) * N + n0 + tx * 8;
#pragma unroll
        for (int j = 0; j < 8; j++) {
            float v = acc[i][j] + __ldg(&bias[n0 + tx * 8 + j]);
            if (relu) v = fmaxf(v, 0.f);
            C[base + j] = v;
        }
    }
}

// ---------------- head kernels ----------------
__global__ void __launch_bounds__(256) pool_ln_scale_kernel(
    const float* __restrict__ hbuf,
    const float* __restrict__ fin_g, const float* __restrict__ fin_b,
    const float* __restrict__ bn_g, const float* __restrict__ bn_b,
    float* __restrict__ z)
{
    const int bb = blockIdx.x;
    const float* x = hbuf + (size_t)(bb * SEQ + (SEQ - 1)) * DMODEL;
    float vals[4];
    float s = 0.f, s2 = 0.f;
#pragma unroll
    for (int i = 0; i < 4; i++) {
        float v = x[threadIdx.x + i * 256];
        vals[i] = v; s += v; s2 += v * v;
    }
#pragma unroll
    for (int o = 16; o; o >>= 1) {
        s  += __shfl_xor_sync(0xffffffffu, s, o);
        s2 += __shfl_xor_sync(0xffffffffu, s2, o);
    }
    __shared__ float sh[2][8];
    const int w = threadIdx.x >> 5;
    if ((threadIdx.x & 31) == 0) { sh[0][w] = s; sh[1][w] = s2; }
    __syncthreads();
    if (threadIdx.x < 32) {
        s  = (threadIdx.x < 8) ? sh[0][threadIdx.x] : 0.f;
        s2 = (threadIdx.x < 8) ? sh[1][threadIdx.x] : 0.f;
#pragma unroll
        for (int o = 4; o; o >>= 1) {
            s  += __shfl_xor_sync(0xffffffffu, s, o);
            s2 += __shfl_xor_sync(0xffffffffu, s2, o);
        }
        if (threadIdx.x == 0) { sh[0][0] = s; sh[1][0] = s2; }
    }
    __syncthreads();
    const float mean = sh[0][0] * (1.f / (float)DMODEL);
    float var = (sh[1][0] - (float)DMODEL * mean * mean) * (1.f / (float)(DMODEL - 1));
    var = fmaxf(var, 0.f);
    const float inv = 1.f / (sqrtf(var) + 1e-6f);
    const float invbn = 1.f / sqrtf(1.0f + 1e-5f);
#pragma unroll
    for (int i = 0; i < 4; i++) {
        const int c = threadIdx.x + i * 256;
        const float lnv = fin_g[c] * (vals[i] - mean) * inv + fin_b[c];
        z[(size_t)bb * DMODEL + c] = lnv * invbn * bn_g[c] + bn_b[c];
    }
}

__global__ void __launch_bounds__(128) fc_kernel(
    const float* __restrict__ z1, const float* __restrict__ bn_g,
    const float* __restrict__ bn_b, const float* __restrict__ W,
    const float* __restrict__ bias, float* __restrict__ out)
{
    __shared__ float zs[DMODEL];
    const int bb = blockIdx.x;
    const float invbn = 1.f / sqrtf(1.0f + 1e-5f);
    for (int i = threadIdx.x; i < DMODEL; i += 128)
        zs[i] = z1[(size_t)bb * DMODEL + i] * invbn * bn_g[i] + bn_b[i];
    __syncthreads();
    const int c = threadIdx.x;
    if (c < NCLS) {
        float acc = bias[c];
        for (int k = 0; k < DMODEL; k++) acc = fmaf(zs[k], W[(size_t)k * NCLS + c], acc);
        out[(size_t)bb * NCLS + c] = acc;
    }
}

// ---------------- host launcher ----------------
extern "C" void kernel_launch(void* const* d_in, const int* in_sizes, int n_in,
                              void* d_out, int out_size)
{
    const float* x        = (const float*)d_in[0];
    const float* embed_w  = (const float*)d_in[1];
    const float* attn_w   = (const float*)d_in[2];
    const float* attn_b   = (const float*)d_in[3];
    const float* ff_w1    = (const float*)d_in[4];
    const float* ff_b1    = (const float*)d_in[5];
    const float* ff_w2    = (const float*)d_in[6];
    const float* ff_b2    = (const float*)d_in[7];
    const float* ln_g     = (const float*)d_in[8];
    const float* ln_b     = (const float*)d_in[9];
    const float* fin_g    = (const float*)d_in[10];
    const float* fin_b    = (const float*)d_in[11];
    const float* cf_bn_g  = (const float*)d_in[12];
    const float* cf_bn_b  = (const float*)d_in[13];
    const float* cf_w     = (const float*)d_in[14];
    const float* cf_b     = (const float*)d_in[15];
    const float* fc_bn_g  = (const float*)d_in[16];
    const float* fc_bn_b  = (const float*)d_in[17];
    const float* fc_w     = (const float*)d_in[18];
    const float* fc_b     = (const float*)d_in[19];

    cudaFuncSetAttribute(tgemm_kernel<128>, cudaFuncAttributeMaxDynamicSharedMemorySize, 3 * STAGE);
    cudaFuncSetAttribute(tgemm_atomic_kernel, cudaFuncAttributeMaxDynamicSharedMemorySize, 3 * STAGE);

    float *g_h, *g_qkv, *g_z0, *g_z1;
    __half *g_xh, *g_xl, *g_ah, *g_al, *g_oh, *g_ol, *g_fh, *g_fl, *g_wth, *g_wtl;
    cudaGetSymbolAddress((void**)&g_h,   d_h);
    cudaGetSymbolAddress((void**)&g_qkv, d_qkv);
    cudaGetSymbolAddress((void**)&g_z0,  d_z0);
    cudaGetSymbolAddress((void**)&g_z1,  d_z1);
    cudaGetSymbolAddress((void**)&g_xh,  d_xh);
    cudaGetSymbolAddress((void**)&g_xl,  d_xl);
    cudaGetSymbolAddress((void**)&g_ah,  d_ah);
    cudaGetSymbolAddress((void**)&g_al,  d_al);
    cudaGetSymbolAddress((void**)&g_oh,  d_oh);
    cudaGetSymbolAddress((void**)&g_ol,  d_ol);
    cudaGetSymbolAddress((void**)&g_fh,  d_fh);
    cudaGetSymbolAddress((void**)&g_fl,  d_fl);
    cudaGetSymbolAddress((void**)&g_wth, d_wth);
    cudaGetSymbolAddress((void**)&g_wtl, d_wtl);

    dim3 blk(32, 8);

    // launch 1: input split
    cvt_x_kernel<<<(NTOK * KEMBP + 255) / 256, 256>>>(x, g_xh, g_xl);
    // launch 2: embed weight
    cvt_wT_batch_kernel<<<dim3(1024 / 32, KEMBP / 32, 1), blk>>>(
        embed_w, g_wth, g_wtl, KEMB, DMODEL, KEMBP, 0, 0, 0, 1);
    // launch 3 (ncu target): embed GEMM, h = X @ We + PE
    {
        dim3 grid(DMODEL / 128, NTOK / 128);
        tgemm_kernel<128><<<grid, 256, 3 * STAGE>>>(
            g_xh, g_xl, g_wth, g_wtl, nullptr, g_h, nullptr, nullptr, KEMBP, DMODEL, 3);
    }
    // launches 4-6: remaining weight converts
    cvt_wT_batch_kernel<<<dim3(32, 32, 20), blk>>>(
        attn_w, g_wth + WT_EMB_SZ, g_wtl + WT_EMB_SZ, DMODEL, DMODEL, DMODEL,
        (size_t)DMODEL * DMODEL, (size_t)WT_LAYER, (size_t)1048576u, 4);
    cvt_wT_batch_kernel<<<dim3(DFF / 32, 32, 5), blk>>>(
        ff_w1, g_wth + WT_EMB_SZ + 4u * 1048576u, g_wtl + WT_EMB_SZ + 4u * 1048576u,
        DMODEL, DFF, DMODEL, (size_t)DMODEL * DFF, (size_t)WT_LAYER, 0, 1);
    cvt_wT_batch_kernel<<<dim3(32, DFF / 32, 5), blk>>>(
        ff_w2, g_wth + WT_EMB_SZ + 8u * 1048576u, g_wtl + WT_EMB_SZ + 8u * 1048576u,
        DFF, DMODEL, DFF, (size_t)DFF * DMODEL, (size_t)WT_LAYER, 0, 1);

    for (int l = 0; l < NLAYER; l++) {
        const size_t lw = (size_t)WT_EMB_SZ + (size_t)l * WT_LAYER;
        const __half* wq_h = g_wth + lw;
        const __half* wq_l = g_wtl + lw;
        const float* bq = attn_b + (size_t)l * 4 * DMODEL;

        ln_kernel<<<NTOK, 256>>>(g_h, ln_g + (size_t)(l * 2) * DMODEL,
                                 ln_b + (size_t)(l * 2) * DMODEL, g_ah, g_al);
        // fused QKV
        {
            dim3 grid(NQKV / 128, NTOK / 128);
            tgemm_kernel<128><<<grid, 256, 3 * STAGE>>>(
                g_ah, g_al, wq_h, wq_l, bq, g_qkv, nullptr, nullptr, DMODEL, NQKV, 0);
        }
        attn_kernel<<<BATCH * NHEAD, 256>>>(g_qkv, g_oh, g_ol);
        // out-proj: h += o @ Wo + bo   (prefill bias, split-K=2 atomic)
        prefill_bias_kernel<<<NTOK * DMODEL / 4 / 256, 256>>>(g_h, bq + 3 * DMODEL);
        {
            dim3 grid(DMODEL / 128, NTOK / 128, 2);
            tgemm_atomic_kernel<<<grid, 256, 3 * STAGE>>>(
                g_oh, g_ol, wq_h + 3u * 1048576u, wq_l + 3u * 1048576u,
                g_h, DMODEL, DMODEL / 2, DMODEL);
        }
        ln_kernel<<<NTOK, 256>>>(g_h, ln_g + (size_t)(l * 2 + 1) * DMODEL,
                                 ln_b + (size_t)(l * 2 + 1) * DMODEL, g_ah, g_al);
        // FF1
        {
            dim3 grid(DFF / 128, NTOK / 128);
            tgemm_kernel<128><<<grid, 256, 3 * STAGE>>>(
                g_ah, g_al, g_wth + lw + 4u * 1048576u, g_wtl + lw + 4u * 1048576u,
                ff_b1 + (size_t)l * DFF, nullptr, g_fh, g_fl, DMODEL, DFF, 1);
        }
        // FF2: h += ff @ W2 + b2   (prefill bias, split-K=2 atomic)
        prefill_bias_kernel<<<NTOK * DMODEL / 4 / 256, 256>>>(g_h, ff_b2 + (size_t)l * DMODEL);
        {
            dim3 grid(DMODEL / 128, NTOK / 128, 2);
            tgemm_atomic_kernel<<<grid, 256, 3 * STAGE>>>(
                g_fh, g_fl, g_wth + lw + 8u * 1048576u, g_wtl + lw + 8u * 1048576u,
                g_h, DFF, DFF / 2, DMODEL);
        }
    }

    // ---- classifier head ----
    pool_ln_scale_kernel<<<BATCH, 256>>>(g_h, fin_g, fin_b, cf_bn_g, cf_bn_b, g_z0);
    sgemm_kernel<<<dim3(DMODEL / BN_S, 1), 256>>>(g_z0, cf_w, cf_b, g_z1, BATCH, DMODEL, DMODEL, 1);
    fc_kernel<<<BATCH, 128>>>(g_z1, fc_bn_g, fc_bn_b, fc_w, fc_b, (float*)d_out);
}

// round 7
// speedup vs baseline: 1.0361x; 1.0074x over previous
#include <cuda_runtime.h>
#include <cuda_fp16.h>
#include <math.h>
#include <stdint.h>

// ---------------- problem constants ----------------
#define BATCH 128
#define SEQ   50
#define DMODEL 1024
#define DFF   4096
#define NHEAD 16
#define DK    64
#define NLAYER 5
#define KEMB  1200
#define KEMBP 1216
#define NTOK  6400
#define NCLS  71
#define NQKV  3072

#define GBK 32

// ---------------- weight scratch layout (transposed fp16 hi/lo) ----------------
#define WT_EMB_SZ (1024u*1216u)
#define WT_LAYER  (12u*1024u*1024u)
#define WT_TOTAL  (WT_EMB_SZ + 5u*WT_LAYER)

// ---------------- scratch (device globals) ----------------
__device__ float d_h  [NTOK * DMODEL];
__device__ float d_qkv[NTOK * NQKV];
__device__ float d_z0 [BATCH * DMODEL];
__device__ float d_z1 [BATCH * DMODEL];

__device__ __align__(16) __half d_xh[NTOK * KEMBP];
__device__ __align__(16) __half d_xl[NTOK * KEMBP];
__device__ __align__(16) __half d_ah[NTOK * DMODEL];
__device__ __align__(16) __half d_al[NTOK * DMODEL];
__device__ __align__(16) __half d_oh[NTOK * DMODEL];
__device__ __align__(16) __half d_ol[NTOK * DMODEL];
__device__ __align__(16) __half d_fh[NTOK * DFF];
__device__ __align__(16) __half d_fl[NTOK * DFF];
__device__ __align__(16) __half d_wth[WT_TOTAL];
__device__ __align__(16) __half d_wtl[WT_TOTAL];

// ---------------- PTX helpers ----------------
__device__ __forceinline__ uint32_t smem_u32(const void* p) {
    uint32_t a;
    asm("{ .reg .u64 t; cvta.to.shared.u64 t, %1; cvt.u32.u64 %0, t; }" : "=r"(a) : "l"(p));
    return a;
}
__device__ __forceinline__ void cpa16(uint32_t dst, const void* src) {
    asm volatile("cp.async.cg.shared.global [%0], [%1], 16;" :: "r"(dst), "l"(src));
}
#define CP_COMMIT() asm volatile("cp.async.commit_group;" ::: "memory")
#define CP_WAIT1()  asm volatile("cp.async.wait_group 1;" ::: "memory")
#define CP_WAIT0()  asm volatile("cp.async.wait_group 0;" ::: "memory")
#define LDSM4(r, a) \
    asm volatile("ldmatrix.sync.aligned.m8n8.x4.shared.b16 {%0,%1,%2,%3}, [%4];" \
        : "=r"((r)[0]), "=r"((r)[1]), "=r"((r)[2]), "=r"((r)[3]) : "r"(a))
#define MMA16816(c, a, b) \
    asm volatile("mma.sync.aligned.m16n8k16.row.col.f32.f16.f16.f32 " \
        "{%0,%1,%2,%3}, {%4,%5,%6,%7}, {%8,%9}, {%0,%1,%2,%3};" \
        : "+f"((c)[0]), "+f"((c)[1]), "+f"((c)[2]), "+f"((c)[3]) \
        : "r"((a)[0]), "r"((a)[1]), "r"((a)[2]), "r"((a)[3]), "r"((b)[0]), "r"((b)[1]))
__device__ __forceinline__ void red_add_f32(float* p, float v) {
    asm volatile("red.global.add.f32 [%0], %1;" :: "l"(p), "f"(v) : "memory");
}

__device__ __forceinline__ void split_f16(float v, __half& h, __half& l) {
    h = __float2half_rn(v);
    l = __float2half_rn(v - __half2float(h));
}

// ================= HMMA GEMM core: 128x128 CTA tile, 128 thr, 4 warps (2x2, 64x64 warp tile)
#define OFFAL 8192u
#define OFFBH 16384u
#define OFFBL 24576u
#define STAGE 32768u

#define TG_LOAD_STAGE(sb, k0)                                                  \
    do {                                                                       \
        _Pragma("unroll")                                                      \
        for (int i_ = 0; i_ < 4; i_++) {                                       \
            const int id_ = tid + i_ * 128;                                    \
            const int row_ = id_ >> 2, cc_ = id_ & 3;                          \
            const uint32_t off_ = (uint32_t)((row_ << 6) + ((cc_ ^ ((row_ >> 1) & 3)) << 4)); \
            const size_t ka_ = (size_t)(m0 + row_) * Kp + (k0) + cc_ * 8;      \
            const size_t kb_ = (size_t)(n0 + row_) * Kp + (k0) + cc_ * 8;      \
            cpa16((sb) + off_, Ah + ka_);                                      \
            cpa16((sb) + OFFAL + off_, Al + ka_);                              \
            cpa16((sb) + OFFBH + off_, Bh + kb_);                              \
            cpa16((sb) + OFFBL + off_, Bl + kb_);                              \
        }                                                                      \
    } while (0)

#define TG_COMPUTE(sb)                                                         \
    do {                                                                       \
        _Pragma("unroll")                                                      \
        for (int ks = 0; ks < 2; ks++) {                                       \
            uint32_t aH[4][4], aL[4][4];                                       \
            _Pragma("unroll")                                                  \
            for (int mt = 0; mt < 4; mt++) {                                   \
                const int r = wm * 64 + mt * 16 + (lane & 15);                 \
                const int ch = ks * 2 + (lane >> 4);                           \
                const uint32_t off = (uint32_t)((r << 6) + ((ch ^ ((r >> 1) & 3)) << 4)); \
                LDSM4(aH[mt], (sb) + off);                                     \
                LDSM4(aL[mt], (sb) + OFFAL + off);                             \
            }                                                                  \
            _Pragma("unroll")                                                  \
            for (int half = 0; half < 2; half++) {                             \
                uint32_t bH[4][2], bL[4][2];                                   \
                _Pragma("unroll")                                              \
                for (int p = 0; p < 2; p++) {                                  \
                    const int r = wn * 64 + half * 32 + p * 16 + (lane & 7) + ((lane & 16) >> 1); \
                    const int ch = ks * 2 + ((lane >> 3) & 1);                 \
                    const uint32_t off = (uint32_t)((r << 6) + ((ch ^ ((r >> 1) & 3)) << 4)); \
                    uint32_t q[4];                                             \
                    LDSM4(q, (sb) + OFFBH + off);                              \
                    bH[p*2][0] = q[0]; bH[p*2][1] = q[1];                      \
                    bH[p*2+1][0] = q[2]; bH[p*2+1][1] = q[3];                  \
                    LDSM4(q, (sb) + OFFBL + off);                              \
                    bL[p*2][0] = q[0]; bL[p*2][1] = q[1];                      \
                    bL[p*2+1][0] = q[2]; bL[p*2+1][1] = q[3];                  \
                }                                                              \
                _Pragma("unroll")                                              \
                for (int mt = 0; mt < 4; mt++)                                 \
                    _Pragma("unroll")                                          \
                    for (int nt = 0; nt < 4; nt++) MMA16816(acc[mt][half*4+nt], aH[mt], bH[nt]); \
                _Pragma("unroll")                                              \
                for (int mt = 0; mt < 4; mt++)                                 \
                    _Pragma("unroll")                                          \
                    for (int nt = 0; nt < 4; nt++) MMA16816(acc[mt][half*4+nt], aH[mt], bL[nt]); \
                _Pragma("unroll")                                              \
                for (int mt = 0; mt < 4; mt++)                                 \
                    _Pragma("unroll")                                          \
                    for (int nt = 0; nt < 4; nt++) MMA16816(acc[mt][half*4+nt], aL[mt], bH[nt]); \
            }                                                                  \
        }                                                                      \
    } while (0)

#define TG_MAINLOOP(kbase, nchunk)                                             \
    do {                                                                       \
        TG_LOAD_STAGE(smb, (kbase));                                           \
        CP_COMMIT();                                                           \
        if ((nchunk) > 1) { TG_LOAD_STAGE(smb + STAGE, (kbase) + GBK); CP_COMMIT(); } \
        int s_c = 0, s_ld = 2;                                                 \
        for (int c = 0; c < (nchunk); c++) {                                   \
            if (c + 1 < (nchunk)) CP_WAIT1(); else CP_WAIT0();                 \
            __syncthreads();                                                   \
            if (c + 2 < (nchunk)) { TG_LOAD_STAGE(smb + (uint32_t)s_ld * STAGE, (kbase) + (c + 2) * GBK); CP_COMMIT(); } \
            TG_COMPUTE(smb + (uint32_t)s_c * STAGE);                           \
            s_c = (s_c == 2) ? 0 : s_c + 1;                                    \
            s_ld = (s_ld == 2) ? 0 : s_ld + 1;                                 \
        }                                                                      \
    } while (0)

// ---------------- standard GEMM with fused epilogue ----------------
// epi: 0 = +bias -> Cf; 1 = relu(+bias) -> Chi/Clo; 3 = +PE -> Cf
__global__ void __launch_bounds__(128, 2) tgemm_kernel(
    const __half* __restrict__ Ah, const __half* __restrict__ Al,
    const __half* __restrict__ Bh, const __half* __restrict__ Bl,
    const float* __restrict__ bias,
    float* __restrict__ Cf, __half* __restrict__ Chi, __half* __restrict__ Clo,
    int Kp, int N, int epi)
{
    extern __shared__ char sm[];
    const uint32_t smb = smem_u32(sm);
    const int tid  = threadIdx.x;
    const int lane = tid & 31;
    const int wid  = tid >> 5;
    const int wm   = wid & 1;
    const int wn   = wid >> 1;
    const int m0 = blockIdx.y * 128;
    const int n0 = blockIdx.x * 128;

    float acc[4][8][4];
#pragma unroll
    for (int i = 0; i < 4; i++)
#pragma unroll
        for (int j = 0; j < 8; j++)
#pragma unroll
            for (int t = 0; t < 4; t++) acc[i][j][t] = 0.f;

    TG_MAINLOOP(0, Kp / GBK);

    // epilogue
#pragma unroll
    for (int mt = 0; mt < 4; mt++) {
        const int r0 = m0 + wm * 64 + mt * 16 + (lane >> 2);
#pragma unroll
        for (int nt = 0; nt < 8; nt++) {
            const int col = n0 + wn * 64 + nt * 8 + (lane & 3) * 2;
            const float* a = acc[mt][nt];
            if (epi == 1) {
                const float b0 = __ldg(&bias[col]);
                const float b1 = __ldg(&bias[col + 1]);
#pragma unroll
                for (int rr = 0; rr < 2; rr++) {
                    const int row = r0 + rr * 8;
                    const float v0 = fmaxf(a[rr * 2 + 0] + b0, 0.f);
                    const float v1 = fmaxf(a[rr * 2 + 1] + b1, 0.f);
                    __half h0, l0, h1, l1;
                    split_f16(v0, h0, l0);
                    split_f16(v1, h1, l1);
                    *reinterpret_cast<__half2*>(&Chi[(size_t)row * N + col]) = __halves2half2(h0, h1);
                    *reinterpret_cast<__half2*>(&Clo[(size_t)row * N + col]) = __halves2half2(l0, l1);
                }
            } else if (epi == 3) {
                const float dv = expf((float)(col & ~1) * (-9.210340371976184f / (float)DMODEL));
#pragma unroll
                for (int rr = 0; rr < 2; rr++) {
                    const int row = r0 + rr * 8;
                    const int srow = row % SEQ;
                    float sn, cs;
                    sincosf((float)srow * dv, &sn, &cs);
                    float2 o;
                    o.x = a[rr * 2 + 0] + sn;
                    o.y = a[rr * 2 + 1] + cs;
                    *reinterpret_cast<float2*>(&Cf[(size_t)row * N + col]) = o;
                }
            } else {
                const float b0 = __ldg(&bias[col]);
                const float b1 = __ldg(&bias[col + 1]);
#pragma unroll
                for (int rr = 0; rr < 2; rr++) {
                    const int row = r0 + rr * 8;
                    float2 o;
                    o.x = a[rr * 2 + 0] + b0;
                    o.y = a[rr * 2 + 1] + b1;
                    *reinterpret_cast<float2*>(&Cf[(size_t)row * N + col]) = o;
                }
            }
        }
    }
}

// ---------------- split-K GEMM: partial sums atomically added into prefilled C ----------------
__global__ void __launch_bounds__(128, 2) tgemm_atomic_kernel(
    const __half* __restrict__ Ah, const __half* __restrict__ Al,
    const __half* __restrict__ Bh, const __half* __restrict__ Bl,
    float* __restrict__ Cf, int Kp, int Kz, int N)
{
    extern __shared__ char sm[];
    const uint32_t smb = smem_u32(sm);
    const int tid  = threadIdx.x;
    const int lane = tid & 31;
    const int wid  = tid >> 5;
    const int wm   = wid & 1;
    const int wn   = wid >> 1;
    const int m0 = blockIdx.y * 128;
    const int n0 = blockIdx.x * 128;
    const int kbase = blockIdx.z * Kz;

    float acc[4][8][4];
#pragma unroll
    for (int i = 0; i < 4; i++)
#pragma unroll
        for (int j = 0; j < 8; j++)
#pragma unroll
            for (int t = 0; t < 4; t++) acc[i][j][t] = 0.f;

    TG_MAINLOOP(kbase, Kz / GBK);

    // atomic epilogue
#pragma unroll
    for (int mt = 0; mt < 4; mt++) {
        const int r0 = m0 + wm * 64 + mt * 16 + (lane >> 2);
#pragma unroll
        for (int nt = 0; nt < 8; nt++) {
            const int col = n0 + wn * 64 + nt * 8 + (lane & 3) * 2;
            const float* a = acc[mt][nt];
#pragma unroll
            for (int rr = 0; rr < 2; rr++) {
                const int row = r0 + rr * 8;
                float* p = &Cf[(size_t)row * N + col];
                red_add_f32(p,     a[rr * 2 + 0]);
                red_add_f32(p + 1, a[rr * 2 + 1]);
            }
        }
    }
}

// ---------------- converters ----------------
__global__ void __launch_bounds__(256) cvt_x_kernel(
    const float* __restrict__ x, __half* __restrict__ xh, __half* __restrict__ xl)
{
    const int idx = blockIdx.x * 256 + threadIdx.x;
    if (idx >= NTOK * KEMBP) return;
    const int r = idx / KEMBP, c = idx % KEMBP;
    const float v = (c < KEMB) ? x[(size_t)r * KEMB + c] : 0.f;
    __half h, l; split_f16(v, h, l);
    xh[idx] = h; xl[idx] = l;
}

__global__ void cvt_wT_batch_kernel(
    const float* __restrict__ W, __half* __restrict__ Th, __half* __restrict__ Tl,
    int K, int N, int Kp,
    size_t w_stride, size_t o_outer, size_t o_inner, int inner_mod)
{
    const int z = blockIdx.z;
    const float* Wz = W + (size_t)z * w_stride;
    const size_t ooff = (size_t)(z / inner_mod) * o_outer + (size_t)(z % inner_mod) * o_inner;
    __shared__ float t[32][33];
    const int k0 = blockIdx.y * 32, n0 = blockIdx.x * 32;
    const int tx = threadIdx.x, ty = threadIdx.y;
#pragma unroll
    for (int i = 0; i < 32; i += 8) {
        const int k = k0 + ty + i;
        t[ty + i][tx] = (k < K) ? Wz[(size_t)k * N + n0 + tx] : 0.f;
    }
    __syncthreads();
#pragma unroll
    for (int i = 0; i < 32; i += 8) {
        const int n = n0 + ty + i;
        const int k = k0 + tx;
        __half h, l; split_f16(t[tx][ty + i], h, l);
        Th[ooff + (size_t)n * Kp + k] = h;
        Tl[ooff + (size_t)n * Kp + k] = l;
    }
}

// ---------------- LayerNorm (ddof=1, eps on std) -> fp16 hi/lo, optional h += bias fused ----------------
__global__ void __launch_bounds__(256) ln_kernel(
    float* __restrict__ hio, const float* __restrict__ g,
    const float* __restrict__ b, __half* __restrict__ outh, __half* __restrict__ outl,
    const float* __restrict__ pbias)
{
    const int row = blockIdx.x;
    float* x = hio + (size_t)row * DMODEL;
    float vals[4];
    float s = 0.f, s2 = 0.f;
#pragma unroll
    for (int i = 0; i < 4; i++) {
        float v = x[threadIdx.x + i * 256];
        vals[i] = v; s += v; s2 += v * v;
    }
#pragma unroll
    for (int o = 16; o; o >>= 1) {
        s  += __shfl_xor_sync(0xffffffffu, s, o);
        s2 += __shfl_xor_sync(0xffffffffu, s2, o);
    }
    __shared__ float sh[2][8];
    const int w = threadIdx.x >> 5;
    if ((threadIdx.x & 31) == 0) { sh[0][w] = s; sh[1][w] = s2; }
    __syncthreads();
    if (threadIdx.x < 32) {
        s  = (threadIdx.x < 8) ? sh[0][threadIdx.x] : 0.f;
        s2 = (threadIdx.x < 8) ? sh[1][threadIdx.x] : 0.f;
#pragma unroll
        for (int o = 4; o; o >>= 1) {
            s  += __shfl_xor_sync(0xffffffffu, s, o);
            s2 += __shfl_xor_sync(0xffffffffu, s2, o);
        }
        if (threadIdx.x == 0) { sh[0][0] = s; sh[1][0] = s2; }
    }
    __syncthreads();
    const float mean = sh[0][0] * (1.f / (float)DMODEL);
    float var = (sh[1][0] - (float)DMODEL * mean * mean) * (1.f / (float)(DMODEL - 1));
    var = fmaxf(var, 0.f);
    const float inv = 1.f / (sqrtf(var) + 1e-6f);
#pragma unroll
    for (int i = 0; i < 4; i++) {
        const int c = threadIdx.x + i * 256;
        const float r = g[c] * (vals[i] - mean) * inv + b[c];
        __half h, l; split_f16(r, h, l);
        outh[(size_t)row * DMODEL + c] = h;
        outl[(size_t)row * DMODEL + c] = l;
        if (pbias) x[c] = vals[i] + pbias[c];   // prefill h += bias for upcoming atomic GEMM
    }
}

// ---------------- attention on fused QKV buffer ----------------
__global__ void __launch_bounds__(256) attn_kernel(
    const float* __restrict__ QKV, __half* __restrict__ Oh, __half* __restrict__ Ol)
{
    const int bh = blockIdx.x;
    const int b = bh >> 4;
    const int h = bh & 15;

    __shared__ float qs[SEQ][DK];
    __shared__ float ks[SEQ][DK + 1];
    __shared__ float vs[SEQ][DK];
    __shared__ float sc[SEQ][SEQ];

    const int tid = threadIdx.x;
    for (int e = tid; e < SEQ * DK; e += 256) {
        const int s = e >> 6;
        const int d = e & 63;
        const size_t gbase = (size_t)(b * SEQ + s) * NQKV + h * DK + d;
        qs[s][d] = QKV[gbase];
        ks[s][d] = QKV[gbase + DMODEL];
        vs[s][d] = QKV[gbase + 2 * DMODEL];
    }
    __syncthreads();

    for (int e = tid; e < SEQ * SEQ; e += 256) {
        const int i = e / SEQ;
        const int j = e % SEQ;
        float acc = 0.f;
#pragma unroll
        for (int d = 0; d < DK; d++) acc = fmaf(qs[i][d], ks[j][d], acc);
        sc[i][j] = acc * 0.125f;
    }
    __syncthreads();

    if (tid < SEQ) {
        float mx = -1e30f;
#pragma unroll 1
        for (int j = 0; j < SEQ; j++) mx = fmaxf(mx, sc[tid][j]);
        float sum = 0.f;
#pragma unroll 1
        for (int j = 0; j < SEQ; j++) {
            float ev = expf(sc[tid][j] - mx);
            sum += ev;
            sc[tid][j] = ev;
        }
        const float r = 1.f / sum;
#pragma unroll 1
        for (int j = 0; j < SEQ; j++) sc[tid][j] *= r;
    }
    __syncthreads();

    for (int e = tid; e < SEQ * DK; e += 256) {
        const int i = e >> 6;
        const int d = e & 63;
        float acc = 0.f;
#pragma unroll
        for (int j = 0; j < SEQ; j++) acc = fmaf(sc[i][j], vs[j][d], acc);
        const size_t gidx = (size_t)(b * SEQ + i) * DMODEL + h * DK + d;
        __half hh, ll; split_f16(acc, hh, ll);
        Oh[gidx] = hh;
        Ol[gidx] = ll;
    }
}

// ---------------- fp32 SGEMM (head only) ----------------
#define BM_S 128
#define BN_S 128
#define BK_S 8
__global__ void __launch_bounds__(256) sgemm_kernel(
    const float* __restrict__ A, const float* __restrict__ B,
    const float* __restrict__ bias, float* __restrict__ C,
    int M, int N, int K, int relu)
{
    __shared__ float As[BK_S][BM_S];
    __shared__ float Bs[BK_S][BN_S];
    const int tid = threadIdx.x;
    const int m0 = blockIdx.y * BM_S;
    const int n0 = blockIdx.x * BN_S;
    const int arow = tid >> 1;
    const int acol = (tid & 1) * 4;
    const int brow = tid >> 5;
    const int bcol = (tid & 31) * 4;
    const float* Aptr = A + (size_t)(m0 + arow) * K + acol;
    const float* Bptr = B + (size_t)brow * N + n0 + bcol;
    const int tx = tid & 15;
    const int ty = tid >> 4;
    float acc[8][8];
#pragma unroll
    for (int i = 0; i < 8; i++)
#pragma unroll
        for (int j = 0; j < 8; j++) acc[i][j] = 0.f;
    for (int k0 = 0; k0 < K; k0 += BK_S) {
        float4 a4 = *reinterpret_cast<const float4*>(Aptr + k0);
        float4 b4 = *reinterpret_cast<const float4*>(Bptr + (size_t)k0 * N);
        As[acol + 0][arow] = a4.x;
        As[acol + 1][arow] = a4.y;
        As[acol + 2][arow] = a4.z;
        As[acol + 3][arow] = a4.w;
        *reinterpret_cast<float4*>(&Bs[brow][bcol]) = b4;
        __syncthreads();
#pragma unroll
        for (int k = 0; k < BK_S; k++) {
            float ra[8], rb[8];
            *reinterpret_cast<float4*>(&ra[0]) = *reinterpret_cast<const float4*>(&As[k][ty * 8]);
            *reinterpret_cast<float4*>(&ra[4]) = *reinterpret_cast<const float4*>(&As[k][ty * 8 + 4]);
            *reinterpret_cast<float4*>(&rb[0]) = *reinterpret_cast<const float4*>(&Bs[k][tx * 8]);
            *reinterpret_cast<float4*>(&rb[4]) = *reinterpret_cast<const float4*>(&Bs[k][tx * 8 + 4]);
#pragma unroll
            for (int i = 0; i < 8; i++)
#pragma unroll
                for (int j = 0; j < 8; j++)
                    acc[i][j] = fmaf(ra[i], rb[j], acc[i][j]);
        }
        __syncthreads();
    }
#pragma unroll
    for (int i = 0; i < 8; i++) {
        const size_t base = (size_t)(m0 + ty * 8 + i) * N + n0 + tx * 8;
#pragma unroll
        for (int j = 0; j < 8; j++) {
            float v = acc[i][j] + __ldg(&bias[n0 + tx * 8 + j]);
            if (relu) v = fmaxf(v, 0.f);
            C[base + j] = v;
        }
    }
}

// ---------------- head kernels ----------------
__global__ void __launch_bounds__(256) pool_ln_scale_kernel(
    const float* __restrict__ hbuf,
    const float* __restrict__ fin_g, const float* __restrict__ fin_b,
    const float* __restrict__ bn_g, const float* __restrict__ bn_b,
    float* __restrict__ z)
{
    const int bb = blockIdx.x;
    const float* x = hbuf + (size_t)(bb * SEQ + (SEQ - 1)) * DMODEL;
    float vals[4];
    float s = 0.f, s2 = 0.f;
#pragma unroll
    for (int i = 0; i < 4; i++) {
        float v = x[threadIdx.x + i * 256];
        vals[i] = v; s += v; s2 += v * v;
    }
#pragma unroll
    for (int o = 16; o; o >>= 1) {
        s  += __shfl_xor_sync(0xffffffffu, s, o);
        s2 += __shfl_xor_sync(0xffffffffu, s2, o);
    }
    __shared__ float sh[2][8];
    const int w = threadIdx.x >> 5;
    if ((threadIdx.x & 31) == 0) { sh[0][w] = s; sh[1][w] = s2; }
    __syncthreads();
    if (threadIdx.x < 32) {
        s  = (threadIdx.x < 8) ? sh[0][threadIdx.x] : 0.f;
        s2 = (threadIdx.x < 8) ? sh[1][threadIdx.x] : 0.f;
#pragma unroll
        for (int o = 4; o; o >>= 1) {
            s  += __shfl_xor_sync(0xffffffffu, s, o);
            s2 += __shfl_xor_sync(0xffffffffu, s2, o);
        }
        if (threadIdx.x == 0) { sh[0][0] = s; sh[1][0] = s2; }
    }
    __syncthreads();
    const float mean = sh[0][0] * (1.f / (float)DMODEL);
    float var = (sh[1][0] - (float)DMODEL * mean * mean) * (1.f / (float)(DMODEL - 1));
    var = fmaxf(var, 0.f);
    const float inv = 1.f / (sqrtf(var) + 1e-6f);
    const float invbn = 1.f / sqrtf(1.0f + 1e-5f);
#pragma unroll
    for (int i = 0; i < 4; i++) {
        const int c = threadIdx.x + i * 256;
        const float lnv = fin_g[c] * (vals[i] - mean) * inv + fin_b[c];
        z[(size_t)bb * DMODEL + c] = lnv * invbn * bn_g[c] + bn_b[c];
    }
}

__global__ void __launch_bounds__(128) fc_kernel(
    const float* __restrict__ z1, const float* __restrict__ bn_g,
    const float* __restrict__ bn_b, const float* __restrict__ W,
    const float* __restrict__ bias, float* __restrict__ out)
{
    __shared__ float zs[DMODEL];
    const int bb = blockIdx.x;
    const float invbn = 1.f / sqrtf(1.0f + 1e-5f);
    for (int i = threadIdx.x; i < DMODEL; i += 128)
        zs[i] = z1[(size_t)bb * DMODEL + i] * invbn * bn_g[i] + bn_b[i];
    __syncthreads();
    const int c = threadIdx.x;
    if (c < NCLS) {
        float acc = bias[c];
        for (int k = 0; k < DMODEL; k++) acc = fmaf(zs[k], W[(size_t)k * NCLS + c], acc);
        out[(size_t)bb * NCLS + c] = acc;
    }
}

// ---------------- host launcher ----------------
extern "C" void kernel_launch(void* const* d_in, const int* in_sizes, int n_in,
                              void* d_out, int out_size)
{
    const float* x        = (const float*)d_in[0];
    const float* embed_w  = (const float*)d_in[1];
    const float* attn_w   = (const float*)d_in[2];
    const float* attn_b   = (const float*)d_in[3];
    const float* ff_w1    = (const float*)d_in[4];
    const float* ff_b1    = (const float*)d_in[5];
    const float* ff_w2    = (const float*)d_in[6];
    const float* ff_b2    = (const float*)d_in[7];
    const float* ln_g     = (const float*)d_in[8];
    const float* ln_b     = (const float*)d_in[9];
    const float* fin_g    = (const float*)d_in[10];
    const float* fin_b    = (const float*)d_in[11];
    const float* cf_bn_g  = (const float*)d_in[12];
    const float* cf_bn_b  = (const float*)d_in[13];
    const float* cf_w     = (const float*)d_in[14];
    const float* cf_b     = (const float*)d_in[15];
    const float* fc_bn_g  = (const float*)d_in[16];
    const float* fc_bn_b  = (const float*)d_in[17];
    const float* fc_w     = (const float*)d_in[18];
    const float* fc_b     = (const float*)d_in[19];

    cudaFuncSetAttribute(tgemm_kernel, cudaFuncAttributeMaxDynamicSharedMemorySize, 3 * STAGE);
    cudaFuncSetAttribute(tgemm_atomic_kernel, cudaFuncAttributeMaxDynamicSharedMemorySize, 3 * STAGE);

    float *g_h, *g_qkv, *g_z0, *g_z1;
    __half *g_xh, *g_xl, *g_ah, *g_al, *g_oh, *g_ol, *g_fh, *g_fl, *g_wth, *g_wtl;
    cudaGetSymbolAddress((void**)&g_h,   d_h);
    cudaGetSymbolAddress((void**)&g_qkv, d_qkv);
    cudaGetSymbolAddress((void**)&g_z0,  d_z0);
    cudaGetSymbolAddress((void**)&g_z1,  d_z1);
    cudaGetSymbolAddress((void**)&g_xh,  d_xh);
    cudaGetSymbolAddress((void**)&g_xl,  d_xl);
    cudaGetSymbolAddress((void**)&g_ah,  d_ah);
    cudaGetSymbolAddress((void**)&g_al,  d_al);
    cudaGetSymbolAddress((void**)&g_oh,  d_oh);
    cudaGetSymbolAddress((void**)&g_ol,  d_ol);
    cudaGetSymbolAddress((void**)&g_fh,  d_fh);
    cudaGetSymbolAddress((void**)&g_fl,  d_fl);
    cudaGetSymbolAddress((void**)&g_wth, d_wth);
    cudaGetSymbolAddress((void**)&g_wtl, d_wtl);

    dim3 blk(32, 8);

    // launch 1: input split
    cvt_x_kernel<<<(NTOK * KEMBP + 255) / 256, 256>>>(x, g_xh, g_xl);
    // launch 2: embed weight
    cvt_wT_batch_kernel<<<dim3(1024 / 32, KEMBP / 32, 1), blk>>>(
        embed_w, g_wth, g_wtl, KEMB, DMODEL, KEMBP, 0, 0, 0, 1);
    // launch 3: attention weights
    cvt_wT_batch_kernel<<<dim3(32, 32, 20), blk>>>(
        attn_w, g_wth + WT_EMB_SZ, g_wtl + WT_EMB_SZ, DMODEL, DMODEL, DMODEL,
        (size_t)DMODEL * DMODEL, (size_t)WT_LAYER, (size_t)1048576u, 4);
    // launch 4: ff1 weights
    cvt_wT_batch_kernel<<<dim3(DFF / 32, 32, 5), blk>>>(
        ff_w1, g_wth + WT_EMB_SZ + 4u * 1048576u, g_wtl + WT_EMB_SZ + 4u * 1048576u,
        DMODEL, DFF, DMODEL, (size_t)DMODEL * DFF, (size_t)WT_LAYER, 0, 1);
    // launch 5 (ncu target): embed GEMM, h = X @ We + PE
    {
        dim3 grid(DMODEL / 128, NTOK / 128);
        tgemm_kernel<<<grid, 128, 3 * STAGE>>>(
            g_xh, g_xl, g_wth, g_wtl, nullptr, g_h, nullptr, nullptr, KEMBP, DMODEL, 3);
    }
    // launch 6: ff2 weights
    cvt_wT_batch_kernel<<<dim3(32, DFF / 32, 5), blk>>>(
        ff_w2, g_wth + WT_EMB_SZ + 8u * 1048576u, g_wtl + WT_EMB_SZ + 8u * 1048576u,
        DFF, DMODEL, DFF, (size_t)DFF * DMODEL, (size_t)WT_LAYER, 0, 1);

    for (int l = 0; l < NLAYER; l++) {
        const size_t lw = (size_t)WT_EMB_SZ + (size_t)l * WT_LAYER;
        const __half* wq_h = g_wth + lw;
        const __half* wq_l = g_wtl + lw;
        const float* bq = attn_b + (size_t)l * 4 * DMODEL;

        // LN1 (fused: h += out-proj bias for the later atomic GEMM)
        ln_kernel<<<NTOK, 256>>>(g_h, ln_g + (size_t)(l * 2) * DMODEL,
                                 ln_b + (size_t)(l * 2) * DMODEL, g_ah, g_al,
                                 bq + 3 * DMODEL);
        // fused QKV
        {
            dim3 grid(NQKV / 128, NTOK / 128);
            tgemm_kernel<<<grid, 128, 3 * STAGE>>>(
                g_ah, g_al, wq_h, wq_l, bq, g_qkv, nullptr, nullptr, DMODEL, NQKV, 0);
        }
        attn_kernel<<<BATCH * NHEAD, 256>>>(g_qkv, g_oh, g_ol);
        // out-proj: h += o @ Wo (bias already prefilled by LN1), split-K=2 atomic
        {
            dim3 grid(DMODEL / 128, NTOK / 128, 2);
            tgemm_atomic_kernel<<<grid, 128, 3 * STAGE>>>(
                g_oh, g_ol, wq_h + 3u * 1048576u, wq_l + 3u * 1048576u,
                g_h, DMODEL, DMODEL / 2, DMODEL);
        }
        // LN2 (fused: h += ff2 bias)
        ln_kernel<<<NTOK, 256>>>(g_h, ln_g + (size_t)(l * 2 + 1) * DMODEL,
                                 ln_b + (size_t)(l * 2 + 1) * DMODEL, g_ah, g_al,
                                 ff_b2 + (size_t)l * DMODEL);
        // FF1
        {
            dim3 grid(DFF / 128, NTOK / 128);
            tgemm_kernel<<<grid, 128, 3 * STAGE>>>(
                g_ah, g_al, g_wth + lw + 4u * 1048576u, g_wtl + lw + 4u * 1048576u,
                ff_b1 + (size_t)l * DFF, nullptr, g_fh, g_fl, DMODEL, DFF, 1);
        }
        // FF2: h += ff @ W2 (bias prefilled by LN2), split-K=2 atomic
        {
            dim3 grid(DMODEL / 128, NTOK / 128, 2);
            tgemm_atomic_kernel<<<grid, 128, 3 * STAGE>>>(
                g_fh, g_fl, g_wth + lw + 8u * 1048576u, g_wtl + lw + 8u * 1048576u,
                g_h, DFF, DFF / 2, DMODEL);
        }
    }

    // ---- classifier head ----
    pool_ln_scale_kernel<<<BATCH, 256>>>(g_h, fin_g, fin_b, cf_bn_g, cf_bn_b, g_z0);
    sgemm_kernel<<<dim3(DMODEL / BN_S, 1), 256>>>(g_z0, cf_w, cf_b, g_z1, BATCH, DMODEL, DMODEL, 1);
    fc_kernel<<<BATCH, 128>>>(g_z1, fc_bn_g, fc_bn_b, fc_w, fc_b, (float*)d_out);
}

// round 8
// speedup vs baseline: 1.1670x; 1.1263x over previous
#include <cuda_runtime.h>
#include <cuda_fp16.h>
#include <math.h>
#include <stdint.h>

// ---------------- problem constants ----------------
#define BATCH 128
#define SEQ   50
#define DMODEL 1024
#define DFF   4096
#define NHEAD 16
#define DK    64
#define NLAYER 5
#define KEMB  1200
#define KEMBP 1216
#define NTOK  6400
#define NCLS  71
#define NQKV  3072

#define GBK 32

// ---------------- weight scratch layout (transposed fp16 hi/lo) ----------------
#define WT_EMB_SZ (1024u*1216u)
#define WT_LAYER  (12u*1024u*1024u)
#define WT_TOTAL  (WT_EMB_SZ + 5u*WT_LAYER)

// ---------------- scratch (device globals) ----------------
__device__ float d_h  [NTOK * DMODEL];
__device__ float d_qkv[NTOK * NQKV];
__device__ float d_hc [BATCH * DMODEL];     // compact last-token h (layer 5 tail)
__device__ float d_z0 [BATCH * DMODEL];
__device__ float d_z1 [BATCH * DMODEL];

__device__ __align__(16) __half d_xh[NTOK * KEMBP];
__device__ __align__(16) __half d_xl[NTOK * KEMBP];
__device__ __align__(16) __half d_ah[NTOK * DMODEL];
__device__ __align__(16) __half d_al[NTOK * DMODEL];
__device__ __align__(16) __half d_oh[NTOK * DMODEL];
__device__ __align__(16) __half d_ol[NTOK * DMODEL];
__device__ __align__(16) __half d_fh[NTOK * DFF];
__device__ __align__(16) __half d_fl[NTOK * DFF];
__device__ __align__(16) __half d_wth[WT_TOTAL];
__device__ __align__(16) __half d_wtl[WT_TOTAL];
// compact (128-row) buffers for last-layer tail
__device__ __align__(16) __half d_och[BATCH * DMODEL];
__device__ __align__(16) __half d_ocl[BATCH * DMODEL];
__device__ __align__(16) __half d_ach[BATCH * DMODEL];
__device__ __align__(16) __half d_acl[BATCH * DMODEL];
__device__ __align__(16) __half d_fch[BATCH * DFF];
__device__ __align__(16) __half d_fcl[BATCH * DFF];

// ---------------- PTX helpers ----------------
__device__ __forceinline__ uint32_t smem_u32(const void* p) {
    uint32_t a;
    asm("{ .reg .u64 t; cvta.to.shared.u64 t, %1; cvt.u32.u64 %0, t; }" : "=r"(a) : "l"(p));
    return a;
}
__device__ __forceinline__ void cpa16(uint32_t dst, const void* src) {
    asm volatile("cp.async.cg.shared.global [%0], [%1], 16;" :: "r"(dst), "l"(src));
}
#define CP_COMMIT() asm volatile("cp.async.commit_group;" ::: "memory")
#define CP_WAIT1()  asm volatile("cp.async.wait_group 1;" ::: "memory")
#define CP_WAIT0()  asm volatile("cp.async.wait_group 0;" ::: "memory")
#define LDSM4(r, a) \
    asm volatile("ldmatrix.sync.aligned.m8n8.x4.shared.b16 {%0,%1,%2,%3}, [%4];" \
        : "=r"((r)[0]), "=r"((r)[1]), "=r"((r)[2]), "=r"((r)[3]) : "r"(a))
#define MMA16816(c, a, b) \
    asm volatile("mma.sync.aligned.m16n8k16.row.col.f32.f16.f16.f32 " \
        "{%0,%1,%2,%3}, {%4,%5,%6,%7}, {%8,%9}, {%0,%1,%2,%3};" \
        : "+f"((c)[0]), "+f"((c)[1]), "+f"((c)[2]), "+f"((c)[3]) \
        : "r"((a)[0]), "r"((a)[1]), "r"((a)[2]), "r"((a)[3]), "r"((b)[0]), "r"((b)[1]))
__device__ __forceinline__ void red_add_f32(float* p, float v) {
    asm volatile("red.global.add.f32 [%0], %1;" :: "l"(p), "f"(v) : "memory");
}

__device__ __forceinline__ void split_f16(float v, __half& h, __half& l) {
    h = __float2half_rn(v);
    l = __float2half_rn(v - __half2float(h));
}

// ================= HMMA GEMM core: 128x128 CTA tile, 128 thr, 4 warps (2x2, 64x64 warp tile)
#define OFFAL 8192u
#define OFFBH 16384u
#define OFFBL 24576u
#define STAGE 32768u

#define TG_LOAD_STAGE(sb, k0)                                                  \
    do {                                                                       \
        _Pragma("unroll")                                                      \
        for (int i_ = 0; i_ < 4; i_++) {                                       \
            const int id_ = tid + i_ * 128;                                    \
            const int row_ = id_ >> 2, cc_ = id_ & 3;                          \
            const uint32_t off_ = (uint32_t)((row_ << 6) + ((cc_ ^ ((row_ >> 1) & 3)) << 4)); \
            const size_t ka_ = (size_t)(m0 + row_) * Kp + (k0) + cc_ * 8;      \
            const size_t kb_ = (size_t)(n0 + row_) * Kp + (k0) + cc_ * 8;      \
            cpa16((sb) + off_, Ah + ka_);                                      \
            cpa16((sb) + OFFAL + off_, Al + ka_);                              \
            cpa16((sb) + OFFBH + off_, Bh + kb_);                              \
            cpa16((sb) + OFFBL + off_, Bl + kb_);                              \
        }                                                                      \
    } while (0)

#define TG_COMPUTE(sb)                                                         \
    do {                                                                       \
        _Pragma("unroll")                                                      \
        for (int ks = 0; ks < 2; ks++) {                                       \
            uint32_t aH[4][4], aL[4][4];                                       \
            _Pragma("unroll")                                                  \
            for (int mt = 0; mt < 4; mt++) {                                   \
                const int r = wm * 64 + mt * 16 + (lane & 15);                 \
                const int ch = ks * 2 + (lane >> 4);                           \
                const uint32_t off = (uint32_t)((r << 6) + ((ch ^ ((r >> 1) & 3)) << 4)); \
                LDSM4(aH[mt], (sb) + off);                                     \
                LDSM4(aL[mt], (sb) + OFFAL + off);                             \
            }                                                                  \
            _Pragma("unroll")                                                  \
            for (int half = 0; half < 2; half++) {                             \
                uint32_t bH[4][2], bL[4][2];                                   \
                _Pragma("unroll")                                              \
                for (int p = 0; p < 2; p++) {                                  \
                    const int r = wn * 64 + half * 32 + p * 16 + (lane & 7) + ((lane & 16) >> 1); \
                    const int ch = ks * 2 + ((lane >> 3) & 1);                 \
                    const uint32_t off = (uint32_t)((r << 6) + ((ch ^ ((r >> 1) & 3)) << 4)); \
                    uint32_t q[4];                                             \
                    LDSM4(q, (sb) + OFFBH + off);                              \
                    bH[p*2][0] = q[0]; bH[p*2][1] = q[1];                      \
                    bH[p*2+1][0] = q[2]; bH[p*2+1][1] = q[3];                  \
                    LDSM4(q, (sb) + OFFBL + off);                              \
                    bL[p*2][0] = q[0]; bL[p*2][1] = q[1];                      \
                    bL[p*2+1][0] = q[2]; bL[p*2+1][1] = q[3];                  \
                }                                                              \
                _Pragma("unroll")                                              \
                for (int mt = 0; mt < 4; mt++)                                 \
                    _Pragma("unroll")                                          \
                    for (int nt = 0; nt < 4; nt++) MMA16816(acc[mt][half*4+nt], aH[mt], bH[nt]); \
                _Pragma("unroll")                                              \
                for (int mt = 0; mt < 4; mt++)                                 \
                    _Pragma("unroll")                                          \
                    for (int nt = 0; nt < 4; nt++) MMA16816(acc[mt][half*4+nt], aH[mt], bL[nt]); \
                _Pragma("unroll")                                              \
                for (int mt = 0; mt < 4; mt++)                                 \
                    _Pragma("unroll")                                          \
                    for (int nt = 0; nt < 4; nt++) MMA16816(acc[mt][half*4+nt], aL[mt], bH[nt]); \
            }                                                                  \
        }                                                                      \
    } while (0)

#define TG_MAINLOOP(kbase, nchunk)                                             \
    do {                                                                       \
        TG_LOAD_STAGE(smb, (kbase));                                           \
        CP_COMMIT();                                                           \
        if ((nchunk) > 1) { TG_LOAD_STAGE(smb + STAGE, (kbase) + GBK); CP_COMMIT(); } \
        int s_c = 0, s_ld = 2;                                                 \
        for (int c = 0; c < (nchunk); c++) {                                   \
            if (c + 1 < (nchunk)) CP_WAIT1(); else CP_WAIT0();                 \
            __syncthreads();                                                   \
            if (c + 2 < (nchunk)) { TG_LOAD_STAGE(smb + (uint32_t)s_ld * STAGE, (kbase) + (c + 2) * GBK); CP_COMMIT(); } \
            TG_COMPUTE(smb + (uint32_t)s_c * STAGE);                           \
            s_c = (s_c == 2) ? 0 : s_c + 1;                                    \
            s_ld = (s_ld == 2) ? 0 : s_ld + 1;                                 \
        }                                                                      \
    } while (0)

// ---------------- standard GEMM with fused epilogue ----------------
// epi: 0 = +bias -> Cf; 1 = relu(+bias) -> Chi/Clo; 3 = +PE -> Cf
__global__ void __launch_bounds__(128, 2) tgemm_kernel(
    const __half* __restrict__ Ah, const __half* __restrict__ Al,
    const __half* __restrict__ Bh, const __half* __restrict__ Bl,
    const float* __restrict__ bias,
    float* __restrict__ Cf, __half* __restrict__ Chi, __half* __restrict__ Clo,
    int Kp, int N, int epi)
{
    extern __shared__ char sm[];
    const uint32_t smb = smem_u32(sm);
    const int tid  = threadIdx.x;
    const int lane = tid & 31;
    const int wid  = tid >> 5;
    const int wm   = wid & 1;
    const int wn   = wid >> 1;
    const int m0 = blockIdx.y * 128;
    const int n0 = blockIdx.x * 128;

    float acc[4][8][4];
#pragma unroll
    for (int i = 0; i < 4; i++)
#pragma unroll
        for (int j = 0; j < 8; j++)
#pragma unroll
            for (int t = 0; t < 4; t++) acc[i][j][t] = 0.f;

    TG_MAINLOOP(0, Kp / GBK);

    // epilogue
#pragma unroll
    for (int mt = 0; mt < 4; mt++) {
        const int r0 = m0 + wm * 64 + mt * 16 + (lane >> 2);
#pragma unroll
        for (int nt = 0; nt < 8; nt++) {
            const int col = n0 + wn * 64 + nt * 8 + (lane & 3) * 2;
            const float* a = acc[mt][nt];
            if (epi == 1) {
                const float b0 = __ldg(&bias[col]);
                const float b1 = __ldg(&bias[col + 1]);
#pragma unroll
                for (int rr = 0; rr < 2; rr++) {
                    const int row = r0 + rr * 8;
                    const float v0 = fmaxf(a[rr * 2 + 0] + b0, 0.f);
                    const float v1 = fmaxf(a[rr * 2 + 1] + b1, 0.f);
                    __half h0, l0, h1, l1;
                    split_f16(v0, h0, l0);
                    split_f16(v1, h1, l1);
                    *reinterpret_cast<__half2*>(&Chi[(size_t)row * N + col]) = __halves2half2(h0, h1);
                    *reinterpret_cast<__half2*>(&Clo[(size_t)row * N + col]) = __halves2half2(l0, l1);
                }
            } else if (epi == 3) {
                const float dv = expf((float)(col & ~1) * (-9.210340371976184f / (float)DMODEL));
#pragma unroll
                for (int rr = 0; rr < 2; rr++) {
                    const int row = r0 + rr * 8;
                    const int srow = row % SEQ;
                    float sn, cs;
                    sincosf((float)srow * dv, &sn, &cs);
                    float2 o;
                    o.x = a[rr * 2 + 0] + sn;
                    o.y = a[rr * 2 + 1] + cs;
                    *reinterpret_cast<float2*>(&Cf[(size_t)row * N + col]) = o;
                }
            } else {
                const float b0 = __ldg(&bias[col]);
                const float b1 = __ldg(&bias[col + 1]);
#pragma unroll
                for (int rr = 0; rr < 2; rr++) {
                    const int row = r0 + rr * 8;
                    float2 o;
                    o.x = a[rr * 2 + 0] + b0;
                    o.y = a[rr * 2 + 1] + b1;
                    *reinterpret_cast<float2*>(&Cf[(size_t)row * N + col]) = o;
                }
            }
        }
    }
}

// ---------------- split-K GEMM: partial sums atomically added into prefilled C ----------------
__global__ void __launch_bounds__(128, 2) tgemm_atomic_kernel(
    const __half* __restrict__ Ah, const __half* __restrict__ Al,
    const __half* __restrict__ Bh, const __half* __restrict__ Bl,
    float* __restrict__ Cf, int Kp, int Kz, int N)
{
    extern __shared__ char sm[];
    const uint32_t smb = smem_u32(sm);
    const int tid  = threadIdx.x;
    const int lane = tid & 31;
    const int wid  = tid >> 5;
    const int wm   = wid & 1;
    const int wn   = wid >> 1;
    const int m0 = blockIdx.y * 128;
    const int n0 = blockIdx.x * 128;
    const int kbase = blockIdx.z * Kz;

    float acc[4][8][4];
#pragma unroll
    for (int i = 0; i < 4; i++)
#pragma unroll
        for (int j = 0; j < 8; j++)
#pragma unroll
            for (int t = 0; t < 4; t++) acc[i][j][t] = 0.f;

    TG_MAINLOOP(kbase, Kz / GBK);

    // atomic epilogue
#pragma unroll
    for (int mt = 0; mt < 4; mt++) {
        const int r0 = m0 + wm * 64 + mt * 16 + (lane >> 2);
#pragma unroll
        for (int nt = 0; nt < 8; nt++) {
            const int col = n0 + wn * 64 + nt * 8 + (lane & 3) * 2;
            const float* a = acc[mt][nt];
#pragma unroll
            for (int rr = 0; rr < 2; rr++) {
                const int row = r0 + rr * 8;
                float* p = &Cf[(size_t)row * N + col];
                red_add_f32(p,     a[rr * 2 + 0]);
                red_add_f32(p + 1, a[rr * 2 + 1]);
            }
        }
    }
}

// ---------------- converters ----------------
__global__ void __launch_bounds__(256) cvt_x_kernel(
    const float* __restrict__ x, __half* __restrict__ xh, __half* __restrict__ xl)
{
    const int idx = blockIdx.x * 256 + threadIdx.x;
    if (idx >= NTOK * KEMBP) return;
    const int r = idx / KEMBP, c = idx % KEMBP;
    const float v = (c < KEMB) ? x[(size_t)r * KEMB + c] : 0.f;
    __half h, l; split_f16(v, h, l);
    xh[idx] = h; xl[idx] = l;
}

__global__ void cvt_wT_batch_kernel(
    const float* __restrict__ W, __half* __restrict__ Th, __half* __restrict__ Tl,
    int K, int N, int Kp,
    size_t w_stride, size_t o_outer, size_t o_inner, int inner_mod)
{
    const int z = blockIdx.z;
    const float* Wz = W + (size_t)z * w_stride;
    const size_t ooff = (size_t)(z / inner_mod) * o_outer + (size_t)(z % inner_mod) * o_inner;
    __shared__ float t[32][33];
    const int k0 = blockIdx.y * 32, n0 = blockIdx.x * 32;
    const int tx = threadIdx.x, ty = threadIdx.y;
#pragma unroll
    for (int i = 0; i < 32; i += 8) {
        const int k = k0 + ty + i;
        t[ty + i][tx] = (k < K) ? Wz[(size_t)k * N + n0 + tx] : 0.f;
    }
    __syncthreads();
#pragma unroll
    for (int i = 0; i < 32; i += 8) {
        const int n = n0 + ty + i;
        const int k = k0 + tx;
        __half h, l; split_f16(t[tx][ty + i], h, l);
        Th[ooff + (size_t)n * Kp + k] = h;
        Tl[ooff + (size_t)n * Kp + k] = l;
    }
}

// ---------------- LayerNorm (ddof=1, eps on std) -> fp16 hi/lo, optional h += bias fused ----------------
__global__ void __launch_bounds__(256) ln_kernel(
    float* __restrict__ hio, const float* __restrict__ g,
    const float* __restrict__ b, __half* __restrict__ outh, __half* __restrict__ outl,
    const float* __restrict__ pbias)
{
    const int row = blockIdx.x;
    float* x = hio + (size_t)row * DMODEL;
    float vals[4];
    float s = 0.f, s2 = 0.f;
#pragma unroll
    for (int i = 0; i < 4; i++) {
        float v = x[threadIdx.x + i * 256];
        vals[i] = v; s += v; s2 += v * v;
    }
#pragma unroll
    for (int o = 16; o; o >>= 1) {
        s  += __shfl_xor_sync(0xffffffffu, s, o);
        s2 += __shfl_xor_sync(0xffffffffu, s2, o);
    }
    __shared__ float sh[2][8];
    const int w = threadIdx.x >> 5;
    if ((threadIdx.x & 31) == 0) { sh[0][w] = s; sh[1][w] = s2; }
    __syncthreads();
    if (threadIdx.x < 32) {
        s  = (threadIdx.x < 8) ? sh[0][threadIdx.x] : 0.f;
        s2 = (threadIdx.x < 8) ? sh[1][threadIdx.x] : 0.f;
#pragma unroll
        for (int o = 4; o; o >>= 1) {
            s  += __shfl_xor_sync(0xffffffffu, s, o);
            s2 += __shfl_xor_sync(0xffffffffu, s2, o);
        }
        if (threadIdx.x == 0) { sh[0][0] = s; sh[1][0] = s2; }
    }
    __syncthreads();
    const float mean = sh[0][0] * (1.f / (float)DMODEL);
    float var = (sh[1][0] - (float)DMODEL * mean * mean) * (1.f / (float)(DMODEL - 1));
    var = fmaxf(var, 0.f);
    const float inv = 1.f / (sqrtf(var) + 1e-6f);
#pragma unroll
    for (int i = 0; i < 4; i++) {
        const int c = threadIdx.x + i * 256;
        const float r = g[c] * (vals[i] - mean) * inv + b[c];
        __half h, l; split_f16(r, h, l);
        outh[(size_t)row * DMODEL + c] = h;
        outl[(size_t)row * DMODEL + c] = l;
        if (pbias) x[c] = vals[i] + pbias[c];   // prefill h += bias for upcoming atomic GEMM
    }
}

// ---------------- gather last token per batch: hc = h[last] + bias_o; oc = o[last] ----------------
__global__ void __launch_bounds__(256) gather_last_kernel(
    const float* __restrict__ h, const __half* __restrict__ oh, const __half* __restrict__ ol,
    const float* __restrict__ bias_o,
    float* __restrict__ hc, __half* __restrict__ och, __half* __restrict__ ocl)
{
    const int b = blockIdx.x;
    const size_t src = (size_t)(b * SEQ + (SEQ - 1)) * DMODEL;
    const size_t dst = (size_t)b * DMODEL;
#pragma unroll
    for (int i = 0; i < 4; i++) {
        const int c = threadIdx.x + i * 256;
        hc[dst + c] = h[src + c] + bias_o[c];
        och[dst + c] = oh[src + c];
        ocl[dst + c] = ol[src + c];
    }
}

// ---------------- attention on fused QKV buffer ----------------
__global__ void __launch_bounds__(256) attn_kernel(
    const float* __restrict__ QKV, __half* __restrict__ Oh, __half* __restrict__ Ol)
{
    const int bh = blockIdx.x;
    const int b = bh >> 4;
    const int h = bh & 15;

    __shared__ float qs[SEQ][DK];
    __shared__ float ks[SEQ][DK + 1];
    __shared__ float vs[SEQ][DK];
    __shared__ float sc[SEQ][SEQ];

    const int tid = threadIdx.x;
    for (int e = tid; e < SEQ * DK; e += 256) {
        const int s = e >> 6;
        const int d = e & 63;
        const size_t gbase = (size_t)(b * SEQ + s) * NQKV + h * DK + d;
        qs[s][d] = QKV[gbase];
        ks[s][d] = QKV[gbase + DMODEL];
        vs[s][d] = QKV[gbase + 2 * DMODEL];
    }
    __syncthreads();

    for (int e = tid; e < SEQ * SEQ; e += 256) {
        const int i = e / SEQ;
        const int j = e % SEQ;
        float acc = 0.f;
#pragma unroll
        for (int d = 0; d < DK; d++) acc = fmaf(qs[i][d], ks[j][d], acc);
        sc[i][j] = acc * 0.125f;
    }
    __syncthreads();

    if (tid < SEQ) {
        float mx = -1e30f;
#pragma unroll 1
        for (int j = 0; j < SEQ; j++) mx = fmaxf(mx, sc[tid][j]);
        float sum = 0.f;
#pragma unroll 1
        for (int j = 0; j < SEQ; j++) {
            float ev = expf(sc[tid][j] - mx);
            sum += ev;
            sc[tid][j] = ev;
        }
        const float r = 1.f / sum;
#pragma unroll 1
        for (int j = 0; j < SEQ; j++) sc[tid][j] *= r;
    }
    __syncthreads();

    for (int e = tid; e < SEQ * DK; e += 256) {
        const int i = e >> 6;
        const int d = e & 63;
        float acc = 0.f;
#pragma unroll
        for (int j = 0; j < SEQ; j++) acc = fmaf(sc[i][j], vs[j][d], acc);
        const size_t gidx = (size_t)(b * SEQ + i) * DMODEL + h * DK + d;
        __half hh, ll; split_f16(acc, hh, ll);
        Oh[gidx] = hh;
        Ol[gidx] = ll;
    }
}

// ---------------- head kernels ----------------
// final LN + bn scale, on compact hc (row b)
__global__ void __launch_bounds__(256) pool_ln_scale_kernel(
    const float* __restrict__ hc,
    const float* __restrict__ fin_g, const float* __restrict__ fin_b,
    const float* __restrict__ bn_g, const float* __restrict__ bn_b,
    float* __restrict__ z)
{
    const int bb = blockIdx.x;
    const float* x = hc + (size_t)bb * DMODEL;
    float vals[4];
    float s = 0.f, s2 = 0.f;
#pragma unroll
    for (int i = 0; i < 4; i++) {
        float v = x[threadIdx.x + i * 256];
        vals[i] = v; s += v; s2 += v * v;
    }
#pragma unroll
    for (int o = 16; o; o >>= 1) {
        s  += __shfl_xor_sync(0xffffffffu, s, o);
        s2 += __shfl_xor_sync(0xffffffffu, s2, o);
    }
    __shared__ float sh[2][8];
    const int w = threadIdx.x >> 5;
    if ((threadIdx.x & 31) == 0) { sh[0][w] = s; sh[1][w] = s2; }
    __syncthreads();
    if (threadIdx.x < 32) {
        s  = (threadIdx.x < 8) ? sh[0][threadIdx.x] : 0.f;
        s2 = (threadIdx.x < 8) ? sh[1][threadIdx.x] : 0.f;
#pragma unroll
        for (int o = 4; o; o >>= 1) {
            s  += __shfl_xor_sync(0xffffffffu, s, o);
            s2 += __shfl_xor_sync(0xffffffffu, s2, o);
        }
        if (threadIdx.x == 0) { sh[0][0] = s; sh[1][0] = s2; }
    }
    __syncthreads();
    const float mean = sh[0][0] * (1.f / (float)DMODEL);
    float var = (sh[1][0] - (float)DMODEL * mean * mean) * (1.f / (float)(DMODEL - 1));
    var = fmaxf(var, 0.f);
    const float inv = 1.f / (sqrtf(var) + 1e-6f);
    const float invbn = 1.f / sqrtf(1.0f + 1e-5f);
#pragma unroll
    for (int i = 0; i < 4; i++) {
        const int c = threadIdx.x + i * 256;
        const float lnv = fin_g[c] * (vals[i] - mean) * inv + fin_b[c];
        z[(size_t)bb * DMODEL + c] = lnv * invbn * bn_g[c] + bn_b[c];
    }
}

// ---------------- fp32 SGEMM (head only) ----------------
#define BM_S 128
#define BN_S 128
#define BK_S 8
__global__ void __launch_bounds__(256) sgemm_kernel(
    const float* __restrict__ A, const float* __restrict__ B,
    const float* __restrict__ bias, float* __restrict__ C,
    int M, int N, int K, int relu)
{
    __shared__ float As[BK_S][BM_S];
    __shared__ float Bs[BK_S][BN_S];
    const int tid = threadIdx.x;
    const int m0 = blockIdx.y * BM_S;
    const int n0 = blockIdx.x * BN_S;
    const int arow = tid >> 1;
    const int acol = (tid & 1) * 4;
    const int brow = tid >> 5;
    const int bcol = (tid & 31) * 4;
    const float* Aptr = A + (size_t)(m0 + arow) * K + acol;
    const float* Bptr = B + (size_t)brow * N + n0 + bcol;
    const int tx = tid & 15;
    const int ty = tid >> 4;
    float acc[8][8];
#pragma unroll
    for (int i = 0; i < 8; i++)
#pragma unroll
        for (int j = 0; j < 8; j++) acc[i][j] = 0.f;
    for (int k0 = 0; k0 < K; k0 += BK_S) {
        float4 a4 = *reinterpret_cast<const float4*>(Aptr + k0);
        float4 b4 = *reinterpret_cast<const float4*>(Bptr + (size_t)k0 * N);
        As[acol + 0][arow] = a4.x;
        As[acol + 1][arow] = a4.y;
        As[acol + 2][arow] = a4.z;
        As[acol + 3][arow] = a4.w;
        *reinterpret_cast<float4*>(&Bs[brow][bcol]) = b4;
        __syncthreads();
#pragma unroll
        for (int k = 0; k < BK_S; k++) {
            float ra[8], rb[8];
            *reinterpret_cast<float4*>(&ra[0]) = *reinterpret_cast<const float4*>(&As[k][ty * 8]);
            *reinterpret_cast<float4*>(&ra[4]) = *reinterpret_cast<const float4*>(&As[k][ty * 8 + 4]);
            *reinterpret_cast<float4*>(&rb[0]) = *reinterpret_cast<const float4*>(&Bs[k][tx * 8]);
            *reinterpret_cast<float4*>(&rb[4]) = *reinterpret_cast<const float4*>(&Bs[k][tx * 8 + 4]);
#pragma unroll
            for (int i = 0; i < 8; i++)
#pragma unroll
                for (int j = 0; j < 8; j++)
                    acc[i][j] = fmaf(ra[i], rb[j], acc[i][j]);
        }
        __syncthreads();
    }
#pragma unroll
    for (int i = 0; i < 8; i++) {
        const size_t base = (size_t)(m0 + ty * 8 + i) * N + n0 + tx * 8;
#pragma unroll
        for (int j = 0; j < 8; j++) {
            float v = acc[i][j] + __ldg(&bias[n0 + tx * 8 + j]);
            if (relu) v = fmaxf(v, 0.f);
            C[base + j] = v;
        }
    }
}

__global__ void __launch_bounds__(128) fc_kernel(
    const float* __restrict__ z1, const float* __restrict__ bn_g,
    const float* __restrict__ bn_b, const float* __restrict__ W,
    const float* __restrict__ bias, float* __restrict__ out)
{
    __shared__ float zs[DMODEL];
    const int bb = blockIdx.x;
    const float invbn = 1.f / sqrtf(1.0f + 1e-5f);
    for (int i = threadIdx.x; i < DMODEL; i += 128)
        zs[i] = z1[(size_t)bb * DMODEL + i] * invbn * bn_g[i] + bn_b[i];
    __syncthreads();
    const int c = threadIdx.x;
    if (c < NCLS) {
        float acc = bias[c];
        for (int k = 0; k < DMODEL; k++) acc = fmaf(zs[k], W[(size_t)k * NCLS + c], acc);
        out[(size_t)bb * NCLS + c] = acc;
    }
}

// ---------------- host launcher ----------------
extern "C" void kernel_launch(void* const* d_in, const int* in_sizes, int n_in,
                              void* d_out, int out_size)
{
    const float* x        = (const float*)d_in[0];
    const float* embed_w  = (const float*)d_in[1];
    const float* attn_w   = (const float*)d_in[2];
    const float* attn_b   = (const float*)d_in[3];
    const float* ff_w1    = (const float*)d_in[4];
    const float* ff_b1    = (const float*)d_in[5];
    const float* ff_w2    = (const float*)d_in[6];
    const float* ff_b2    = (const float*)d_in[7];
    const float* ln_g     = (const float*)d_in[8];
    const float* ln_b     = (const float*)d_in[9];
    const float* fin_g    = (const float*)d_in[10];
    const float* fin_b    = (const float*)d_in[11];
    const float* cf_bn_g  = (const float*)d_in[12];
    const float* cf_bn_b  = (const float*)d_in[13];
    const float* cf_w     = (const float*)d_in[14];
    const float* cf_b     = (const float*)d_in[15];
    const float* fc_bn_g  = (const float*)d_in[16];
    const float* fc_bn_b  = (const float*)d_in[17];
    const float* fc_w     = (const float*)d_in[18];
    const float* fc_b     = (const float*)d_in[19];

    cudaFuncSetAttribute(tgemm_kernel, cudaFuncAttributeMaxDynamicSharedMemorySize, 3 * STAGE);
    cudaFuncSetAttribute(tgemm_atomic_kernel, cudaFuncAttributeMaxDynamicSharedMemorySize, 3 * STAGE);

    float *g_h, *g_qkv, *g_hc, *g_z0, *g_z1;
    __half *g_xh, *g_xl, *g_ah, *g_al, *g_oh, *g_ol, *g_fh, *g_fl, *g_wth, *g_wtl;
    __half *g_och, *g_ocl, *g_ach, *g_acl, *g_fch, *g_fcl;
    cudaGetSymbolAddress((void**)&g_h,   d_h);
    cudaGetSymbolAddress((void**)&g_qkv, d_qkv);
    cudaGetSymbolAddress((void**)&g_hc,  d_hc);
    cudaGetSymbolAddress((void**)&g_z0,  d_z0);
    cudaGetSymbolAddress((void**)&g_z1,  d_z1);
    cudaGetSymbolAddress((void**)&g_xh,  d_xh);
    cudaGetSymbolAddress((void**)&g_xl,  d_xl);
    cudaGetSymbolAddress((void**)&g_ah,  d_ah);
    cudaGetSymbolAddress((void**)&g_al,  d_al);
    cudaGetSymbolAddress((void**)&g_oh,  d_oh);
    cudaGetSymbolAddress((void**)&g_ol,  d_ol);
    cudaGetSymbolAddress((void**)&g_fh,  d_fh);
    cudaGetSymbolAddress((void**)&g_fl,  d_fl);
    cudaGetSymbolAddress((void**)&g_wth, d_wth);
    cudaGetSymbolAddress((void**)&g_wtl, d_wtl);
    cudaGetSymbolAddress((void**)&g_och, d_och);
    cudaGetSymbolAddress((void**)&g_ocl, d_ocl);
    cudaGetSymbolAddress((void**)&g_ach, d_ach);
    cudaGetSymbolAddress((void**)&g_acl, d_acl);
    cudaGetSymbolAddress((void**)&g_fch, d_fch);
    cudaGetSymbolAddress((void**)&g_fcl, d_fcl);

    dim3 blk(32, 8);

    // launch 1: input split
    cvt_x_kernel<<<(NTOK * KEMBP + 255) / 256, 256>>>(x, g_xh, g_xl);
    // launch 2: embed weight
    cvt_wT_batch_kernel<<<dim3(1024 / 32, KEMBP / 32, 1), blk>>>(
        embed_w, g_wth, g_wtl, KEMB, DMODEL, KEMBP, 0, 0, 0, 1);
    // launch 3: attention weights
    cvt_wT_batch_kernel<<<dim3(32, 32, 20), blk>>>(
        attn_w, g_wth + WT_EMB_SZ, g_wtl + WT_EMB_SZ, DMODEL, DMODEL, DMODEL,
        (size_t)DMODEL * DMODEL, (size_t)WT_LAYER, (size_t)1048576u, 4);
    // launch 4: ff1 weights
    cvt_wT_batch_kernel<<<dim3(DFF / 32, 32, 5), blk>>>(
        ff_w1, g_wth + WT_EMB_SZ + 4u * 1048576u, g_wtl + WT_EMB_SZ + 4u * 1048576u,
        DMODEL, DFF, DMODEL, (size_t)DMODEL * DFF, (size_t)WT_LAYER, 0, 1);
    // launch 5: ff2 weights
    cvt_wT_batch_kernel<<<dim3(32, DFF / 32, 5), blk>>>(
        ff_w2, g_wth + WT_EMB_SZ + 8u * 1048576u, g_wtl + WT_EMB_SZ + 8u * 1048576u,
        DFF, DMODEL, DFF, (size_t)DFF * DMODEL, (size_t)WT_LAYER, 0, 1);
    // launch 6 (ncu target): embed GEMM, h = X @ We + PE
    {
        dim3 grid(DMODEL / 128, NTOK / 128);
        tgemm_kernel<<<grid, 128, 3 * STAGE>>>(
            g_xh, g_xl, g_wth, g_wtl, nullptr, g_h, nullptr, nullptr, KEMBP, DMODEL, 3);
    }

    // ---- layers 0..3 (full) ----
    for (int l = 0; l < NLAYER - 1; l++) {
        const size_t lw = (size_t)WT_EMB_SZ + (size_t)l * WT_LAYER;
        const __half* wq_h = g_wth + lw;
        const __half* wq_l = g_wtl + lw;
        const float* bq = attn_b + (size_t)l * 4 * DMODEL;

        ln_kernel<<<NTOK, 256>>>(g_h, ln_g + (size_t)(l * 2) * DMODEL,
                                 ln_b + (size_t)(l * 2) * DMODEL, g_ah, g_al,
                                 bq + 3 * DMODEL);
        {
            dim3 grid(NQKV / 128, NTOK / 128);
            tgemm_kernel<<<grid, 128, 3 * STAGE>>>(
                g_ah, g_al, wq_h, wq_l, bq, g_qkv, nullptr, nullptr, DMODEL, NQKV, 0);
        }
        attn_kernel<<<BATCH * NHEAD, 256>>>(g_qkv, g_oh, g_ol);
        {
            dim3 grid(DMODEL / 128, NTOK / 128, 2);
            tgemm_atomic_kernel<<<grid, 128, 3 * STAGE>>>(
                g_oh, g_ol, wq_h + 3u * 1048576u, wq_l + 3u * 1048576u,
                g_h, DMODEL, DMODEL / 2, DMODEL);
        }
        ln_kernel<<<NTOK, 256>>>(g_h, ln_g + (size_t)(l * 2 + 1) * DMODEL,
                                 ln_b + (size_t)(l * 2 + 1) * DMODEL, g_ah, g_al,
                                 ff_b2 + (size_t)l * DMODEL);
        {
            dim3 grid(DFF / 128, NTOK / 128);
            tgemm_kernel<<<grid, 128, 3 * STAGE>>>(
                g_ah, g_al, g_wth + lw + 4u * 1048576u, g_wtl + lw + 4u * 1048576u,
                ff_b1 + (size_t)l * DFF, nullptr, g_fh, g_fl, DMODEL, DFF, 1);
        }
        {
            dim3 grid(DMODEL / 128, NTOK / 128, 2);
            tgemm_atomic_kernel<<<grid, 128, 3 * STAGE>>>(
                g_fh, g_fl, g_wth + lw + 8u * 1048576u, g_wtl + lw + 8u * 1048576u,
                g_h, DFF, DFF / 2, DMODEL);
        }
    }

    // ---- layer 4 (last): full QKV + attention, then compact 128-row tail ----
    {
        const int l = NLAYER - 1;
        const size_t lw = (size_t)WT_EMB_SZ + (size_t)l * WT_LAYER;
        const __half* wq_h = g_wth + lw;
        const __half* wq_l = g_wtl + lw;
        const float* bq = attn_b + (size_t)l * 4 * DMODEL;

        ln_kernel<<<NTOK, 256>>>(g_h, ln_g + (size_t)(l * 2) * DMODEL,
                                 ln_b + (size_t)(l * 2) * DMODEL, g_ah, g_al, nullptr);
        {
            dim3 grid(NQKV / 128, NTOK / 128);
            tgemm_kernel<<<grid, 128, 3 * STAGE>>>(
                g_ah, g_al, wq_h, wq_l, bq, g_qkv, nullptr, nullptr, DMODEL, NQKV, 0);
        }
        attn_kernel<<<BATCH * NHEAD, 256>>>(g_qkv, g_oh, g_ol);
        // gather last tokens; hc = h[last] + bias_o
        gather_last_kernel<<<BATCH, 256>>>(g_h, g_oh, g_ol, bq + 3 * DMODEL, g_hc, g_och, g_ocl);
        // out-proj on 128 rows: hc += oc @ Wo (split-K=8 to spread CTAs)
        {
            dim3 grid(DMODEL / 128, 1, 8);
            tgemm_atomic_kernel<<<grid, 128, 3 * STAGE>>>(
                g_och, g_ocl, wq_h + 3u * 1048576u, wq_l + 3u * 1048576u,
                g_hc, DMODEL, DMODEL / 8, DMODEL);
        }
        // LN2 on 128 rows (fused hc += ff2 bias)
        ln_kernel<<<BATCH, 256>>>(g_hc, ln_g + (size_t)(l * 2 + 1) * DMODEL,
                                  ln_b + (size_t)(l * 2 + 1) * DMODEL, g_ach, g_acl,
                                  ff_b2 + (size_t)l * DMODEL);
        // FF1 on 128 rows
        {
            dim3 grid(DFF / 128, 1);
            tgemm_kernel<<<grid, 128, 3 * STAGE>>>(
                g_ach, g_acl, g_wth + lw + 4u * 1048576u, g_wtl + lw + 4u * 1048576u,
                ff_b1 + (size_t)l * DFF, nullptr, g_fch, g_fcl, DMODEL, DFF, 1);
        }
        // FF2 on 128 rows: hc += fc @ W2 (split-K=8)
        {
            dim3 grid(DMODEL / 128, 1, 8);
            tgemm_atomic_kernel<<<grid, 128, 3 * STAGE>>>(
                g_fch, g_fcl, g_wth + lw + 8u * 1048576u, g_wtl + lw + 8u * 1048576u,
                g_hc, DFF, DFF / 8, DMODEL);
        }
    }

    // ---- classifier head (reads compact hc) ----
    pool_ln_scale_kernel<<<BATCH, 256>>>(g_hc, fin_g, fin_b, cf_bn_g, cf_bn_b, g_z0);
    sgemm_kernel<<<dim3(DMODEL / BN_S, 1), 256>>>(g_z0, cf_w, cf_b, g_z1, BATCH, DMODEL, DMODEL, 1);
    fc_kernel<<<BATCH, 128>>>(g_z1, fc_bn_g, fc_bn_b, fc_w, fc_b, (float*)d_out);
}

// round 9
// speedup vs baseline: 1.5347x; 1.3150x over previous
#include <cuda_runtime.h>
#include <cuda_fp16.h>
#include <math.h>
#include <stdint.h>

// ---------------- problem constants ----------------
#define BATCH 128
#define SEQ   50
#define DMODEL 1024
#define DFF   4096
#define NHEAD 16
#define DK    64
#define NLAYER 5
#define KEMB  1200
#define KEMBP 1216
#define NTOK  6400
#define NCLS  71
#define NQKV  3072

#define GBK 32

// ---------------- weight scratch layout (transposed fp16 hi/lo) ----------------
#define WT_EMB_SZ (1024u*1216u)
#define WT_LAYER  (12u*1024u*1024u)
#define WT_TOTAL  (WT_EMB_SZ + 5u*WT_LAYER)

// ---------------- scratch (device globals) ----------------
__device__ float d_h  [NTOK * DMODEL];
__device__ float d_qkv[NTOK * NQKV];
__device__ float d_hc [BATCH * DMODEL];
__device__ float d_z0 [BATCH * DMODEL];
__device__ float d_z1 [BATCH * DMODEL];

__device__ __align__(16) __half d_xh[NTOK * KEMBP];
__device__ __align__(16) __half d_a [NTOK * DMODEL];
__device__ __align__(16) __half d_o [NTOK * DMODEL];
__device__ __align__(16) __half d_f [NTOK * DFF];
__device__ __align__(16) __half d_wth[WT_TOTAL];
__device__ __align__(16) __half d_wtl[WT_TOTAL];
// compact (128-row) buffers for last-layer tail
__device__ __align__(16) __half d_oc[BATCH * DMODEL];
__device__ __align__(16) __half d_ac[BATCH * DMODEL];
__device__ __align__(16) __half d_fc[BATCH * DFF];

// ---------------- PTX helpers ----------------
__device__ __forceinline__ uint32_t smem_u32(const void* p) {
    uint32_t a;
    asm("{ .reg .u64 t; cvta.to.shared.u64 t, %1; cvt.u32.u64 %0, t; }" : "=r"(a) : "l"(p));
    return a;
}
__device__ __forceinline__ void cpa16(uint32_t dst, const void* src) {
    asm volatile("cp.async.cg.shared.global [%0], [%1], 16;" :: "r"(dst), "l"(src));
}
#define CP_COMMIT() asm volatile("cp.async.commit_group;" ::: "memory")
#define CP_WAIT1()  asm volatile("cp.async.wait_group 1;" ::: "memory")
#define CP_WAIT0()  asm volatile("cp.async.wait_group 0;" ::: "memory")
#define LDSM4(r, a) \
    asm volatile("ldmatrix.sync.aligned.m8n8.x4.shared.b16 {%0,%1,%2,%3}, [%4];" \
        : "=r"((r)[0]), "=r"((r)[1]), "=r"((r)[2]), "=r"((r)[3]) : "r"(a))
#define MMA16816(c, a, b) \
    asm volatile("mma.sync.aligned.m16n8k16.row.col.f32.f16.f16.f32 " \
        "{%0,%1,%2,%3}, {%4,%5,%6,%7}, {%8,%9}, {%0,%1,%2,%3};" \
        : "+f"((c)[0]), "+f"((c)[1]), "+f"((c)[2]), "+f"((c)[3]) \
        : "r"((a)[0]), "r"((a)[1]), "r"((a)[2]), "r"((a)[3]), "r"((b)[0]), "r"((b)[1]))
__device__ __forceinline__ void red_add_f32(float* p, float v) {
    asm volatile("red.global.add.f32 [%0], %1;" :: "l"(p), "f"(v) : "memory");
}

__device__ __forceinline__ void split_f16(float v, __half& h, __half& l) {
    h = __float2half_rn(v);
    l = __float2half_rn(v - __half2float(h));
}

// ================= HMMA GEMM core: 128x128 CTA tile, 128 thr, 4 warps (2x2, 64x64 warp tile)
// A: single fp16 activations. B: fp16 hi/lo split weights (transposed [N][Kp]).
#define OFFBH 8192u
#define OFFBL 16384u
#define STAGE 24576u

#define TG_LOAD_STAGE(sb, k0)                                                  \
    do {                                                                       \
        _Pragma("unroll")                                                      \
        for (int i_ = 0; i_ < 4; i_++) {                                       \
            const int id_ = tid + i_ * 128;                                    \
            const int row_ = id_ >> 2, cc_ = id_ & 3;                          \
            const uint32_t off_ = (uint32_t)((row_ << 6) + ((cc_ ^ ((row_ >> 1) & 3)) << 4)); \
            const size_t ka_ = (size_t)(m0 + row_) * Kp + (k0) + cc_ * 8;      \
            const size_t kb_ = (size_t)(n0 + row_) * Kp + (k0) + cc_ * 8;      \
            cpa16((sb) + off_, A + ka_);                                       \
            cpa16((sb) + OFFBH + off_, Bh + kb_);                              \
            cpa16((sb) + OFFBL + off_, Bl + kb_);                              \
        }                                                                      \
    } while (0)

#define TG_COMPUTE(sb)                                                         \
    do {                                                                       \
        _Pragma("unroll")                                                      \
        for (int ks = 0; ks < 2; ks++) {                                       \
            uint32_t aF[4][4];                                                 \
            _Pragma("unroll")                                                  \
            for (int mt = 0; mt < 4; mt++) {                                   \
                const int r = wm * 64 + mt * 16 + (lane & 15);                 \
                const int ch = ks * 2 + (lane >> 4);                           \
                const uint32_t off = (uint32_t)((r << 6) + ((ch ^ ((r >> 1) & 3)) << 4)); \
                LDSM4(aF[mt], (sb) + off);                                     \
            }                                                                  \
            _Pragma("unroll")                                                  \
            for (int half = 0; half < 2; half++) {                             \
                uint32_t bH[4][2], bL[4][2];                                   \
                _Pragma("unroll")                                              \
                for (int p = 0; p < 2; p++) {                                  \
                    const int r = wn * 64 + half * 32 + p * 16 + (lane & 7) + ((lane & 16) >> 1); \
                    const int ch = ks * 2 + ((lane >> 3) & 1);                 \
                    const uint32_t off = (uint32_t)((r << 6) + ((ch ^ ((r >> 1) & 3)) << 4)); \
                    uint32_t q[4];                                             \
                    LDSM4(q, (sb) + OFFBH + off);                              \
                    bH[p*2][0] = q[0]; bH[p*2][1] = q[1];                      \
                    bH[p*2+1][0] = q[2]; bH[p*2+1][1] = q[3];                  \
                    LDSM4(q, (sb) + OFFBL + off);                              \
                    bL[p*2][0] = q[0]; bL[p*2][1] = q[1];                      \
                    bL[p*2+1][0] = q[2]; bL[p*2+1][1] = q[3];                  \
                }                                                              \
                _Pragma("unroll")                                              \
                for (int mt = 0; mt < 4; mt++)                                 \
                    _Pragma("unroll")                                          \
                    for (int nt = 0; nt < 4; nt++) MMA16816(acc[mt][half*4+nt], aF[mt], bH[nt]); \
                _Pragma("unroll")                                              \
                for (int mt = 0; mt < 4; mt++)                                 \
                    _Pragma("unroll")                                          \
                    for (int nt = 0; nt < 4; nt++) MMA16816(acc[mt][half*4+nt], aF[mt], bL[nt]); \
            }                                                                  \
        }                                                                      \
    } while (0)

#define TG_MAINLOOP(kbase, nchunk)                                             \
    do {                                                                       \
        TG_LOAD_STAGE(smb, (kbase));                                           \
        CP_COMMIT();                                                           \
        if ((nchunk) > 1) { TG_LOAD_STAGE(smb + STAGE, (kbase) + GBK); CP_COMMIT(); } \
        int s_c = 0, s_ld = 2;                                                 \
        for (int c = 0; c < (nchunk); c++) {                                   \
            if (c + 1 < (nchunk)) CP_WAIT1(); else CP_WAIT0();                 \
            __syncthreads();                                                   \
            if (c + 2 < (nchunk)) { TG_LOAD_STAGE(smb + (uint32_t)s_ld * STAGE, (kbase) + (c + 2) * GBK); CP_COMMIT(); } \
            TG_COMPUTE(smb + (uint32_t)s_c * STAGE);                           \
            s_c = (s_c == 2) ? 0 : s_c + 1;                                    \
            s_ld = (s_ld == 2) ? 0 : s_ld + 1;                                 \
        }                                                                      \
    } while (0)

// ---------------- standard GEMM with fused epilogue ----------------
// epi: 0 = +bias -> Cf; 1 = relu(+bias) -> Ch (fp16); 3 = +PE -> Cf
__global__ void __launch_bounds__(128, 2) tgemm_kernel(
    const __half* __restrict__ A,
    const __half* __restrict__ Bh, const __half* __restrict__ Bl,
    const float* __restrict__ bias,
    float* __restrict__ Cf, __half* __restrict__ Ch,
    int Kp, int N, int epi)
{
    extern __shared__ char sm[];
    const uint32_t smb = smem_u32(sm);
    const int tid  = threadIdx.x;
    const int lane = tid & 31;
    const int wid  = tid >> 5;
    const int wm   = wid & 1;
    const int wn   = wid >> 1;
    const int m0 = blockIdx.y * 128;
    const int n0 = blockIdx.x * 128;

    float acc[4][8][4];
#pragma unroll
    for (int i = 0; i < 4; i++)
#pragma unroll
        for (int j = 0; j < 8; j++)
#pragma unroll
            for (int t = 0; t < 4; t++) acc[i][j][t] = 0.f;

    TG_MAINLOOP(0, Kp / GBK);

    // epilogue
#pragma unroll
    for (int mt = 0; mt < 4; mt++) {
        const int r0 = m0 + wm * 64 + mt * 16 + (lane >> 2);
#pragma unroll
        for (int nt = 0; nt < 8; nt++) {
            const int col = n0 + wn * 64 + nt * 8 + (lane & 3) * 2;
            const float* a = acc[mt][nt];
            if (epi == 1) {
                const float b0 = __ldg(&bias[col]);
                const float b1 = __ldg(&bias[col + 1]);
#pragma unroll
                for (int rr = 0; rr < 2; rr++) {
                    const int row = r0 + rr * 8;
                    const float v0 = fmaxf(a[rr * 2 + 0] + b0, 0.f);
                    const float v1 = fmaxf(a[rr * 2 + 1] + b1, 0.f);
                    *reinterpret_cast<__half2*>(&Ch[(size_t)row * N + col]) =
                        __halves2half2(__float2half_rn(v0), __float2half_rn(v1));
                }
            } else if (epi == 3) {
                const float dv = expf((float)(col & ~1) * (-9.210340371976184f / (float)DMODEL));
#pragma unroll
                for (int rr = 0; rr < 2; rr++) {
                    const int row = r0 + rr * 8;
                    const int srow = row % SEQ;
                    float sn, cs;
                    sincosf((float)srow * dv, &sn, &cs);
                    float2 o;
                    o.x = a[rr * 2 + 0] + sn;
                    o.y = a[rr * 2 + 1] + cs;
                    *reinterpret_cast<float2*>(&Cf[(size_t)row * N + col]) = o;
                }
            } else {
                const float b0 = __ldg(&bias[col]);
                const float b1 = __ldg(&bias[col + 1]);
#pragma unroll
                for (int rr = 0; rr < 2; rr++) {
                    const int row = r0 + rr * 8;
                    float2 o;
                    o.x = a[rr * 2 + 0] + b0;
                    o.y = a[rr * 2 + 1] + b1;
                    *reinterpret_cast<float2*>(&Cf[(size_t)row * N + col]) = o;
                }
            }
        }
    }
}

// ---------------- split-K GEMM: partial sums atomically added into prefilled C ----------------
__global__ void __launch_bounds__(128, 2) tgemm_atomic_kernel(
    const __half* __restrict__ A,
    const __half* __restrict__ Bh, const __half* __restrict__ Bl,
    float* __restrict__ Cf, int Kp, int Kz, int N)
{
    extern __shared__ char sm[];
    const uint32_t smb = smem_u32(sm);
    const int tid  = threadIdx.x;
    const int lane = tid & 31;
    const int wid  = tid >> 5;
    const int wm   = wid & 1;
    const int wn   = wid >> 1;
    const int m0 = blockIdx.y * 128;
    const int n0 = blockIdx.x * 128;
    const int kbase = blockIdx.z * Kz;

    float acc[4][8][4];
#pragma unroll
    for (int i = 0; i < 4; i++)
#pragma unroll
        for (int j = 0; j < 8; j++)
#pragma unroll
            for (int t = 0; t < 4; t++) acc[i][j][t] = 0.f;

    TG_MAINLOOP(kbase, Kz / GBK);

    // atomic epilogue
#pragma unroll
    for (int mt = 0; mt < 4; mt++) {
        const int r0 = m0 + wm * 64 + mt * 16 + (lane >> 2);
#pragma unroll
        for (int nt = 0; nt < 8; nt++) {
            const int col = n0 + wn * 64 + nt * 8 + (lane & 3) * 2;
            const float* a = acc[mt][nt];
#pragma unroll
            for (int rr = 0; rr < 2; rr++) {
                const int row = r0 + rr * 8;
                float* p = &Cf[(size_t)row * N + col];
                red_add_f32(p,     a[rr * 2 + 0]);
                red_add_f32(p + 1, a[rr * 2 + 1]);
            }
        }
    }
}

// ---------------- converters ----------------
__global__ void __launch_bounds__(256) cvt_x_kernel(
    const float* __restrict__ x, __half* __restrict__ xh)
{
    const int idx = blockIdx.x * 256 + threadIdx.x;
    if (idx >= NTOK * KEMBP) return;
    const int r = idx / KEMBP, c = idx % KEMBP;
    const float v = (c < KEMB) ? x[(size_t)r * KEMB + c] : 0.f;
    xh[idx] = __float2half_rn(v);
}

__global__ void cvt_wT_batch_kernel(
    const float* __restrict__ W, __half* __restrict__ Th, __half* __restrict__ Tl,
    int K, int N, int Kp,
    size_t w_stride, size_t o_outer, size_t o_inner, int inner_mod)
{
    const int z = blockIdx.z;
    const float* Wz = W + (size_t)z * w_stride;
    const size_t ooff = (size_t)(z / inner_mod) * o_outer + (size_t)(z % inner_mod) * o_inner;
    __shared__ float t[32][33];
    const int k0 = blockIdx.y * 32, n0 = blockIdx.x * 32;
    const int tx = threadIdx.x, ty = threadIdx.y;
#pragma unroll
    for (int i = 0; i < 32; i += 8) {
        const int k = k0 + ty + i;
        t[ty + i][tx] = (k < K) ? Wz[(size_t)k * N + n0 + tx] : 0.f;
    }
    __syncthreads();
#pragma unroll
    for (int i = 0; i < 32; i += 8) {
        const int n = n0 + ty + i;
        const int k = k0 + tx;
        __half h, l; split_f16(t[tx][ty + i], h, l);
        Th[ooff + (size_t)n * Kp + k] = h;
        Tl[ooff + (size_t)n * Kp + k] = l;
    }
}

// ---------------- LayerNorm (ddof=1, eps on std) -> fp16, optional h += bias fused ----------------
__global__ void __launch_bounds__(256) ln_kernel(
    float* __restrict__ hio, const float* __restrict__ g,
    const float* __restrict__ b, __half* __restrict__ outh,
    const float* __restrict__ pbias)
{
    const int row = blockIdx.x;
    float* x = hio + (size_t)row * DMODEL;
    float vals[4];
    float s = 0.f, s2 = 0.f;
#pragma unroll
    for (int i = 0; i < 4; i++) {
        float v = x[threadIdx.x + i * 256];
        vals[i] = v; s += v; s2 += v * v;
    }
#pragma unroll
    for (int o = 16; o; o >>= 1) {
        s  += __shfl_xor_sync(0xffffffffu, s, o);
        s2 += __shfl_xor_sync(0xffffffffu, s2, o);
    }
    __shared__ float sh[2][8];
    const int w = threadIdx.x >> 5;
    if ((threadIdx.x & 31) == 0) { sh[0][w] = s; sh[1][w] = s2; }
    __syncthreads();
    if (threadIdx.x < 32) {
        s  = (threadIdx.x < 8) ? sh[0][threadIdx.x] : 0.f;
        s2 = (threadIdx.x < 8) ? sh[1][threadIdx.x] : 0.f;
#pragma unroll
        for (int o = 4; o; o >>= 1) {
            s  += __shfl_xor_sync(0xffffffffu, s, o);
            s2 += __shfl_xor_sync(0xffffffffu, s2, o);
        }
        if (threadIdx.x == 0) { sh[0][0] = s; sh[1][0] = s2; }
    }
    __syncthreads();
    const float mean = sh[0][0] * (1.f / (float)DMODEL);
    float var = (sh[1][0] - (float)DMODEL * mean * mean) * (1.f / (float)(DMODEL - 1));
    var = fmaxf(var, 0.f);
    const float inv = 1.f / (sqrtf(var) + 1e-6f);
#pragma unroll
    for (int i = 0; i < 4; i++) {
        const int c = threadIdx.x + i * 256;
        const float r = g[c] * (vals[i] - mean) * inv + b[c];
        outh[(size_t)row * DMODEL + c] = __float2half_rn(r);
        if (pbias) x[c] = vals[i] + pbias[c];
    }
}

// ---------------- gather last token per batch ----------------
__global__ void __launch_bounds__(256) gather_last_kernel(
    const float* __restrict__ h, const __half* __restrict__ o,
    const float* __restrict__ bias_o,
    float* __restrict__ hc, __half* __restrict__ oc)
{
    const int b = blockIdx.x;
    const size_t src = (size_t)(b * SEQ + (SEQ - 1)) * DMODEL;
    const size_t dst = (size_t)b * DMODEL;
#pragma unroll
    for (int i = 0; i < 4; i++) {
        const int c = threadIdx.x + i * 256;
        hc[dst + c] = h[src + c] + bias_o[c];
        oc[dst + c] = o[src + c];
    }
}

// ---------------- attention on fused QKV buffer ----------------
__global__ void __launch_bounds__(256) attn_kernel(
    const float* __restrict__ QKV, __half* __restrict__ O)
{
    const int bh = blockIdx.x;
    const int b = bh >> 4;
    const int h = bh & 15;

    __shared__ float qs[SEQ][DK];
    __shared__ float ks[SEQ][DK + 1];
    __shared__ float vs[SEQ][DK];
    __shared__ float sc[SEQ][SEQ];

    const int tid = threadIdx.x;
    for (int e = tid; e < SEQ * DK; e += 256) {
        const int s = e >> 6;
        const int d = e & 63;
        const size_t gbase = (size_t)(b * SEQ + s) * NQKV + h * DK + d;
        qs[s][d] = QKV[gbase];
        ks[s][d] = QKV[gbase + DMODEL];
        vs[s][d] = QKV[gbase + 2 * DMODEL];
    }
    __syncthreads();

    for (int e = tid; e < SEQ * SEQ; e += 256) {
        const int i = e / SEQ;
        const int j = e % SEQ;
        float acc = 0.f;
#pragma unroll
        for (int d = 0; d < DK; d++) acc = fmaf(qs[i][d], ks[j][d], acc);
        sc[i][j] = acc * 0.125f;
    }
    __syncthreads();

    if (tid < SEQ) {
        float mx = -1e30f;
#pragma unroll 1
        for (int j = 0; j < SEQ; j++) mx = fmaxf(mx, sc[tid][j]);
        float sum = 0.f;
#pragma unroll 1
        for (int j = 0; j < SEQ; j++) {
            float ev = expf(sc[tid][j] - mx);
            sum += ev;
            sc[tid][j] = ev;
        }
        const float r = 1.f / sum;
#pragma unroll 1
        for (int j = 0; j < SEQ; j++) sc[tid][j] *= r;
    }
    __syncthreads();

    for (int e = tid; e < SEQ * DK; e += 256) {
        const int i = e >> 6;
        const int d = e & 63;
        float acc = 0.f;
#pragma unroll
        for (int j = 0; j < SEQ; j++) acc = fmaf(sc[i][j], vs[j][d], acc);
        const size_t gidx = (size_t)(b * SEQ + i) * DMODEL + h * DK + d;
        O[gidx] = __float2half_rn(acc);
    }
}

// ---------------- head kernels ----------------
__global__ void __launch_bounds__(256) pool_ln_scale_kernel(
    const float* __restrict__ hc,
    const float* __restrict__ fin_g, const float* __restrict__ fin_b,
    const float* __restrict__ bn_g, const float* __restrict__ bn_b,
    float* __restrict__ z)
{
    const int bb = blockIdx.x;
    const float* x = hc + (size_t)bb * DMODEL;
    float vals[4];
    float s = 0.f, s2 = 0.f;
#pragma unroll
    for (int i = 0; i < 4; i++) {
        float v = x[threadIdx.x + i * 256];
        vals[i] = v; s += v; s2 += v * v;
    }
#pragma unroll
    for (int o = 16; o; o >>= 1) {
        s  += __shfl_xor_sync(0xffffffffu, s, o);
        s2 += __shfl_xor_sync(0xffffffffu, s2, o);
    }
    __shared__ float sh[2][8];
    const int w = threadIdx.x >> 5;
    if ((threadIdx.x & 31) == 0) { sh[0][w] = s; sh[1][w] = s2; }
    __syncthreads();
    if (threadIdx.x < 32) {
        s  = (threadIdx.x < 8) ? sh[0][threadIdx.x] : 0.f;
        s2 = (threadIdx.x < 8) ? sh[1][threadIdx.x] : 0.f;
#pragma unroll
        for (int o = 4; o; o >>= 1) {
            s  += __shfl_xor_sync(0xffffffffu, s, o);
            s2 += __shfl_xor_sync(0xffffffffu, s2, o);
        }
        if (threadIdx.x == 0) { sh[0][0] = s; sh[1][0] = s2; }
    }
    __syncthreads();
    const float mean = sh[0][0] * (1.f / (float)DMODEL);
    float var = (sh[1][0] - (float)DMODEL * mean * mean) * (1.f / (float)(DMODEL - 1));
    var = fmaxf(var, 0.f);
    const float inv = 1.f / (sqrtf(var) + 1e-6f);
    const float invbn = 1.f / sqrtf(1.0f + 1e-5f);
#pragma unroll
    for (int i = 0; i < 4; i++) {
        const int c = threadIdx.x + i * 256;
        const float lnv = fin_g[c] * (vals[i] - mean) * inv + fin_b[c];
        z[(size_t)bb * DMODEL + c] = lnv * invbn * bn_g[c] + bn_b[c];
    }
}

// ---------------- fp32 SGEMM (head only) ----------------
#define BM_S 128
#define BN_S 128
#define BK_S 8
__global__ void __launch_bounds__(256) sgemm_kernel(
    const float* __restrict__ A, const float* __restrict__ B,
    const float* __restrict__ bias, float* __restrict__ C,
    int M, int N, int K, int relu)
{
    __shared__ float As[BK_S][BM_S];
    __shared__ float Bs[BK_S][BN_S];
    const int tid = threadIdx.x;
    const int m0 = blockIdx.y * BM_S;
    const int n0 = blockIdx.x * BN_S;
    const int arow = tid >> 1;
    const int acol = (tid & 1) * 4;
    const int brow = tid >> 5;
    const int bcol = (tid & 31) * 4;
    const float* Aptr = A + (size_t)(m0 + arow) * K + acol;
    const float* Bptr = B + (size_t)brow * N + n0 + bcol;
    const int tx = tid & 15;
    const int ty = tid >> 4;
    float acc[8][8];
#pragma unroll
    for (int i = 0; i < 8; i++)
#pragma unroll
        for (int j = 0; j < 8; j++) acc[i][j] = 0.f;
    for (int k0 = 0; k0 < K; k0 += BK_S) {
        float4 a4 = *reinterpret_cast<const float4*>(Aptr + k0);
        float4 b4 = *reinterpret_cast<const float4*>(Bptr + (size_t)k0 * N);
        As[acol + 0][arow] = a4.x;
        As[acol + 1][arow] = a4.y;
        As[acol + 2][arow] = a4.z;
        As[acol + 3][arow] = a4.w;
        *reinterpret_cast<float4*>(&Bs[brow][bcol]) = b4;
        __syncthreads();
#pragma unroll
        for (int k = 0; k < BK_S; k++) {
            float ra[8], rb[8];
            *reinterpret_cast<float4*>(&ra[0]) = *reinterpret_cast<const float4*>(&As[k][ty * 8]);
            *reinterpret_cast<float4*>(&ra[4]) = *reinterpret_cast<const float4*>(&As[k][ty * 8 + 4]);
            *reinterpret_cast<float4*>(&rb[0]) = *reinterpret_cast<const float4*>(&Bs[k][tx * 8]);
            *reinterpret_cast<float4*>(&rb[4]) = *reinterpret_cast<const float4*>(&Bs[k][tx * 8 + 4]);
#pragma unroll
            for (int i = 0; i < 8; i++)
#pragma unroll
                for (int j = 0; j < 8; j++)
                    acc[i][j] = fmaf(ra[i], rb[j], acc[i][j]);
        }
        __syncthreads();
    }
#pragma unroll
    for (int i = 0; i < 8; i++) {
        const size_t base = (size_t)(m0 + ty * 8 + i) * N + n0 + tx * 8;
#pragma unroll
        for (int j = 0; j < 8; j++) {
            float v = acc[i][j] + __ldg(&bias[n0 + tx * 8 + j]);
            if (relu) v = fmaxf(v, 0.f);
            C[base + j] = v;
        }
    }
}

__global__ void __launch_bounds__(128) fc_kernel(
    const float* __restrict__ z1, const float* __restrict__ bn_g,
    const float* __restrict__ bn_b, const float* __restrict__ W,
    const float* __restrict__ bias, float* __restrict__ out)
{
    __shared__ float zs[DMODEL];
    const int bb = blockIdx.x;
    const float invbn = 1.f / sqrtf(1.0f + 1e-5f);
    for (int i = threadIdx.x; i < DMODEL; i += 128)
        zs[i] = z1[(size_t)bb * DMODEL + i] * invbn * bn_g[i] + bn_b[i];
    __syncthreads();
    const int c = threadIdx.x;
    if (c < NCLS) {
        float acc = bias[c];
        for (int k = 0; k < DMODEL; k++) acc = fmaf(zs[k], W[(size_t)k * NCLS + c], acc);
        out[(size_t)bb * NCLS + c] = acc;
    }
}

// ---------------- host launcher ----------------
extern "C" void kernel_launch(void* const* d_in, const int* in_sizes, int n_in,
                              void* d_out, int out_size)
{
    const float* x        = (const float*)d_in[0];
    const float* embed_w  = (const float*)d_in[1];
    const float* attn_w   = (const float*)d_in[2];
    const float* attn_b   = (const float*)d_in[3];
    const float* ff_w1    = (const float*)d_in[4];
    const float* ff_b1    = (const float*)d_in[5];
    const float* ff_w2    = (const float*)d_in[6];
    const float* ff_b2    = (const float*)d_in[7];
    const float* ln_g     = (const float*)d_in[8];
    const float* ln_b     = (const float*)d_in[9];
    const float* fin_g    = (const float*)d_in[10];
    const float* fin_b    = (const float*)d_in[11];
    const float* cf_bn_g  = (const float*)d_in[12];
    const float* cf_bn_b  = (const float*)d_in[13];
    const float* cf_w     = (const float*)d_in[14];
    const float* cf_b     = (const float*)d_in[15];
    const float* fc_bn_g  = (const float*)d_in[16];
    const float* fc_bn_b  = (const float*)d_in[17];
    const float* fc_w     = (const float*)d_in[18];
    const float* fc_b     = (const float*)d_in[19];

    cudaFuncSetAttribute(tgemm_kernel, cudaFuncAttributeMaxDynamicSharedMemorySize, 3 * STAGE);
    cudaFuncSetAttribute(tgemm_atomic_kernel, cudaFuncAttributeMaxDynamicSharedMemorySize, 3 * STAGE);

    float *g_h, *g_qkv, *g_hc, *g_z0, *g_z1;
    __half *g_xh, *g_a, *g_o, *g_f, *g_wth, *g_wtl, *g_oc, *g_ac, *g_fc;
    cudaGetSymbolAddress((void**)&g_h,   d_h);
    cudaGetSymbolAddress((void**)&g_qkv, d_qkv);
    cudaGetSymbolAddress((void**)&g_hc,  d_hc);
    cudaGetSymbolAddress((void**)&g_z0,  d_z0);
    cudaGetSymbolAddress((void**)&g_z1,  d_z1);
    cudaGetSymbolAddress((void**)&g_xh,  d_xh);
    cudaGetSymbolAddress((void**)&g_a,   d_a);
    cudaGetSymbolAddress((void**)&g_o,   d_o);
    cudaGetSymbolAddress((void**)&g_f,   d_f);
    cudaGetSymbolAddress((void**)&g_wth, d_wth);
    cudaGetSymbolAddress((void**)&g_wtl, d_wtl);
    cudaGetSymbolAddress((void**)&g_oc,  d_oc);
    cudaGetSymbolAddress((void**)&g_ac,  d_ac);
    cudaGetSymbolAddress((void**)&g_fc,  d_fc);

    dim3 blk(32, 8);

    // converts
    cvt_x_kernel<<<(NTOK * KEMBP + 255) / 256, 256>>>(x, g_xh);
    cvt_wT_batch_kernel<<<dim3(1024 / 32, KEMBP / 32, 1), blk>>>(
        embed_w, g_wth, g_wtl, KEMB, DMODEL, KEMBP, 0, 0, 0, 1);
    cvt_wT_batch_kernel<<<dim3(32, 32, 20), blk>>>(
        attn_w, g_wth + WT_EMB_SZ, g_wtl + WT_EMB_SZ, DMODEL, DMODEL, DMODEL,
        (size_t)DMODEL * DMODEL, (size_t)WT_LAYER, (size_t)1048576u, 4);
    cvt_wT_batch_kernel<<<dim3(DFF / 32, 32, 5), blk>>>(
        ff_w1, g_wth + WT_EMB_SZ + 4u * 1048576u, g_wtl + WT_EMB_SZ + 4u * 1048576u,
        DMODEL, DFF, DMODEL, (size_t)DMODEL * DFF, (size_t)WT_LAYER, 0, 1);
    cvt_wT_batch_kernel<<<dim3(32, DFF / 32, 5), blk>>>(
        ff_w2, g_wth + WT_EMB_SZ + 8u * 1048576u, g_wtl + WT_EMB_SZ + 8u * 1048576u,
        DFF, DMODEL, DFF, (size_t)DFF * DMODEL, (size_t)WT_LAYER, 0, 1);
    // embed GEMM, h = X @ We + PE
    {
        dim3 grid(DMODEL / 128, NTOK / 128);
        tgemm_kernel<<<grid, 128, 3 * STAGE>>>(
            g_xh, g_wth, g_wtl, nullptr, g_h, nullptr, KEMBP, DMODEL, 3);
    }

    // ---- layers 0..3 (full) ----
    for (int l = 0; l < NLAYER - 1; l++) {
        const size_t lw = (size_t)WT_EMB_SZ + (size_t)l * WT_LAYER;
        const __half* wq_h = g_wth + lw;
        const __half* wq_l = g_wtl + lw;
        const float* bq = attn_b + (size_t)l * 4 * DMODEL;

        ln_kernel<<<NTOK, 256>>>(g_h, ln_g + (size_t)(l * 2) * DMODEL,
                                 ln_b + (size_t)(l * 2) * DMODEL, g_a,
                                 bq + 3 * DMODEL);
        {
            dim3 grid(NQKV / 128, NTOK / 128);
            tgemm_kernel<<<grid, 128, 3 * STAGE>>>(
                g_a, wq_h, wq_l, bq, g_qkv, nullptr, DMODEL, NQKV, 0);
        }
        attn_kernel<<<BATCH * NHEAD, 256>>>(g_qkv, g_o);
        {
            dim3 grid(DMODEL / 128, NTOK / 128, 2);
            tgemm_atomic_kernel<<<grid, 128, 3 * STAGE>>>(
                g_o, wq_h + 3u * 1048576u, wq_l + 3u * 1048576u,
                g_h, DMODEL, DMODEL / 2, DMODEL);
        }
        ln_kernel<<<NTOK, 256>>>(g_h, ln_g + (size_t)(l * 2 + 1) * DMODEL,
                                 ln_b + (size_t)(l * 2 + 1) * DMODEL, g_a,
                                 ff_b2 + (size_t)l * DMODEL);
        {
            dim3 grid(DFF / 128, NTOK / 128);
            tgemm_kernel<<<grid, 128, 3 * STAGE>>>(
                g_a, g_wth + lw + 4u * 1048576u, g_wtl + lw + 4u * 1048576u,
                ff_b1 + (size_t)l * DFF, nullptr, g_f, DMODEL, DFF, 1);
        }
        {
            dim3 grid(DMODEL / 128, NTOK / 128, 2);
            tgemm_atomic_kernel<<<grid, 128, 3 * STAGE>>>(
                g_f, g_wth + lw + 8u * 1048576u, g_wtl + lw + 8u * 1048576u,
                g_h, DFF, DFF / 2, DMODEL);
        }
    }

    // ---- layer 4 (last): full QKV + attention, then compact 128-row tail ----
    {
        const int l = NLAYER - 1;
        const size_t lw = (size_t)WT_EMB_SZ + (size_t)l * WT_LAYER;
        const __half* wq_h = g_wth + lw;
        const __half* wq_l = g_wtl + lw;
        const float* bq = attn_b + (size_t)l * 4 * DMODEL;

        ln_kernel<<<NTOK, 256>>>(g_h, ln_g + (size_t)(l * 2) * DMODEL,
                                 ln_b + (size_t)(l * 2) * DMODEL, g_a, nullptr);
        {
            dim3 grid(NQKV / 128, NTOK / 128);
            tgemm_kernel<<<grid, 128, 3 * STAGE>>>(
                g_a, wq_h, wq_l, bq, g_qkv, nullptr, DMODEL, NQKV, 0);
        }
        attn_kernel<<<BATCH * NHEAD, 256>>>(g_qkv, g_o);
        gather_last_kernel<<<BATCH, 256>>>(g_h, g_o, bq + 3 * DMODEL, g_hc, g_oc);
        {
            dim3 grid(DMODEL / 128, 1, 8);
            tgemm_atomic_kernel<<<grid, 128, 3 * STAGE>>>(
                g_oc, wq_h + 3u * 1048576u, wq_l + 3u * 1048576u,
                g_hc, DMODEL, DMODEL / 8, DMODEL);
        }
        ln_kernel<<<BATCH, 256>>>(g_hc, ln_g + (size_t)(l * 2 + 1) * DMODEL,
                                  ln_b + (size_t)(l * 2 + 1) * DMODEL, g_ac,
                                  ff_b2 + (size_t)l * DMODEL);
        {
            dim3 grid(DFF / 128, 1);
            tgemm_kernel<<<grid, 128, 3 * STAGE>>>(
                g_ac, g_wth + lw + 4u * 1048576u, g_wtl + lw + 4u * 1048576u,
                ff_b1 + (size_t)l * DFF, nullptr, g_fc, DMODEL, DFF, 1);
        }
        {
            dim3 grid(DMODEL / 128, 1, 8);
            tgemm_atomic_kernel<<<grid, 128, 3 * STAGE>>>(
                g_fc, g_wth + lw + 8u * 1048576u, g_wtl + lw + 8u * 1048576u,
                g_hc, DFF, DFF / 8, DMODEL);
        }
    }

    // ---- classifier head ----
    pool_ln_scale_kernel<<<BATCH, 256>>>(g_hc, fin_g, fin_b, cf_bn_g, cf_bn_b, g_z0);
    sgemm_kernel<<<dim3(DMODEL / BN_S, 1), 256>>>(g_z0, cf_w, cf_b, g_z1, BATCH, DMODEL, DMODEL, 1);
    fc_kernel<<<BATCH, 128>>>(g_z1, fc_bn_g, fc_bn_b, fc_w, fc_b, (float*)d_out);
}

// round 10
// speedup vs baseline: 2.2759x; 1.4830x over previous
#include <cuda_runtime.h>
#include <cuda_fp16.h>
#include <math.h>
#include <stdint.h>

// ---------------- problem constants ----------------
#define BATCH 128
#define SEQ   50
#define DMODEL 1024
#define DFF   4096
#define NHEAD 16
#define DK    64
#define NLAYER 5
#define KEMB  1200
#define KEMBP 1216
#define NTOK  6400
#define NCLS  71
#define NQKV  3072

#define GBK 32

// ---------------- weight scratch layout (transposed fp16) ----------------
#define WT_EMB_SZ (1024u*1216u)
#define WT_LAYER  (12u*1024u*1024u)
#define WT_TOTAL  (WT_EMB_SZ + 5u*WT_LAYER)

// ---------------- scratch (device globals) ----------------
__device__ float d_h  [NTOK * DMODEL];
__device__ float d_qkv[NTOK * NQKV];
__device__ float d_hc [BATCH * DMODEL];
__device__ float d_z0 [BATCH * DMODEL];
__device__ float d_z1 [BATCH * DMODEL];

__device__ __align__(16) __half d_xh[NTOK * KEMBP];
__device__ __align__(16) __half d_a [NTOK * DMODEL];
__device__ __align__(16) __half d_o [NTOK * DMODEL];
__device__ __align__(16) __half d_f [NTOK * DFF];
__device__ __align__(16) __half d_wt[WT_TOTAL];
// compact (128-row) buffers for last-layer tail
__device__ __align__(16) __half d_oc[BATCH * DMODEL];
__device__ __align__(16) __half d_ac[BATCH * DMODEL];
__device__ __align__(16) __half d_fc[BATCH * DFF];

// ---------------- PTX helpers ----------------
__device__ __forceinline__ uint32_t smem_u32(const void* p) {
    uint32_t a;
    asm("{ .reg .u64 t; cvta.to.shared.u64 t, %1; cvt.u32.u64 %0, t; }" : "=r"(a) : "l"(p));
    return a;
}
__device__ __forceinline__ void cpa16(uint32_t dst, const void* src) {
    asm volatile("cp.async.cg.shared.global [%0], [%1], 16;" :: "r"(dst), "l"(src));
}
#define CP_COMMIT() asm volatile("cp.async.commit_group;" ::: "memory")
#define CP_WAIT1()  asm volatile("cp.async.wait_group 1;" ::: "memory")
#define CP_WAIT0()  asm volatile("cp.async.wait_group 0;" ::: "memory")
#define LDSM4(r, a) \
    asm volatile("ldmatrix.sync.aligned.m8n8.x4.shared.b16 {%0,%1,%2,%3}, [%4];" \
        : "=r"((r)[0]), "=r"((r)[1]), "=r"((r)[2]), "=r"((r)[3]) : "r"(a))
#define MMA16816(c, a, b) \
    asm volatile("mma.sync.aligned.m16n8k16.row.col.f32.f16.f16.f32 " \
        "{%0,%1,%2,%3}, {%4,%5,%6,%7}, {%8,%9}, {%0,%1,%2,%3};" \
        : "+f"((c)[0]), "+f"((c)[1]), "+f"((c)[2]), "+f"((c)[3]) \
        : "r"((a)[0]), "r"((a)[1]), "r"((a)[2]), "r"((a)[3]), "r"((b)[0]), "r"((b)[1]))
__device__ __forceinline__ void red_add_f32(float* p, float v) {
    asm volatile("red.global.add.f32 [%0], %1;" :: "l"(p), "f"(v) : "memory");
}

// ================= HMMA GEMM core: 128x128 CTA tile, 128 thr, 4 warps (2x2, 64x64 warp tile)
// A: fp16 activations. B: fp16 weights (transposed [N][Kp]).
#define OFFB  8192u
#define STAGE 16384u

#define TG_LOAD_STAGE(sb, k0)                                                  \
    do {                                                                       \
        _Pragma("unroll")                                                      \
        for (int i_ = 0; i_ < 4; i_++) {                                       \
            const int id_ = tid + i_ * 128;                                    \
            const int row_ = id_ >> 2, cc_ = id_ & 3;                          \
            const uint32_t off_ = (uint32_t)((row_ << 6) + ((cc_ ^ ((row_ >> 1) & 3)) << 4)); \
            const size_t ka_ = (size_t)(m0 + row_) * Kp + (k0) + cc_ * 8;      \
            const size_t kb_ = (size_t)(n0 + row_) * Kp + (k0) + cc_ * 8;      \
            cpa16((sb) + off_, A + ka_);                                       \
            cpa16((sb) + OFFB + off_, B + kb_);                                \
        }                                                                      \
    } while (0)

#define TG_COMPUTE(sb)                                                         \
    do {                                                                       \
        _Pragma("unroll")                                                      \
        for (int ks = 0; ks < 2; ks++) {                                       \
            uint32_t aF[4][4];                                                 \
            _Pragma("unroll")                                                  \
            for (int mt = 0; mt < 4; mt++) {                                   \
                const int r = wm * 64 + mt * 16 + (lane & 15);                 \
                const int ch = ks * 2 + (lane >> 4);                           \
                const uint32_t off = (uint32_t)((r << 6) + ((ch ^ ((r >> 1) & 3)) << 4)); \
                LDSM4(aF[mt], (sb) + off);                                     \
            }                                                                  \
            _Pragma("unroll")                                                  \
            for (int half = 0; half < 2; half++) {                             \
                uint32_t bF[4][2];                                             \
                _Pragma("unroll")                                              \
                for (int p = 0; p < 2; p++) {                                  \
                    const int r = wn * 64 + half * 32 + p * 16 + (lane & 7) + ((lane & 16) >> 1); \
                    const int ch = ks * 2 + ((lane >> 3) & 1);                 \
                    const uint32_t off = (uint32_t)((r << 6) + ((ch ^ ((r >> 1) & 3)) << 4)); \
                    uint32_t q[4];                                             \
                    LDSM4(q, (sb) + OFFB + off);                               \
                    bF[p*2][0] = q[0]; bF[p*2][1] = q[1];                      \
                    bF[p*2+1][0] = q[2]; bF[p*2+1][1] = q[3];                  \
                }                                                              \
                _Pragma("unroll")                                              \
                for (int mt = 0; mt < 4; mt++)                                 \
                    _Pragma("unroll")                                          \
                    for (int nt = 0; nt < 4; nt++) MMA16816(acc[mt][half*4+nt], aF[mt], bF[nt]); \
            }                                                                  \
        }                                                                      \
    } while (0)

#define TG_MAINLOOP(kbase, nchunk)                                             \
    do {                                                                       \
        TG_LOAD_STAGE(smb, (kbase));                                           \
        CP_COMMIT();                                                           \
        if ((nchunk) > 1) { TG_LOAD_STAGE(smb + STAGE, (kbase) + GBK); CP_COMMIT(); } \
        int s_c = 0, s_ld = 2;                                                 \
        for (int c = 0; c < (nchunk); c++) {                                   \
            if (c + 1 < (nchunk)) CP_WAIT1(); else CP_WAIT0();                 \
            __syncthreads();                                                   \
            if (c + 2 < (nchunk)) { TG_LOAD_STAGE(smb + (uint32_t)s_ld * STAGE, (kbase) + (c + 2) * GBK); CP_COMMIT(); } \
            TG_COMPUTE(smb + (uint32_t)s_c * STAGE);                           \
            s_c = (s_c == 2) ? 0 : s_c + 1;                                    \
            s_ld = (s_ld == 2) ? 0 : s_ld + 1;                                 \
        }                                                                      \
    } while (0)

// ---------------- standard GEMM with fused epilogue ----------------
// epi: 0 = +bias -> Cf; 1 = relu(+bias) -> Ch (fp16); 3 = +PE -> Cf
__global__ void __launch_bounds__(128, 2) tgemm_kernel(
    const __half* __restrict__ A, const __half* __restrict__ B,
    const float* __restrict__ bias,
    float* __restrict__ Cf, __half* __restrict__ Ch,
    int Kp, int N, int epi)
{
    extern __shared__ char sm[];
    const uint32_t smb = smem_u32(sm);
    const int tid  = threadIdx.x;
    const int lane = tid & 31;
    const int wid  = tid >> 5;
    const int wm   = wid & 1;
    const int wn   = wid >> 1;
    const int m0 = blockIdx.y * 128;
    const int n0 = blockIdx.x * 128;

    float acc[4][8][4];
#pragma unroll
    for (int i = 0; i < 4; i++)
#pragma unroll
        for (int j = 0; j < 8; j++)
#pragma unroll
            for (int t = 0; t < 4; t++) acc[i][j][t] = 0.f;

    TG_MAINLOOP(0, Kp / GBK);

    // epilogue
#pragma unroll
    for (int mt = 0; mt < 4; mt++) {
        const int r0 = m0 + wm * 64 + mt * 16 + (lane >> 2);
#pragma unroll
        for (int nt = 0; nt < 8; nt++) {
            const int col = n0 + wn * 64 + nt * 8 + (lane & 3) * 2;
            const float* a = acc[mt][nt];
            if (epi == 1) {
                const float b0 = __ldg(&bias[col]);
                const float b1 = __ldg(&bias[col + 1]);
#pragma unroll
                for (int rr = 0; rr < 2; rr++) {
                    const int row = r0 + rr * 8;
                    const float v0 = fmaxf(a[rr * 2 + 0] + b0, 0.f);
                    const float v1 = fmaxf(a[rr * 2 + 1] + b1, 0.f);
                    *reinterpret_cast<__half2*>(&Ch[(size_t)row * N + col]) =
                        __halves2half2(__float2half_rn(v0), __float2half_rn(v1));
                }
            } else if (epi == 3) {
                const float dv = expf((float)(col & ~1) * (-9.210340371976184f / (float)DMODEL));
#pragma unroll
                for (int rr = 0; rr < 2; rr++) {
                    const int row = r0 + rr * 8;
                    const int srow = row % SEQ;
                    float sn, cs;
                    sincosf((float)srow * dv, &sn, &cs);
                    float2 o;
                    o.x = a[rr * 2 + 0] + sn;
                    o.y = a[rr * 2 + 1] + cs;
                    *reinterpret_cast<float2*>(&Cf[(size_t)row * N + col]) = o;
                }
            } else {
                const float b0 = __ldg(&bias[col]);
                const float b1 = __ldg(&bias[col + 1]);
#pragma unroll
                for (int rr = 0; rr < 2; rr++) {
                    const int row = r0 + rr * 8;
                    float2 o;
                    o.x = a[rr * 2 + 0] + b0;
                    o.y = a[rr * 2 + 1] + b1;
                    *reinterpret_cast<float2*>(&Cf[(size_t)row * N + col]) = o;
                }
            }
        }
    }
}

// ---------------- split-K GEMM: partial sums atomically added into prefilled C ----------------
__global__ void __launch_bounds__(128, 2) tgemm_atomic_kernel(
    const __half* __restrict__ A, const __half* __restrict__ B,
    float* __restrict__ Cf, int Kp, int Kz, int N)
{
    extern __shared__ char sm[];
    const uint32_t smb = smem_u32(sm);
    const int tid  = threadIdx.x;
    const int lane = tid & 31;
    const int wid  = tid >> 5;
    const int wm   = wid & 1;
    const int wn   = wid >> 1;
    const int m0 = blockIdx.y * 128;
    const int n0 = blockIdx.x * 128;
    const int kbase = blockIdx.z * Kz;

    float acc[4][8][4];
#pragma unroll
    for (int i = 0; i < 4; i++)
#pragma unroll
        for (int j = 0; j < 8; j++)
#pragma unroll
            for (int t = 0; t < 4; t++) acc[i][j][t] = 0.f;

    TG_MAINLOOP(kbase, Kz / GBK);

    // atomic epilogue
#pragma unroll
    for (int mt = 0; mt < 4; mt++) {
        const int r0 = m0 + wm * 64 + mt * 16 + (lane >> 2);
#pragma unroll
        for (int nt = 0; nt < 8; nt++) {
            const int col = n0 + wn * 64 + nt * 8 + (lane & 3) * 2;
            const float* a = acc[mt][nt];
#pragma unroll
            for (int rr = 0; rr < 2; rr++) {
                const int row = r0 + rr * 8;
                float* p = &Cf[(size_t)row * N + col];
                red_add_f32(p,     a[rr * 2 + 0]);
                red_add_f32(p + 1, a[rr * 2 + 1]);
            }
        }
    }
}

// ---------------- converters ----------------
__global__ void __launch_bounds__(256) cvt_x_kernel(
    const float* __restrict__ x, __half* __restrict__ xh)
{
    const int idx = blockIdx.x * 256 + threadIdx.x;
    if (idx >= NTOK * KEMBP) return;
    const int r = idx / KEMBP, c = idx % KEMBP;
    const float v = (c < KEMB) ? x[(size_t)r * KEMB + c] : 0.f;
    xh[idx] = __float2half_rn(v);
}

__global__ void cvt_wT_batch_kernel(
    const float* __restrict__ W, __half* __restrict__ Th,
    int K, int N, int Kp,
    size_t w_stride, size_t o_outer, size_t o_inner, int inner_mod)
{
    const int z = blockIdx.z;
    const float* Wz = W + (size_t)z * w_stride;
    const size_t ooff = (size_t)(z / inner_mod) * o_outer + (size_t)(z % inner_mod) * o_inner;
    __shared__ float t[32][33];
    const int k0 = blockIdx.y * 32, n0 = blockIdx.x * 32;
    const int tx = threadIdx.x, ty = threadIdx.y;
#pragma unroll
    for (int i = 0; i < 32; i += 8) {
        const int k = k0 + ty + i;
        t[ty + i][tx] = (k < K) ? Wz[(size_t)k * N + n0 + tx] : 0.f;
    }
    __syncthreads();
#pragma unroll
    for (int i = 0; i < 32; i += 8) {
        const int n = n0 + ty + i;
        const int k = k0 + tx;
        Th[ooff + (size_t)n * Kp + k] = __float2half_rn(t[tx][ty + i]);
    }
}

// ---------------- LayerNorm (ddof=1, eps on std) -> fp16, optional h += bias fused ----------------
__global__ void __launch_bounds__(256) ln_kernel(
    float* __restrict__ hio, const float* __restrict__ g,
    const float* __restrict__ b, __half* __restrict__ outh,
    const float* __restrict__ pbias)
{
    const int row = blockIdx.x;
    float* x = hio + (size_t)row * DMODEL;
    float vals[4];
    float s = 0.f, s2 = 0.f;
#pragma unroll
    for (int i = 0; i < 4; i++) {
        float v = x[threadIdx.x + i * 256];
        vals[i] = v; s += v; s2 += v * v;
    }
#pragma unroll
    for (int o = 16; o; o >>= 1) {
        s  += __shfl_xor_sync(0xffffffffu, s, o);
        s2 += __shfl_xor_sync(0xffffffffu, s2, o);
    }
    __shared__ float sh[2][8];
    const int w = threadIdx.x >> 5;
    if ((threadIdx.x & 31) == 0) { sh[0][w] = s; sh[1][w] = s2; }
    __syncthreads();
    if (threadIdx.x < 32) {
        s  = (threadIdx.x < 8) ? sh[0][threadIdx.x] : 0.f;
        s2 = (threadIdx.x < 8) ? sh[1][threadIdx.x] : 0.f;
#pragma unroll
        for (int o = 4; o; o >>= 1) {
            s  += __shfl_xor_sync(0xffffffffu, s, o);
            s2 += __shfl_xor_sync(0xffffffffu, s2, o);
        }
        if (threadIdx.x == 0) { sh[0][0] = s; sh[1][0] = s2; }
    }
    __syncthreads();
    const float mean = sh[0][0] * (1.f / (float)DMODEL);
    float var = (sh[1][0] - (float)DMODEL * mean * mean) * (1.f / (float)(DMODEL - 1));
    var = fmaxf(var, 0.f);
    const float inv = 1.f / (sqrtf(var) + 1e-6f);
#pragma unroll
    for (int i = 0; i < 4; i++) {
        const int c = threadIdx.x + i * 256;
        const float r = g[c] * (vals[i] - mean) * inv + b[c];
        outh[(size_t)row * DMODEL + c] = __float2half_rn(r);
        if (pbias) x[c] = vals[i] + pbias[c];
    }
}

// ---------------- gather last token per batch ----------------
__global__ void __launch_bounds__(256) gather_last_kernel(
    const float* __restrict__ h, const __half* __restrict__ o,
    const float* __restrict__ bias_o,
    float* __restrict__ hc, __half* __restrict__ oc)
{
    const int b = blockIdx.x;
    const size_t src = (size_t)(b * SEQ + (SEQ - 1)) * DMODEL;
    const size_t dst = (size_t)b * DMODEL;
#pragma unroll
    for (int i = 0; i < 4; i++) {
        const int c = threadIdx.x + i * 256;
        hc[dst + c] = h[src + c] + bias_o[c];
        oc[dst + c] = o[src + c];
    }
}

// ---------------- attention on fused QKV buffer ----------------
__global__ void __launch_bounds__(256) attn_kernel(
    const float* __restrict__ QKV, __half* __restrict__ O)
{
    const int bh = blockIdx.x;
    const int b = bh >> 4;
    const int h = bh & 15;

    __shared__ float qs[SEQ][DK];
    __shared__ float ks[SEQ][DK + 1];
    __shared__ float vs[SEQ][DK];
    __shared__ float sc[SEQ][SEQ];

    const int tid = threadIdx.x;
    for (int e = tid; e < SEQ * DK; e += 256) {
        const int s = e >> 6;
        const int d = e & 63;
        const size_t gbase = (size_t)(b * SEQ + s) * NQKV + h * DK + d;
        qs[s][d] = QKV[gbase];
        ks[s][d] = QKV[gbase + DMODEL];
        vs[s][d] = QKV[gbase + 2 * DMODEL];
    }
    __syncthreads();

    for (int e = tid; e < SEQ * SEQ; e += 256) {
        const int i = e / SEQ;
        const int j = e % SEQ;
        float acc = 0.f;
#pragma unroll
        for (int d = 0; d < DK; d++) acc = fmaf(qs[i][d], ks[j][d], acc);
        sc[i][j] = acc * 0.125f;
    }
    __syncthreads();

    if (tid < SEQ) {
        float mx = -1e30f;
#pragma unroll 1
        for (int j = 0; j < SEQ; j++) mx = fmaxf(mx, sc[tid][j]);
        float sum = 0.f;
#pragma unroll 1
        for (int j = 0; j < SEQ; j++) {
            float ev = expf(sc[tid][j] - mx);
            sum += ev;
            sc[tid][j] = ev;
        }
        const float r = 1.f / sum;
#pragma unroll 1
        for (int j = 0; j < SEQ; j++) sc[tid][j] *= r;
    }
    __syncthreads();

    for (int e = tid; e < SEQ * DK; e += 256) {
        const int i = e >> 6;
        const int d = e & 63;
        float acc = 0.f;
#pragma unroll
        for (int j = 0; j < SEQ; j++) acc = fmaf(sc[i][j], vs[j][d], acc);
        const size_t gidx = (size_t)(b * SEQ + i) * DMODEL + h * DK + d;
        O[gidx] = __float2half_rn(acc);
    }
}

// ---------------- head kernels ----------------
__global__ void __launch_bounds__(256) pool_ln_scale_kernel(
    const float* __restrict__ hc,
    const float* __restrict__ fin_g, const float* __restrict__ fin_b,
    const float* __restrict__ bn_g, const float* __restrict__ bn_b,
    float* __restrict__ z)
{
    const int bb = blockIdx.x;
    const float* x = hc + (size_t)bb * DMODEL;
    float vals[4];
    float s = 0.f, s2 = 0.f;
#pragma unroll
    for (int i = 0; i < 4; i++) {
        float v = x[threadIdx.x + i * 256];
        vals[i] = v; s += v; s2 += v * v;
    }
#pragma unroll
    for (int o = 16; o; o >>= 1) {
        s  += __shfl_xor_sync(0xffffffffu, s, o);
        s2 += __shfl_xor_sync(0xffffffffu, s2, o);
    }
    __shared__ float sh[2][8];
    const int w = threadIdx.x >> 5;
    if ((threadIdx.x & 31) == 0) { sh[0][w] = s; sh[1][w] = s2; }
    __syncthreads();
    if (threadIdx.x < 32) {
        s  = (threadIdx.x < 8) ? sh[0][threadIdx.x] : 0.f;
        s2 = (threadIdx.x < 8) ? sh[1][threadIdx.x] : 0.f;
#pragma unroll
        for (int o = 4; o; o >>= 1) {
            s  += __shfl_xor_sync(0xffffffffu, s, o);
            s2 += __shfl_xor_sync(0xffffffffu, s2, o);
        }
        if (threadIdx.x == 0) { sh[0][0] = s; sh[1][0] = s2; }
    }
    __syncthreads();
    const float mean = sh[0][0] * (1.f / (float)DMODEL);
    float var = (sh[1][0] - (float)DMODEL * mean * mean) * (1.f / (float)(DMODEL - 1));
    var = fmaxf(var, 0.f);
    const float inv = 1.f / (sqrtf(var) + 1e-6f);
    const float invbn = 1.f / sqrtf(1.0f + 1e-5f);
#pragma unroll
    for (int i = 0; i < 4; i++) {
        const int c = threadIdx.x + i * 256;
        const float lnv = fin_g[c] * (vals[i] - mean) * inv + fin_b[c];
        z[(size_t)bb * DMODEL + c] = lnv * invbn * bn_g[c] + bn_b[c];
    }
}

// ---------------- fp32 SGEMM (head only) ----------------
#define BM_S 128
#define BN_S 128
#define BK_S 8
__global__ void __launch_bounds__(256) sgemm_kernel(
    const float* __restrict__ A, const float* __restrict__ B,
    const float* __restrict__ bias, float* __restrict__ C,
    int M, int N, int K, int relu)
{
    __shared__ float As[BK_S][BM_S];
    __shared__ float Bs[BK_S][BN_S];
    const int tid = threadIdx.x;
    const int m0 = blockIdx.y * BM_S;
    const int n0 = blockIdx.x * BN_S;
    const int arow = tid >> 1;
    const int acol = (tid & 1) * 4;
    const int brow = tid >> 5;
    const int bcol = (tid & 31) * 4;
    const float* Aptr = A + (size_t)(m0 + arow) * K + acol;
    const float* Bptr = B + (size_t)brow * N + n0 + bcol;
    const int tx = tid & 15;
    const int ty = tid >> 4;
    float acc[8][8];
#pragma unroll
    for (int i = 0; i < 8; i++)
#pragma unroll
        for (int j = 0; j < 8; j++) acc[i][j] = 0.f;
    for (int k0 = 0; k0 < K; k0 += BK_S) {
        float4 a4 = *reinterpret_cast<const float4*>(Aptr + k0);
        float4 b4 = *reinterpret_cast<const float4*>(Bptr + (size_t)k0 * N);
        As[acol + 0][arow] = a4.x;
        As[acol + 1][arow] = a4.y;
        As[acol + 2][arow] = a4.z;
        As[acol + 3][arow] = a4.w;
        *reinterpret_cast<float4*>(&Bs[brow][bcol]) = b4;
        __syncthreads();
#pragma unroll
        for (int k = 0; k < BK_S; k++) {
            float ra[8], rb[8];
            *reinterpret_cast<float4*>(&ra[0]) = *reinterpret_cast<const float4*>(&As[k][ty * 8]);
            *reinterpret_cast<float4*>(&ra[4]) = *reinterpret_cast<const float4*>(&As[k][ty * 8 + 4]);
            *reinterpret_cast<float4*>(&rb[0]) = *reinterpret_cast<const float4*>(&Bs[k][tx * 8]);
            *reinterpret_cast<float4*>(&rb[4]) = *reinterpret_cast<const float4*>(&Bs[k][tx * 8 + 4]);
#pragma unroll
            for (int i = 0; i < 8; i++)
#pragma unroll
                for (int j = 0; j < 8; j++)
                    acc[i][j] = fmaf(ra[i], rb[j], acc[i][j]);
        }
        __syncthreads();
    }
#pragma unroll
    for (int i = 0; i < 8; i++) {
        const size_t base = (size_t)(m0 + ty * 8 + i) * N + n0 + tx * 8;
#pragma unroll
        for (int j = 0; j < 8; j++) {
            float v = acc[i][j] + __ldg(&bias[n0 + tx * 8 + j]);
            if (relu) v = fmaxf(v, 0.f);
            C[base + j] = v;
        }
    }
}

__global__ void __launch_bounds__(128) fc_kernel(
    const float* __restrict__ z1, const float* __restrict__ bn_g,
    const float* __restrict__ bn_b, const float* __restrict__ W,
    const float* __restrict__ bias, float* __restrict__ out)
{
    __shared__ float zs[DMODEL];
    const int bb = blockIdx.x;
    const float invbn = 1.f / sqrtf(1.0f + 1e-5f);
    for (int i = threadIdx.x; i < DMODEL; i += 128)
        zs[i] = z1[(size_t)bb * DMODEL + i] * invbn * bn_g[i] + bn_b[i];
    __syncthreads();
    const int c = threadIdx.x;
    if (c < NCLS) {
        float acc = bias[c];
        for (int k = 0; k < DMODEL; k++) acc = fmaf(zs[k], W[(size_t)k * NCLS + c], acc);
        out[(size_t)bb * NCLS + c] = acc;
    }
}

// ---------------- host launcher ----------------
extern "C" void kernel_launch(void* const* d_in, const int* in_sizes, int n_in,
                              void* d_out, int out_size)
{
    const float* x        = (const float*)d_in[0];
    const float* embed_w  = (const float*)d_in[1];
    const float* attn_w   = (const float*)d_in[2];
    const float* attn_b   = (const float*)d_in[3];
    const float* ff_w1    = (const float*)d_in[4];
    const float* ff_b1    = (const float*)d_in[5];
    const float* ff_w2    = (const float*)d_in[6];
    const float* ff_b2    = (const float*)d_in[7];
    const float* ln_g     = (const float*)d_in[8];
    const float* ln_b     = (const float*)d_in[9];
    const float* fin_g    = (const float*)d_in[10];
    const float* fin_b    = (const float*)d_in[11];
    const float* cf_bn_g  = (const float*)d_in[12];
    const float* cf_bn_b  = (const float*)d_in[13];
    const float* cf_w     = (const float*)d_in[14];
    const float* cf_b     = (const float*)d_in[15];
    const float* fc_bn_g  = (const float*)d_in[16];
    const float* fc_bn_b  = (const float*)d_in[17];
    const float* fc_w     = (const float*)d_in[18];
    const float* fc_b     = (const float*)d_in[19];

    cudaFuncSetAttribute(tgemm_kernel, cudaFuncAttributeMaxDynamicSharedMemorySize, 3 * STAGE);
    cudaFuncSetAttribute(tgemm_atomic_kernel, cudaFuncAttributeMaxDynamicSharedMemorySize, 3 * STAGE);

    float *g_h, *g_qkv, *g_hc, *g_z0, *g_z1;
    __half *g_xh, *g_a, *g_o, *g_f, *g_wt, *g_oc, *g_ac, *g_fc;
    cudaGetSymbolAddress((void**)&g_h,   d_h);
    cudaGetSymbolAddress((void**)&g_qkv, d_qkv);
    cudaGetSymbolAddress((void**)&g_hc,  d_hc);
    cudaGetSymbolAddress((void**)&g_z0,  d_z0);
    cudaGetSymbolAddress((void**)&g_z1,  d_z1);
    cudaGetSymbolAddress((void**)&g_xh,  d_xh);
    cudaGetSymbolAddress((void**)&g_a,   d_a);
    cudaGetSymbolAddress((void**)&g_o,   d_o);
    cudaGetSymbolAddress((void**)&g_f,   d_f);
    cudaGetSymbolAddress((void**)&g_wt,  d_wt);
    cudaGetSymbolAddress((void**)&g_oc,  d_oc);
    cudaGetSymbolAddress((void**)&g_ac,  d_ac);
    cudaGetSymbolAddress((void**)&g_fc,  d_fc);

    dim3 blk(32, 8);

    // converts
    cvt_x_kernel<<<(NTOK * KEMBP + 255) / 256, 256>>>(x, g_xh);
    cvt_wT_batch_kernel<<<dim3(1024 / 32, KEMBP / 32, 1), blk>>>(
        embed_w, g_wt, KEMB, DMODEL, KEMBP, 0, 0, 0, 1);
    cvt_wT_batch_kernel<<<dim3(32, 32, 20), blk>>>(
        attn_w, g_wt + WT_EMB_SZ, DMODEL, DMODEL, DMODEL,
        (size_t)DMODEL * DMODEL, (size_t)WT_LAYER, (size_t)1048576u, 4);
    cvt_wT_batch_kernel<<<dim3(DFF / 32, 32, 5), blk>>>(
        ff_w1, g_wt + WT_EMB_SZ + 4u * 1048576u,
        DMODEL, DFF, DMODEL, (size_t)DMODEL * DFF, (size_t)WT_LAYER, 0, 1);
    cvt_wT_batch_kernel<<<dim3(32, DFF / 32, 5), blk>>>(
        ff_w2, g_wt + WT_EMB_SZ + 8u * 1048576u,
        DFF, DMODEL, DFF, (size_t)DFF * DMODEL, (size_t)WT_LAYER, 0, 1);
    // embed GEMM, h = X @ We + PE
    {
        dim3 grid(DMODEL / 128, NTOK / 128);
        tgemm_kernel<<<grid, 128, 3 * STAGE>>>(
            g_xh, g_wt, nullptr, g_h, nullptr, KEMBP, DMODEL, 3);
    }

    // ---- layers 0..3 (full) ----
    for (int l = 0; l < NLAYER - 1; l++) {
        const size_t lw = (size_t)WT_EMB_SZ + (size_t)l * WT_LAYER;
        const __half* wq = g_wt + lw;
        const float* bq = attn_b + (size_t)l * 4 * DMODEL;

        ln_kernel<<<NTOK, 256>>>(g_h, ln_g + (size_t)(l * 2) * DMODEL,
                                 ln_b + (size_t)(l * 2) * DMODEL, g_a,
                                 bq + 3 * DMODEL);
        {
            dim3 grid(NQKV / 128, NTOK / 128);
            tgemm_kernel<<<grid, 128, 3 * STAGE>>>(
                g_a, wq, bq, g_qkv, nullptr, DMODEL, NQKV, 0);
        }
        attn_kernel<<<BATCH * NHEAD, 256>>>(g_qkv, g_o);
        {
            dim3 grid(DMODEL / 128, NTOK / 128, 2);
            tgemm_atomic_kernel<<<grid, 128, 3 * STAGE>>>(
                g_o, wq + 3u * 1048576u, g_h, DMODEL, DMODEL / 2, DMODEL);
        }
        ln_kernel<<<NTOK, 256>>>(g_h, ln_g + (size_t)(l * 2 + 1) * DMODEL,
                                 ln_b + (size_t)(l * 2 + 1) * DMODEL, g_a,
                                 ff_b2 + (size_t)l * DMODEL);
        {
            dim3 grid(DFF / 128, NTOK / 128);
            tgemm_kernel<<<grid, 128, 3 * STAGE>>>(
                g_a, g_wt + lw + 4u * 1048576u,
                ff_b1 + (size_t)l * DFF, nullptr, g_f, DMODEL, DFF, 1);
        }
        {
            dim3 grid(DMODEL / 128, NTOK / 128, 2);
            tgemm_atomic_kernel<<<grid, 128, 3 * STAGE>>>(
                g_f, g_wt + lw + 8u * 1048576u, g_h, DFF, DFF / 2, DMODEL);
        }
    }

    // ---- layer 4 (last): full QKV + attention, then compact 128-row tail ----
    {
        const int l = NLAYER - 1;
        const size_t lw = (size_t)WT_EMB_SZ + (size_t)l * WT_LAYER;
        const __half* wq = g_wt + lw;
        const float* bq = attn_b + (size_t)l * 4 * DMODEL;

        ln_kernel<<<NTOK, 256>>>(g_h, ln_g + (size_t)(l * 2) * DMODEL,
                                 ln_b + (size_t)(l * 2) * DMODEL, g_a, nullptr);
        {
            dim3 grid(NQKV / 128, NTOK / 128);
            tgemm_kernel<<<grid, 128, 3 * STAGE>>>(
                g_a, wq, bq, g_qkv, nullptr, DMODEL, NQKV, 0);
        }
        attn_kernel<<<BATCH * NHEAD, 256>>>(g_qkv, g_o);
        gather_last_kernel<<<BATCH, 256>>>(g_h, g_o, bq + 3 * DMODEL, g_hc, g_oc);
        {
            dim3 grid(DMODEL / 128, 1, 8);
            tgemm_atomic_kernel<<<grid, 128, 3 * STAGE>>>(
                g_oc, wq + 3u * 1048576u, g_hc, DMODEL, DMODEL / 8, DMODEL);
        }
        ln_kernel<<<BATCH, 256>>>(g_hc, ln_g + (size_t)(l * 2 + 1) * DMODEL,
                                  ln_b + (size_t)(l * 2 + 1) * DMODEL, g_ac,
                                  ff_b2 + (size_t)l * DMODEL);
        {
            dim3 grid(DFF / 128, 1);
            tgemm_kernel<<<grid, 128, 3 * STAGE>>>(
                g_ac, g_wt + lw + 4u * 1048576u,
                ff_b1 + (size_t)l * DFF, nullptr, g_fc, DMODEL, DFF, 1);
        }
        {
            dim3 grid(DMODEL / 128, 1, 8);
            tgemm_atomic_kernel<<<grid, 128, 3 * STAGE>>>(
                g_fc, g_wt + lw + 8u * 1048576u, g_hc, DFF, DFF / 8, DMODEL);
        }
    }

    // ---- classifier head ----
    pool_ln_scale_kernel<<<BATCH, 256>>>(g_hc, fin_g, fin_b, cf_bn_g, cf_bn_b, g_z0);
    sgemm_kernel<<<dim3(DMODEL / BN_S, 1), 256>>>(g_z0, cf_w, cf_b, g_z1, BATCH, DMODEL, DMODEL, 1);
    fc_kernel<<<BATCH, 128>>>(g_z1, fc_bn_g, fc_bn_b, fc_w, fc_b, (float*)d_out);
}

// round 11
// speedup vs baseline: 2.3725x; 1.0424x over previous
#include <cuda_runtime.h>
#include <cuda_fp16.h>
#include <math.h>
#include <stdint.h>

// ---------------- problem constants ----------------
#define BATCH 128
#define SEQ   50
#define DMODEL 1024
#define DFF   4096
#define NHEAD 16
#define DK    64
#define NLAYER 5
#define KEMB  1200
#define KEMBP 1216
#define NTOK  6400
#define NCLS  71
#define NQKV  3072

#define GBK 32

// ---------------- weight scratch layout (transposed fp16) ----------------
#define WT_EMB_SZ (1024u*1216u)
#define WT_LAYER  (12u*1024u*1024u)
#define WT_TOTAL  (WT_EMB_SZ + 5u*WT_LAYER)

// ---------------- scratch (device globals) ----------------
__device__ float d_h  [NTOK * DMODEL];
__device__ float d_hc [BATCH * DMODEL];
__device__ float d_z0 [BATCH * DMODEL];
__device__ float d_z1 [BATCH * DMODEL];

__device__ __align__(16) __half d_qkv[NTOK * NQKV];
__device__ __align__(16) __half d_xh[NTOK * KEMBP];
__device__ __align__(16) __half d_a [NTOK * DMODEL];
__device__ __align__(16) __half d_o [NTOK * DMODEL];
__device__ __align__(16) __half d_f [NTOK * DFF];
__device__ __align__(16) __half d_wt[WT_TOTAL];
// compact (128-row) buffers for last-layer tail
__device__ __align__(16) __half d_oc[BATCH * DMODEL];
__device__ __align__(16) __half d_ac[BATCH * DMODEL];
__device__ __align__(16) __half d_fc[BATCH * DFF];

// ---------------- PTX helpers ----------------
__device__ __forceinline__ uint32_t smem_u32(const void* p) {
    uint32_t a;
    asm("{ .reg .u64 t; cvta.to.shared.u64 t, %1; cvt.u32.u64 %0, t; }" : "=r"(a) : "l"(p));
    return a;
}
__device__ __forceinline__ void cpa16(uint32_t dst, const void* src) {
    asm volatile("cp.async.cg.shared.global [%0], [%1], 16;" :: "r"(dst), "l"(src));
}
#define CP_COMMIT() asm volatile("cp.async.commit_group;" ::: "memory")
#define CP_WAIT2()  asm volatile("cp.async.wait_group 2;" ::: "memory")
#define CP_WAIT1()  asm volatile("cp.async.wait_group 1;" ::: "memory")
#define CP_WAIT0()  asm volatile("cp.async.wait_group 0;" ::: "memory")
#define LDSM4(r, a) \
    asm volatile("ldmatrix.sync.aligned.m8n8.x4.shared.b16 {%0,%1,%2,%3}, [%4];" \
        : "=r"((r)[0]), "=r"((r)[1]), "=r"((r)[2]), "=r"((r)[3]) : "r"(a))
#define MMA16816(c, a, b) \
    asm volatile("mma.sync.aligned.m16n8k16.row.col.f32.f16.f16.f32 " \
        "{%0,%1,%2,%3}, {%4,%5,%6,%7}, {%8,%9}, {%0,%1,%2,%3};" \
        : "+f"((c)[0]), "+f"((c)[1]), "+f"((c)[2]), "+f"((c)[3]) \
        : "r"((a)[0]), "r"((a)[1]), "r"((a)[2]), "r"((a)[3]), "r"((b)[0]), "r"((b)[1]))
__device__ __forceinline__ void red_add_f32(float* p, float v) {
    asm volatile("red.global.add.f32 [%0], %1;" :: "l"(p), "f"(v) : "memory");
}

// ================= HMMA GEMM core: 128x128 CTA tile, 128 thr, 4 warps (2x2, 64x64 warp tile)
// A: fp16 activations. B: fp16 weights (transposed [N][Kp]). 4-stage cp.async pipeline.
#define OFFB  8192u
#define STAGE 16384u
#define TGSMEM (4u * STAGE)

#define TG_LOAD_STAGE(sb, k0)                                                  \
    do {                                                                       \
        _Pragma("unroll")                                                      \
        for (int i_ = 0; i_ < 4; i_++) {                                       \
            const int id_ = tid + i_ * 128;                                    \
            const int row_ = id_ >> 2, cc_ = id_ & 3;                          \
            const uint32_t off_ = (uint32_t)((row_ << 6) + ((cc_ ^ ((row_ >> 1) & 3)) << 4)); \
            const size_t ka_ = (size_t)(m0 + row_) * Kp + (k0) + cc_ * 8;      \
            const size_t kb_ = (size_t)(n0 + row_) * Kp + (k0) + cc_ * 8;      \
            cpa16((sb) + off_, A + ka_);                                       \
            cpa16((sb) + OFFB + off_, B + kb_);                                \
        }                                                                      \
    } while (0)

#define TG_COMPUTE(sb)                                                         \
    do {                                                                       \
        _Pragma("unroll")                                                      \
        for (int ks = 0; ks < 2; ks++) {                                       \
            uint32_t aF[4][4];                                                 \
            _Pragma("unroll")                                                  \
            for (int mt = 0; mt < 4; mt++) {                                   \
                const int r = wm * 64 + mt * 16 + (lane & 15);                 \
                const int ch = ks * 2 + (lane >> 4);                           \
                const uint32_t off = (uint32_t)((r << 6) + ((ch ^ ((r >> 1) & 3)) << 4)); \
                LDSM4(aF[mt], (sb) + off);                                     \
            }                                                                  \
            _Pragma("unroll")                                                  \
            for (int half = 0; half < 2; half++) {                             \
                uint32_t bF[4][2];                                             \
                _Pragma("unroll")                                              \
                for (int p = 0; p < 2; p++) {                                  \
                    const int r = wn * 64 + half * 32 + p * 16 + (lane & 7) + ((lane & 16) >> 1); \
                    const int ch = ks * 2 + ((lane >> 3) & 1);                 \
                    const uint32_t off = (uint32_t)((r << 6) + ((ch ^ ((r >> 1) & 3)) << 4)); \
                    uint32_t q[4];                                             \
                    LDSM4(q, (sb) + OFFB + off);                               \
                    bF[p*2][0] = q[0]; bF[p*2][1] = q[1];                      \
                    bF[p*2+1][0] = q[2]; bF[p*2+1][1] = q[3];                  \
                }                                                              \
                _Pragma("unroll")                                              \
                for (int mt = 0; mt < 4; mt++)                                 \
                    _Pragma("unroll")                                          \
                    for (int nt = 0; nt < 4; nt++) MMA16816(acc[mt][half*4+nt], aF[mt], bF[nt]); \
            }                                                                  \
        }                                                                      \
    } while (0)

#define TG_MAINLOOP(kbase, nchunk)                                             \
    do {                                                                       \
        TG_LOAD_STAGE(smb, (kbase));                                           \
        CP_COMMIT();                                                           \
        if ((nchunk) > 1) { TG_LOAD_STAGE(smb + STAGE, (kbase) + GBK); CP_COMMIT(); } \
        if ((nchunk) > 2) { TG_LOAD_STAGE(smb + 2u * STAGE, (kbase) + 2 * GBK); CP_COMMIT(); } \
        int s_c = 0, s_ld = 3;                                                 \
        for (int c = 0; c < (nchunk); c++) {                                   \
            const int wg_ = (nchunk) - c - 1;                                  \
            if (wg_ >= 2) CP_WAIT2(); else if (wg_ == 1) CP_WAIT1(); else CP_WAIT0(); \
            __syncthreads();                                                   \
            if (c + 3 < (nchunk)) { TG_LOAD_STAGE(smb + (uint32_t)s_ld * STAGE, (kbase) + (c + 3) * GBK); CP_COMMIT(); } \
            TG_COMPUTE(smb + (uint32_t)s_c * STAGE);                           \
            s_c = (s_c + 1) & 3; s_ld = (s_ld + 1) & 3;                        \
        }                                                                      \
    } while (0)

// ---------------- standard GEMM with fused epilogue ----------------
// epi: 0 = +bias -> Ch (fp16); 1 = relu(+bias) -> Ch (fp16); 3 = +PE -> Cf
__global__ void __launch_bounds__(128, 2) tgemm_kernel(
    const __half* __restrict__ A, const __half* __restrict__ B,
    const float* __restrict__ bias,
    float* __restrict__ Cf, __half* __restrict__ Ch,
    int Kp, int N, int epi)
{
    extern __shared__ char sm[];
    const uint32_t smb = smem_u32(sm);
    const int tid  = threadIdx.x;
    const int lane = tid & 31;
    const int wid  = tid >> 5;
    const int wm   = wid & 1;
    const int wn   = wid >> 1;
    const int m0 = blockIdx.y * 128;
    const int n0 = blockIdx.x * 128;

    float acc[4][8][4];
#pragma unroll
    for (int i = 0; i < 4; i++)
#pragma unroll
        for (int j = 0; j < 8; j++)
#pragma unroll
            for (int t = 0; t < 4; t++) acc[i][j][t] = 0.f;

    TG_MAINLOOP(0, Kp / GBK);

    // epilogue
#pragma unroll
    for (int mt = 0; mt < 4; mt++) {
        const int r0 = m0 + wm * 64 + mt * 16 + (lane >> 2);
#pragma unroll
        for (int nt = 0; nt < 8; nt++) {
            const int col = n0 + wn * 64 + nt * 8 + (lane & 3) * 2;
            const float* a = acc[mt][nt];
            if (epi == 3) {
                const float dv = expf((float)(col & ~1) * (-9.210340371976184f / (float)DMODEL));
#pragma unroll
                for (int rr = 0; rr < 2; rr++) {
                    const int row = r0 + rr * 8;
                    const int srow = row % SEQ;
                    float sn, cs;
                    sincosf((float)srow * dv, &sn, &cs);
                    float2 o;
                    o.x = a[rr * 2 + 0] + sn;
                    o.y = a[rr * 2 + 1] + cs;
                    *reinterpret_cast<float2*>(&Cf[(size_t)row * N + col]) = o;
                }
            } else {
                const float b0 = __ldg(&bias[col]);
                const float b1 = __ldg(&bias[col + 1]);
#pragma unroll
                for (int rr = 0; rr < 2; rr++) {
                    const int row = r0 + rr * 8;
                    float v0 = a[rr * 2 + 0] + b0;
                    float v1 = a[rr * 2 + 1] + b1;
                    if (epi == 1) { v0 = fmaxf(v0, 0.f); v1 = fmaxf(v1, 0.f); }
                    *reinterpret_cast<__half2*>(&Ch[(size_t)row * N + col]) =
                        __halves2half2(__float2half_rn(v0), __float2half_rn(v1));
                }
            }
        }
    }
}

// ---------------- split-K GEMM: partial sums atomically added into prefilled C ----------------
__global__ void __launch_bounds__(128, 2) tgemm_atomic_kernel(
    const __half* __restrict__ A, const __half* __restrict__ B,
    float* __restrict__ Cf, int Kp, int Kz, int N)
{
    extern __shared__ char sm[];
    const uint32_t smb = smem_u32(sm);
    const int tid  = threadIdx.x;
    const int lane = tid & 31;
    const int wid  = tid >> 5;
    const int wm   = wid & 1;
    const int wn   = wid >> 1;
    const int m0 = blockIdx.y * 128;
    const int n0 = blockIdx.x * 128;
    const int kbase = blockIdx.z * Kz;

    float acc[4][8][4];
#pragma unroll
    for (int i = 0; i < 4; i++)
#pragma unroll
        for (int j = 0; j < 8; j++)
#pragma unroll
            for (int t = 0; t < 4; t++) acc[i][j][t] = 0.f;

    TG_MAINLOOP(kbase, Kz / GBK);

    // atomic epilogue
#pragma unroll
    for (int mt = 0; mt < 4; mt++) {
        const int r0 = m0 + wm * 64 + mt * 16 + (lane >> 2);
#pragma unroll
        for (int nt = 0; nt < 8; nt++) {
            const int col = n0 + wn * 64 + nt * 8 + (lane & 3) * 2;
            const float* a = acc[mt][nt];
#pragma unroll
            for (int rr = 0; rr < 2; rr++) {
                const int row = r0 + rr * 8;
                float* p = &Cf[(size_t)row * N + col];
                red_add_f32(p,     a[rr * 2 + 0]);
                red_add_f32(p + 1, a[rr * 2 + 1]);
            }
        }
    }
}

// ---------------- converters ----------------
__global__ void __launch_bounds__(256) cvt_x_kernel(
    const float* __restrict__ x, __half* __restrict__ xh)
{
    const int idx = blockIdx.x * 256 + threadIdx.x;
    if (idx >= NTOK * KEMBP) return;
    const int r = idx / KEMBP, c = idx % KEMBP;
    const float v = (c < KEMB) ? x[(size_t)r * KEMB + c] : 0.f;
    xh[idx] = __float2half_rn(v);
}

__global__ void cvt_wT_batch_kernel(
    const float* __restrict__ W, __half* __restrict__ Th,
    int K, int N, int Kp,
    size_t w_stride, size_t o_outer, size_t o_inner, int inner_mod)
{
    const int z = blockIdx.z;
    const float* Wz = W + (size_t)z * w_stride;
    const size_t ooff = (size_t)(z / inner_mod) * o_outer + (size_t)(z % inner_mod) * o_inner;
    __shared__ float t[32][33];
    const int k0 = blockIdx.y * 32, n0 = blockIdx.x * 32;
    const int tx = threadIdx.x, ty = threadIdx.y;
#pragma unroll
    for (int i = 0; i < 32; i += 8) {
        const int k = k0 + ty + i;
        t[ty + i][tx] = (k < K) ? Wz[(size_t)k * N + n0 + tx] : 0.f;
    }
    __syncthreads();
#pragma unroll
    for (int i = 0; i < 32; i += 8) {
        const int n = n0 + ty + i;
        const int k = k0 + tx;
        Th[ooff + (size_t)n * Kp + k] = __float2half_rn(t[tx][ty + i]);
    }
}

// ---------------- LayerNorm (ddof=1, eps on std) -> fp16, optional h += bias fused ----------------
__global__ void __launch_bounds__(256) ln_kernel(
    float* __restrict__ hio, const float* __restrict__ g,
    const float* __restrict__ b, __half* __restrict__ outh,
    const float* __restrict__ pbias)
{
    const int row = blockIdx.x;
    float* x = hio + (size_t)row * DMODEL;
    float vals[4];
    float s = 0.f, s2 = 0.f;
#pragma unroll
    for (int i = 0; i < 4; i++) {
        float v = x[threadIdx.x + i * 256];
        vals[i] = v; s += v; s2 += v * v;
    }
#pragma unroll
    for (int o = 16; o; o >>= 1) {
        s  += __shfl_xor_sync(0xffffffffu, s, o);
        s2 += __shfl_xor_sync(0xffffffffu, s2, o);
    }
    __shared__ float sh[2][8];
    const int w = threadIdx.x >> 5;
    if ((threadIdx.x & 31) == 0) { sh[0][w] = s; sh[1][w] = s2; }
    __syncthreads();
    if (threadIdx.x < 32) {
        s  = (threadIdx.x < 8) ? sh[0][threadIdx.x] : 0.f;
        s2 = (threadIdx.x < 8) ? sh[1][threadIdx.x] : 0.f;
#pragma unroll
        for (int o = 4; o; o >>= 1) {
            s  += __shfl_xor_sync(0xffffffffu, s, o);
            s2 += __shfl_xor_sync(0xffffffffu, s2, o);
        }
        if (threadIdx.x == 0) { sh[0][0] = s; sh[1][0] = s2; }
    }
    __syncthreads();
    const float mean = sh[0][0] * (1.f / (float)DMODEL);
    float var = (sh[1][0] - (float)DMODEL * mean * mean) * (1.f / (float)(DMODEL - 1));
    var = fmaxf(var, 0.f);
    const float inv = 1.f / (sqrtf(var) + 1e-6f);
#pragma unroll
    for (int i = 0; i < 4; i++) {
        const int c = threadIdx.x + i * 256;
        const float r = g[c] * (vals[i] - mean) * inv + b[c];
        outh[(size_t)row * DMODEL + c] = __float2half_rn(r);
        if (pbias) x[c] = vals[i] + pbias[c];
    }
}

// ---------------- gather last token per batch ----------------
__global__ void __launch_bounds__(256) gather_last_kernel(
    const float* __restrict__ h, const __half* __restrict__ o,
    const float* __restrict__ bias_o,
    float* __restrict__ hc, __half* __restrict__ oc)
{
    const int b = blockIdx.x;
    const size_t src = (size_t)(b * SEQ + (SEQ - 1)) * DMODEL;
    const size_t dst = (size_t)b * DMODEL;
#pragma unroll
    for (int i = 0; i < 4; i++) {
        const int c = threadIdx.x + i * 256;
        hc[dst + c] = h[src + c] + bias_o[c];
        oc[dst + c] = o[src + c];
    }
}

// ---------------- attention on fused fp16 QKV buffer; warp-parallel softmax ----------------
__global__ void __launch_bounds__(256) attn_kernel(
    const __half* __restrict__ QKV, __half* __restrict__ O)
{
    const int bh = blockIdx.x;
    const int b = bh >> 4;
    const int h = bh & 15;

    __shared__ float qs[SEQ][DK];
    __shared__ float ks[SEQ][DK + 1];
    __shared__ float vs[SEQ][DK];
    __shared__ float sc[SEQ][SEQ + 2];

    const int tid = threadIdx.x;
    const int lane = tid & 31;
    const int wid = tid >> 5;

    for (int e = tid; e < SEQ * DK; e += 256) {
        const int s = e >> 6;
        const int d = e & 63;
        const size_t gbase = (size_t)(b * SEQ + s) * NQKV + h * DK + d;
        qs[s][d] = __half2float(QKV[gbase]);
        ks[s][d] = __half2float(QKV[gbase + DMODEL]);
        vs[s][d] = __half2float(QKV[gbase + 2 * DMODEL]);
    }
    __syncthreads();

    for (int e = tid; e < SEQ * SEQ; e += 256) {
        const int i = e / SEQ;
        const int j = e % SEQ;
        float acc = 0.f;
#pragma unroll
        for (int d = 0; d < DK; d++) acc = fmaf(qs[i][d], ks[j][d], acc);
        sc[i][j] = acc * 0.125f;
    }
    __syncthreads();

    // warp-per-row softmax: warp w handles rows w, w+8, ...
    for (int r = wid; r < SEQ; r += 8) {
        const float v0 = (lane < SEQ) ? sc[r][lane] : -1e30f;
        const float v1 = (lane + 32 < SEQ) ? sc[r][lane + 32] : -1e30f;
        float mx = fmaxf(v0, v1);
#pragma unroll
        for (int o = 16; o; o >>= 1) mx = fmaxf(mx, __shfl_xor_sync(0xffffffffu, mx, o));
        const float e0 = (lane < SEQ) ? expf(v0 - mx) : 0.f;
        const float e1 = (lane + 32 < SEQ) ? expf(v1 - mx) : 0.f;
        float sum = e0 + e1;
#pragma unroll
        for (int o = 16; o; o >>= 1) sum += __shfl_xor_sync(0xffffffffu, sum, o);
        const float rinv = 1.f / sum;
        if (lane < SEQ) sc[r][lane] = e0 * rinv;
        if (lane + 32 < SEQ) sc[r][lane + 32] = e1 * rinv;
    }
    __syncthreads();

    for (int e = tid; e < SEQ * DK; e += 256) {
        const int i = e >> 6;
        const int d = e & 63;
        float acc = 0.f;
#pragma unroll
        for (int j = 0; j < SEQ; j++) acc = fmaf(sc[i][j], vs[j][d], acc);
        const size_t gidx = (size_t)(b * SEQ + i) * DMODEL + h * DK + d;
        O[gidx] = __float2half_rn(acc);
    }
}

// ---------------- head kernels ----------------
__global__ void __launch_bounds__(256) pool_ln_scale_kernel(
    const float* __restrict__ hc,
    const float* __restrict__ fin_g, const float* __restrict__ fin_b,
    const float* __restrict__ bn_g, const float* __restrict__ bn_b,
    float* __restrict__ z)
{
    const int bb = blockIdx.x;
    const float* x = hc + (size_t)bb * DMODEL;
    float vals[4];
    float s = 0.f, s2 = 0.f;
#pragma unroll
    for (int i = 0; i < 4; i++) {
        float v = x[threadIdx.x + i * 256];
        vals[i] = v; s += v; s2 += v * v;
    }
#pragma unroll
    for (int o = 16; o; o >>= 1) {
        s  += __shfl_xor_sync(0xffffffffu, s, o);
        s2 += __shfl_xor_sync(0xffffffffu, s2, o);
    }
    __shared__ float sh[2][8];
    const int w = threadIdx.x >> 5;
    if ((threadIdx.x & 31) == 0) { sh[0][w] = s; sh[1][w] = s2; }
    __syncthreads();
    if (threadIdx.x < 32) {
        s  = (threadIdx.x < 8) ? sh[0][threadIdx.x] : 0.f;
        s2 = (threadIdx.x < 8) ? sh[1][threadIdx.x] : 0.f;
#pragma unroll
        for (int o = 4; o; o >>= 1) {
            s  += __shfl_xor_sync(0xffffffffu, s, o);
            s2 += __shfl_xor_sync(0xffffffffu, s2, o);
        }
        if (threadIdx.x == 0) { sh[0][0] = s; sh[1][0] = s2; }
    }
    __syncthreads();
    const float mean = sh[0][0] * (1.f / (float)DMODEL);
    float var = (sh[1][0] - (float)DMODEL * mean * mean) * (1.f / (float)(DMODEL - 1));
    var = fmaxf(var, 0.f);
    const float inv = 1.f / (sqrtf(var) + 1e-6f);
    const float invbn = 1.f / sqrtf(1.0f + 1e-5f);
#pragma unroll
    for (int i = 0; i < 4; i++) {
        const int c = threadIdx.x + i * 256;
        const float lnv = fin_g[c] * (vals[i] - mean) * inv + fin_b[c];
        z[(size_t)bb * DMODEL + c] = lnv * invbn * bn_g[c] + bn_b[c];
    }
}

// ---------------- fp32 SGEMM (head only) ----------------
#define BM_S 128
#define BN_S 128
#define BK_S 8
__global__ void __launch_bounds__(256) sgemm_kernel(
    const float* __restrict__ A, const float* __restrict__ B,
    const float* __restrict__ bias, float* __restrict__ C,
    int M, int N, int K, int relu)
{
    __shared__ float As[BK_S][BM_S];
    __shared__ float Bs[BK_S][BN_S];
    const int tid = threadIdx.x;
    const int m0 = blockIdx.y * BM_S;
    const int n0 = blockIdx.x * BN_S;
    const int arow = tid >> 1;
    const int acol = (tid & 1) * 4;
    const int brow = tid >> 5;
    const int bcol = (tid & 31) * 4;
    const float* Aptr = A + (size_t)(m0 + arow) * K + acol;
    const float* Bptr = B + (size_t)brow * N + n0 + bcol;
    const int tx = tid & 15;
    const int ty = tid >> 4;
    float acc[8][8];
#pragma unroll
    for (int i = 0; i < 8; i++)
#pragma unroll
        for (int j = 0; j < 8; j++) acc[i][j] = 0.f;
    for (int k0 = 0; k0 < K; k0 += BK_S) {
        float4 a4 = *reinterpret_cast<const float4*>(Aptr + k0);
        float4 b4 = *reinterpret_cast<const float4*>(Bptr + (size_t)k0 * N);
        As[acol + 0][arow] = a4.x;
        As[acol + 1][arow] = a4.y;
        As[acol + 2][arow] = a4.z;
        As[acol + 3][arow] = a4.w;
        *reinterpret_cast<float4*>(&Bs[brow][bcol]) = b4;
        __syncthreads();
#pragma unroll
        for (int k = 0; k < BK_S; k++) {
            float ra[8], rb[8];
            *reinterpret_cast<float4*>(&ra[0]) = *reinterpret_cast<const float4*>(&As[k][ty * 8]);
            *reinterpret_cast<float4*>(&ra[4]) = *reinterpret_cast<const float4*>(&As[k][ty * 8 + 4]);
            *reinterpret_cast<float4*>(&rb[0]) = *reinterpret_cast<const float4*>(&Bs[k][tx * 8]);
            *reinterpret_cast<float4*>(&rb[4]) = *reinterpret_cast<const float4*>(&Bs[k][tx * 8 + 4]);
#pragma unroll
            for (int i = 0; i < 8; i++)
#pragma unroll
                for (int j = 0; j < 8; j++)
                    acc[i][j] = fmaf(ra[i], rb[j], acc[i][j]);
        }
        __syncthreads();
    }
#pragma unroll
    for (int i = 0; i < 8; i++) {
        const size_t base = (size_t)(m0 + ty * 8 + i) * N + n0 + tx * 8;
#pragma unroll
        for (int j = 0; j < 8; j++) {
            float v = acc[i][j] + __ldg(&bias[n0 + tx * 8 + j]);
            if (relu) v = fmaxf(v, 0.f);
            C[base + j] = v;
        }
    }
}

__global__ void __launch_bounds__(128) fc_kernel(
    const float* __restrict__ z1, const float* __restrict__ bn_g,
    const float* __restrict__ bn_b, const float* __restrict__ W,
    const float* __restrict__ bias, float* __restrict__ out)
{
    __shared__ float zs[DMODEL];
    const int bb = blockIdx.x;
    const float invbn = 1.f / sqrtf(1.0f + 1e-5f);
    for (int i = threadIdx.x; i < DMODEL; i += 128)
        zs[i] = z1[(size_t)bb * DMODEL + i] * invbn * bn_g[i] + bn_b[i];
    __syncthreads();
    const int c = threadIdx.x;
    if (c < NCLS) {
        float acc = bias[c];
        for (int k = 0; k < DMODEL; k++) acc = fmaf(zs[k], W[(size_t)k * NCLS + c], acc);
        out[(size_t)bb * NCLS + c] = acc;
    }
}

// ---------------- host launcher ----------------
extern "C" void kernel_launch(void* const* d_in, const int* in_sizes, int n_in,
                              void* d_out, int out_size)
{
    const float* x        = (const float*)d_in[0];
    const float* embed_w  = (const float*)d_in[1];
    const float* attn_w   = (const float*)d_in[2];
    const float* attn_b   = (const float*)d_in[3];
    const float* ff_w1    = (const float*)d_in[4];
    const float* ff_b1    = (const float*)d_in[5];
    const float* ff_w2    = (const float*)d_in[6];
    const float* ff_b2    = (const float*)d_in[7];
    const float* ln_g     = (const float*)d_in[8];
    const float* ln_b     = (const float*)d_in[9];
    const float* fin_g    = (const float*)d_in[10];
    const float* fin_b    = (const float*)d_in[11];
    const float* cf_bn_g  = (const float*)d_in[12];
    const float* cf_bn_b  = (const float*)d_in[13];
    const float* cf_w     = (const float*)d_in[14];
    const float* cf_b     = (const float*)d_in[15];
    const float* fc_bn_g  = (const float*)d_in[16];
    const float* fc_bn_b  = (const float*)d_in[17];
    const float* fc_w     = (const float*)d_in[18];
    const float* fc_b     = (const float*)d_in[19];

    cudaFuncSetAttribute(tgemm_kernel, cudaFuncAttributeMaxDynamicSharedMemorySize, TGSMEM);
    cudaFuncSetAttribute(tgemm_atomic_kernel, cudaFuncAttributeMaxDynamicSharedMemorySize, TGSMEM);

    float *g_h, *g_hc, *g_z0, *g_z1;
    __half *g_qkv, *g_xh, *g_a, *g_o, *g_f, *g_wt, *g_oc, *g_ac, *g_fc;
    cudaGetSymbolAddress((void**)&g_h,   d_h);
    cudaGetSymbolAddress((void**)&g_qkv, d_qkv);
    cudaGetSymbolAddress((void**)&g_hc,  d_hc);
    cudaGetSymbolAddress((void**)&g_z0,  d_z0);
    cudaGetSymbolAddress((void**)&g_z1,  d_z1);
    cudaGetSymbolAddress((void**)&g_xh,  d_xh);
    cudaGetSymbolAddress((void**)&g_a,   d_a);
    cudaGetSymbolAddress((void**)&g_o,   d_o);
    cudaGetSymbolAddress((void**)&g_f,   d_f);
    cudaGetSymbolAddress((void**)&g_wt,  d_wt);
    cudaGetSymbolAddress((void**)&g_oc,  d_oc);
    cudaGetSymbolAddress((void**)&g_ac,  d_ac);
    cudaGetSymbolAddress((void**)&g_fc,  d_fc);

    dim3 blk(32, 8);

    // converts
    cvt_x_kernel<<<(NTOK * KEMBP + 255) / 256, 256>>>(x, g_xh);
    cvt_wT_batch_kernel<<<dim3(1024 / 32, KEMBP / 32, 1), blk>>>(
        embed_w, g_wt, KEMB, DMODEL, KEMBP, 0, 0, 0, 1);
    cvt_wT_batch_kernel<<<dim3(32, 32, 20), blk>>>(
        attn_w, g_wt + WT_EMB_SZ, DMODEL, DMODEL, DMODEL,
        (size_t)DMODEL * DMODEL, (size_t)WT_LAYER, (size_t)1048576u, 4);
    cvt_wT_batch_kernel<<<dim3(DFF / 32, 32, 5), blk>>>(
        ff_w1, g_wt + WT_EMB_SZ + 4u * 1048576u,
        DMODEL, DFF, DMODEL, (size_t)DMODEL * DFF, (size_t)WT_LAYER, 0, 1);
    cvt_wT_batch_kernel<<<dim3(32, DFF / 32, 5), blk>>>(
        ff_w2, g_wt + WT_EMB_SZ + 8u * 1048576u,
        DFF, DMODEL, DFF, (size_t)DFF * DMODEL, (size_t)WT_LAYER, 0, 1);
    // embed GEMM, h = X @ We + PE
    {
        dim3 grid(DMODEL / 128, NTOK / 128);
        tgemm_kernel<<<grid, 128, TGSMEM>>>(
            g_xh, g_wt, nullptr, g_h, nullptr, KEMBP, DMODEL, 3);
    }

    // ---- layers 0..3 (full) ----
    for (int l = 0; l < NLAYER - 1; l++) {
        const size_t lw = (size_t)WT_EMB_SZ + (size_t)l * WT_LAYER;
        const __half* wq = g_wt + lw;
        const float* bq = attn_b + (size_t)l * 4 * DMODEL;

        ln_kernel<<<NTOK, 256>>>(g_h, ln_g + (size_t)(l * 2) * DMODEL,
                                 ln_b + (size_t)(l * 2) * DMODEL, g_a,
                                 bq + 3 * DMODEL);
        {
            dim3 grid(NQKV / 128, NTOK / 128);
            tgemm_kernel<<<grid, 128, TGSMEM>>>(
                g_a, wq, bq, nullptr, g_qkv, DMODEL, NQKV, 0);
        }
        attn_kernel<<<BATCH * NHEAD, 256>>>(g_qkv, g_o);
        {
            dim3 grid(DMODEL / 128, NTOK / 128, 2);
            tgemm_atomic_kernel<<<grid, 128, TGSMEM>>>(
                g_o, wq + 3u * 1048576u, g_h, DMODEL, DMODEL / 2, DMODEL);
        }
        ln_kernel<<<NTOK, 256>>>(g_h, ln_g + (size_t)(l * 2 + 1) * DMODEL,
                                 ln_b + (size_t)(l * 2 + 1) * DMODEL, g_a,
                                 ff_b2 + (size_t)l * DMODEL);
        {
            dim3 grid(DFF / 128, NTOK / 128);
            tgemm_kernel<<<grid, 128, TGSMEM>>>(
                g_a, g_wt + lw + 4u * 1048576u,
                ff_b1 + (size_t)l * DFF, nullptr, g_f, DMODEL, DFF, 1);
        }
        {
            dim3 grid(DMODEL / 128, NTOK / 128, 2);
            tgemm_atomic_kernel<<<grid, 128, TGSMEM>>>(
                g_f, g_wt + lw + 8u * 1048576u, g_h, DFF, DFF / 2, DMODEL);
        }
    }

    // ---- layer 4 (last): full QKV + attention, then compact 128-row tail ----
    {
        const int l = NLAYER - 1;
        const size_t lw = (size_t)WT_EMB_SZ + (size_t)l * WT_LAYER;
        const __half* wq = g_wt + lw;
        const float* bq = attn_b + (size_t)l * 4 * DMODEL;

        ln_kernel<<<NTOK, 256>>>(g_h, ln_g + (size_t)(l * 2) * DMODEL,
                                 ln_b + (size_t)(l * 2) * DMODEL, g_a, nullptr);
        {
            dim3 grid(NQKV / 128, NTOK / 128);
            tgemm_kernel<<<grid, 128, TGSMEM>>>(
                g_a, wq, bq, nullptr, g_qkv, DMODEL, NQKV, 0);
        }
        attn_kernel<<<BATCH * NHEAD, 256>>>(g_qkv, g_o);
        gather_last_kernel<<<BATCH, 256>>>(g_h, g_o, bq + 3 * DMODEL, g_hc, g_oc);
        {
            dim3 grid(DMODEL / 128, 1, 8);
            tgemm_atomic_kernel<<<grid, 128, TGSMEM>>>(
                g_oc, wq + 3u * 1048576u, g_hc, DMODEL, DMODEL / 8, DMODEL);
        }
        ln_kernel<<<BATCH, 256>>>(g_hc, ln_g + (size_t)(l * 2 + 1) * DMODEL,
                                  ln_b + (size_t)(l * 2 + 1) * DMODEL, g_ac,
                                  ff_b2 + (size_t)l * DMODEL);
        {
            dim3 grid(DFF / 128, 1);
            tgemm_kernel<<<grid, 128, TGSMEM>>>(
                g_ac, g_wt + lw + 4u * 1048576u,
                ff_b1 + (size_t)l * DFF, nullptr, g_fc, DMODEL, DFF, 1);
        }
        {
            dim3 grid(DMODEL / 128, 1, 8);
            tgemm_atomic_kernel<<<grid, 128, TGSMEM>>>(
                g_fc, g_wt + lw + 8u * 1048576u, g_hc, DFF, DFF / 8, DMODEL);
        }
    }

    // ---- classifier head ----
    pool_ln_scale_kernel<<<BATCH, 256>>>(g_hc, fin_g, fin_b, cf_bn_g, cf_bn_b, g_z0);
    sgemm_kernel<<<dim3(DMODEL / BN_S, 1), 256>>>(g_z0, cf_w, cf_b, g_z1, BATCH, DMODEL, DMODEL, 1);
    fc_kernel<<<BATCH, 128>>>(g_z1, fc_bn_g, fc_bn_b, fc_w, fc_b, (float*)d_out);
}